// round 13
// baseline (speedup 1.0000x reference)
#include <cuda_runtime.h>

typedef unsigned long long u64;
typedef unsigned int u32;
__device__ __forceinline__ u64 pk2(float lo, float hi) {
    u64 r; asm("mov.b64 %0,{%1,%2};" : "=l"(r) : "f"(lo), "f"(hi)); return r;
}
__device__ __forceinline__ void upk2(u64 v, float& lo, float& hi) {
    asm("mov.b64 {%0,%1},%2;" : "=f"(lo), "=f"(hi) : "l"(v));
}
__device__ __forceinline__ void fma2(u64& d, u64 a, u64 b) {
    asm("fma.rn.f32x2 %0,%1,%2,%0;" : "+l"(d) : "l"(a), "l"(b));
}
__device__ __forceinline__ u64 add2(u64 a, u64 b) {
    u64 r; asm("add.rn.f32x2 %0,%1,%2;" : "=l"(r) : "l"(a), "l"(b)); return r;
}
__device__ __forceinline__ u32 to_tf32(float v) {
    u32 r; asm("cvt.rna.tf32.f32 %0, %1;" : "=r"(r) : "f"(v)); return r;
}
__device__ __forceinline__ void mma_tf32(float* c, const u32* a, u32 b0, u32 b1) {
    asm("mma.sync.aligned.m16n8k8.row.col.f32.tf32.tf32.f32 "
        "{%0,%1,%2,%3}, {%4,%5,%6,%7}, {%8,%9}, {%0,%1,%2,%3};"
        : "+f"(c[0]), "+f"(c[1]), "+f"(c[2]), "+f"(c[3])
        : "r"(a[0]), "r"(a[1]), "r"(a[2]), "r"(a[3]), "r"(b0), "r"(b1));
}
__device__ __forceinline__ void cp4(u32 dst, const float* src, bool pred) {
    asm volatile("cp.async.ca.shared.global [%0], [%1], 4, %2;"
                 :: "r"(dst), "l"(src), "r"(pred ? 4 : 0));
}
#define CP_COMMIT() asm volatile("cp.async.commit_group;")
#define CP_WAIT0()  asm volatile("cp.async.wait_group 0;")

// ---------------- scratch ----------------
__device__ float g_h1[(size_t)32*64*128*128];   // enc1 out, NCHW
__device__ float g_h2[(size_t)32*64*64*32];     // enc2 out, NHWC
__device__ int   g_idx[131072];
__device__ u64   g_z2[(size_t)32*131072];       // z pair-major [pair][px]
__device__ u64   g_vqkey[131072];               // packed (ordered score, idx)
__device__ float g_d1[(size_t)32*32*64*64];     // dec1 out, NCHW
__device__ float g_d2[(size_t)32*64*128*128];   // dec2 out, NCHW
__device__ float g_weff2[256*288];              // dec2 effective weights (tf32)
__device__ float g_weff3[16*576];               // dec3 effective weights (tf32)
__device__ float g_loss;

__device__ __forceinline__ u32 ordf(float f) {
    u32 u = __float_as_uint(f);
    return (u & 0x80000000u) ? ~u : (u | 0x80000000u);
}

// ---------------- parity matrices ----------------
__device__ __constant__ float c_M[2][3][3] = {
    {{0.75f,0.25f,0.f},{0.25f,0.75f,0.f},{0.f,0.75f,0.25f}},
    {{0.25f,0.75f,0.f},{0.f,0.75f,0.25f},{0.f,0.25f,0.75f}}};

// ---------------- prep: loss + weff2 + weff3 + vqkey init -------------------
__global__ void k_prep(const float* __restrict__ w2, const float* __restrict__ w3)
{
    int idx = blockIdx.x*128 + threadIdx.x;
    if (idx < 73728) {
        int m = idx / 288, k = idx - m*288;
        int oc = m >> 2, a = (m >> 1) & 1, bp = m & 1;
        int cin = k / 9, r = k - cin*9, dy = r / 3, dx = r - dy*3;
        float s = 0.f;
        #pragma unroll
        for (int ky = 0; ky < 3; ky++)
            #pragma unroll
            for (int kx = 0; kx < 3; kx++)
                s += w2[((oc*32+cin)*3+ky)*3+kx] * c_M[a][ky][dy] * c_M[bp][kx][dx];
        g_weff2[m*288 + k] = __uint_as_float(to_tf32(s));
    } else if (idx < 82944) {
        int j = idx - 73728;
        int m = j / 576, k = j - m*576;
        float s = 0.f;
        if (m < 12) {
            int oc = m >> 2, a = (m >> 1) & 1, bp = m & 1;
            int cin = k / 9, r = k - cin*9, dy = r / 3, dx = r - dy*3;
            #pragma unroll
            for (int ky = 0; ky < 3; ky++)
                #pragma unroll
                for (int kx = 0; kx < 3; kx++)
                    s += w3[((oc*64+cin)*3+ky)*3+kx] * c_M[a][ky][dy] * c_M[bp][kx][dx];
        }
        g_weff3[m*576 + k] = __uint_as_float(to_tf32(s));
    } else if (idx == 82944) {
        g_loss = 0.f;
    } else if (idx >= 82945 && idx < 82945 + 131072) {
        g_vqkey[idx - 82945] = 0xFFFFFFFFFFFFFFFFull;
    }
}

// ---------------- enc1 (unchanged) ----------------
__global__ __launch_bounds__(256) void k_enc1(const float* __restrict__ x,
                                              const float* __restrict__ w,
                                              const float* __restrict__ bias)
{
    __shared__ __align__(16) float sWt[27*64];
    __shared__ __align__(16) float sIn[3*33*65];
    __shared__ __align__(16) float sB[64];
    int blk = blockIdx.x;
    int img = blk >> 5;
    int tile = blk & 31;
    int tx0 = (tile & 3) * 32;
    int ty0 = (tile >> 2) * 16;
    int tid = threadIdx.x;
    for (int i = tid; i < 27*64; i += 256) {
        int t = i >> 6, o = i & 63;
        sWt[i] = w[o*27 + t];
    }
    if (tid < 64) sB[tid] = bias[tid];
    int iy0 = 2*ty0 - 1, ix0 = 2*tx0 - 1;
    const float* xim = x + (size_t)img*3*65536;
    for (int i = tid; i < 3*33*65; i += 256) {
        int c = i / (33*65); int rem = i - c*(33*65);
        int r = rem / 65; int cc = rem - r*65;
        int gy = iy0 + r, gx = ix0 + cc;
        float v = 0.f;
        if (gy >= 0 && gy < 256 && gx >= 0 && gx < 256)
            v = xim[(size_t)c*65536 + gy*256 + gx];
        sIn[i] = v;
    }
    __syncthreads();
    int tx = tid & 31, tyq = tid >> 5;
    float in[3][5][3];
    int lr0 = 4*tyq, lc0 = 2*tx;
    #pragma unroll
    for (int c = 0; c < 3; c++)
        #pragma unroll
        for (int r = 0; r < 5; r++)
            #pragma unroll
            for (int cc = 0; cc < 3; cc++)
                in[c][r][cc] = sIn[c*(33*65) + (lr0+r)*65 + lc0+cc];
    float* h1o = g_h1 + (size_t)img*64*16384;
    int oy = ty0 + 2*tyq, ox = tx0 + tx;
    #pragma unroll 1
    for (int half = 0; half < 2; half++) {
        int ocg = half * 32;
        u64 a0[16], a1[16];
        #pragma unroll
        for (int i = 0; i < 16; i++) {
            a0[i] = pk2(sB[ocg+2*i], sB[ocg+2*i+1]);
            a1[i] = a0[i];
        }
        #pragma unroll
        for (int c = 0; c < 3; c++)
            #pragma unroll
            for (int ky = 0; ky < 3; ky++)
                #pragma unroll
                for (int kx = 0; kx < 3; kx++) {
                    u64 vv0 = pk2(in[c][ky][kx], in[c][ky][kx]);
                    u64 vv1 = pk2(in[c][ky+2][kx], in[c][ky+2][kx]);
                    const ulonglong2* wp = reinterpret_cast<const ulonglong2*>(&sWt[(c*9+ky*3+kx)*64 + ocg]);
                    #pragma unroll
                    for (int q = 0; q < 8; q++) {
                        ulonglong2 wq = wp[q];
                        fma2(a0[2*q],   vv0, wq.x);
                        fma2(a0[2*q+1], vv0, wq.y);
                        fma2(a1[2*q],   vv1, wq.x);
                        fma2(a1[2*q+1], vv1, wq.y);
                    }
                }
        #pragma unroll
        for (int i = 0; i < 16; i++) {
            float l0, h0v, l1, h1v;
            upk2(a0[i], l0, h0v);
            upk2(a1[i], l1, h1v);
            h1o[(size_t)(ocg+2*i)*16384   + (size_t)oy*128 + ox]     = fmaxf(l0, 0.f);
            h1o[(size_t)(ocg+2*i+1)*16384 + (size_t)oy*128 + ox]     = fmaxf(h0v, 0.f);
            h1o[(size_t)(ocg+2*i)*16384   + (size_t)(oy+1)*128 + ox] = fmaxf(l1, 0.f);
            h1o[(size_t)(ocg+2*i+1)*16384 + (size_t)(oy+1)*128 + ox] = fmaxf(h1v, 0.f);
        }
    }
}

// ---------------- enc2: cp.async double-buffered (unchanged) ----------------
__global__ __launch_bounds__(128) void k_enc2(const float* __restrict__ w,
                                              const float* __restrict__ bias)
{
    extern __shared__ __align__(16) float se2[];
    float* sWt = se2;
    float* sInb[2] = { se2 + 9216, se2 + 9216 + 2145 };
    float* sB  = se2 + 9216 + 4290;
    int b = blockIdx.x;
    int og = b & 1;
    int t = (b >> 1) & 7;
    int img = b >> 4;
    int ox0 = (t & 1) * 32;
    int oy0 = (t >> 1) * 16;
    int tid = threadIdx.x;
    for (int i = tid; i < 9216; i += 128) {
        int o = i & 15, rc = i >> 4;
        sWt[i] = w[(og*16 + o)*576 + rc];
    }
    if (tid < 16) sB[tid] = bias[og*16 + tid];
    const float* h1im = g_h1 + (size_t)img*64*16384;
    int iy0 = 2*oy0 - 1, ix0 = 2*ox0 - 1;
    {
        u32 dst0 = (u32)__cvta_generic_to_shared(sInb[0]);
        for (int i = tid; i < 2145; i += 128) {
            int r = i / 65, cc = i - r*65;
            int gy = iy0 + r, gx = ix0 + cc;
            bool ok = (gy >= 0 && gy < 128 && gx >= 0 && gx < 128);
            cp4(dst0 + 4u*i, h1im + ((size_t)gy*128 + gx), ok);
        }
        CP_COMMIT();
    }
    int ttx = tid & 15, tty = tid >> 4;
    u64 acc[2][2][8];
    #pragma unroll 1
    for (int cin = 0; cin < 64; cin++) {
        float* cur = sInb[cin & 1];
        float* nxt = sInb[(cin & 1) ^ 1];
        CP_WAIT0();
        __syncthreads();
        if (cin == 0) {
            #pragma unroll
            for (int r = 0; r < 2; r++)
                #pragma unroll
                for (int cc = 0; cc < 2; cc++)
                    #pragma unroll
                    for (int p = 0; p < 8; p++) acc[r][cc][p] = pk2(sB[2*p], sB[2*p+1]);
        }
        if (cin < 63) {
            const float* hp = h1im + (size_t)(cin+1)*16384;
            u32 dstn = (u32)__cvta_generic_to_shared(nxt);
            for (int i = tid; i < 2145; i += 128) {
                int r = i / 65, cc = i - r*65;
                int gy = iy0 + r, gx = ix0 + cc;
                bool ok = (gy >= 0 && gy < 128 && gx >= 0 && gx < 128);
                cp4(dstn + 4u*i, hp + ((size_t)gy*128 + gx), ok);
            }
        }
        CP_COMMIT();
        float in[5][5];
        #pragma unroll
        for (int r = 0; r < 5; r++)
            #pragma unroll
            for (int c = 0; c < 5; c++)
                in[r][c] = cur[(4*tty + r)*65 + 4*ttx + c];
        #pragma unroll
        for (int ky = 0; ky < 3; ky++)
            #pragma unroll
            for (int kx = 0; kx < 3; kx++) {
                u64 vv[2][2];
                #pragma unroll
                for (int r = 0; r < 2; r++)
                    #pragma unroll
                    for (int cc = 0; cc < 2; cc++) {
                        float v = in[2*r+ky][2*cc+kx];
                        vv[r][cc] = pk2(v, v);
                    }
                const ulonglong2* wp = reinterpret_cast<const ulonglong2*>(&sWt[(cin*9+ky*3+kx)*16]);
                #pragma unroll
                for (int q = 0; q < 4; q++) {
                    ulonglong2 wq = wp[q];
                    #pragma unroll
                    for (int r = 0; r < 2; r++)
                        #pragma unroll
                        for (int cc = 0; cc < 2; cc++) {
                            fma2(acc[r][cc][2*q],   vv[r][cc], wq.x);
                            fma2(acc[r][cc][2*q+1], vv[r][cc], wq.y);
                        }
                }
            }
    }
    #pragma unroll
    for (int r = 0; r < 2; r++)
        #pragma unroll
        for (int cc = 0; cc < 2; cc++) {
            int oy = oy0 + 2*tty + r, ox = ox0 + 2*ttx + cc;
            float* dp = g_h2 + ((size_t)(img*64 + oy)*64 + ox)*32 + og*16;
            #pragma unroll
            for (int p = 0; p < 8; p++) {
                float lo, hi;
                upk2(acc[r][cc][p], lo, hi);
                dp[2*p]   = fmaxf(lo, 0.f);
                dp[2*p+1] = fmaxf(hi, 0.f);
            }
        }
}

// ---------------- enc3z: z = W3 h + b3; store pair-major; sum ||z||^2 -------
__global__ __launch_bounds__(256) void k_enc3z(const float* __restrict__ w3,
                                               const float* __restrict__ b3)
{
    __shared__ __align__(16) float sW[2048];
    __shared__ __align__(16) float sB[64];
    int tid = threadIdx.x;
    for (int i = tid; i < 2048; i += 256) sW[i] = w3[i];
    if (tid < 64) sB[tid] = b3[tid];
    __syncthreads();
    int p0 = blockIdx.x*512 + tid;
    int p1 = p0 + 256;
    float h0[32], h1[32];
    {
        const float4* hp0 = reinterpret_cast<const float4*>(g_h2 + (size_t)p0*32);
        const float4* hp1 = reinterpret_cast<const float4*>(g_h2 + (size_t)p1*32);
        #pragma unroll
        for (int q = 0; q < 8; q++) {
            float4 v0 = hp0[q];
            h0[4*q] = v0.x; h0[4*q+1] = v0.y; h0[4*q+2] = v0.z; h0[4*q+3] = v0.w;
            float4 v1 = hp1[q];
            h1[4*q] = v1.x; h1[4*q+1] = v1.y; h1[4*q+2] = v1.z; h1[4*q+3] = v1.w;
        }
    }
    const float4* sW4 = reinterpret_cast<const float4*>(sW);
    u64 n0 = 0, n1 = 0;
    #pragma unroll 2
    for (int i = 0; i < 32; i++) {
        float a0 = 0.f, a1 = 0.f, b0 = 0.f, b1 = 0.f;
        #pragma unroll
        for (int q = 0; q < 8; q++) {
            float4 wa = sW4[(2*i)*8 + q];
            float4 wb = sW4[(2*i+1)*8 + q];
            a0 = fmaf(wa.x, h0[4*q],   a0); a0 = fmaf(wa.y, h0[4*q+1], a0);
            a0 = fmaf(wa.z, h0[4*q+2], a0); a0 = fmaf(wa.w, h0[4*q+3], a0);
            a1 = fmaf(wa.x, h1[4*q],   a1); a1 = fmaf(wa.y, h1[4*q+1], a1);
            a1 = fmaf(wa.z, h1[4*q+2], a1); a1 = fmaf(wa.w, h1[4*q+3], a1);
            b0 = fmaf(wb.x, h0[4*q],   b0); b0 = fmaf(wb.y, h0[4*q+1], b0);
            b0 = fmaf(wb.z, h0[4*q+2], b0); b0 = fmaf(wb.w, h0[4*q+3], b0);
            b1 = fmaf(wb.x, h1[4*q],   b1); b1 = fmaf(wb.y, h1[4*q+1], b1);
            b1 = fmaf(wb.z, h1[4*q+2], b1); b1 = fmaf(wb.w, h1[4*q+3], b1);
        }
        u64 z0 = pk2(sB[2*i] + a0, sB[2*i+1] + b0);
        u64 z1 = pk2(sB[2*i] + a1, sB[2*i+1] + b1);
        g_z2[(size_t)i*131072 + p0] = z0;
        g_z2[(size_t)i*131072 + p1] = z1;
        fma2(n0, z0, z0);
        fma2(n1, z1, z1);
    }
    float l0, h0v, l1, h1v;
    upk2(n0, l0, h0v);
    upk2(n1, l1, h1v);
    float s = (l0 + h0v) + (l1 + h1v);
    #pragma unroll
    for (int off = 16; off > 0; off >>= 1)
        s += __shfl_down_sync(0xffffffffu, s, off);
    if ((tid & 31) == 0) atomicAdd(&g_loss, s);
}

// ---------------- vq2: k-quartered argmin, atomicMin combine ---------------
// grid 2048 = 512 px-chunks(256px) x 4 quarters; 256 thr, 1 px/thread.
__global__ __launch_bounds__(256) void k_vq2(const float* __restrict__ cb)
{
    __shared__ __align__(16) float sCB[128*64];   // 32 KB quarter
    __shared__ float sCn[128];
    int q = blockIdx.x & 3;
    int chunk = blockIdx.x >> 2;
    int tid = threadIdx.x;
    const float* cbq = cb + (size_t)q*128*64;
    for (int i = tid; i < 8192; i += 256) sCB[i] = cbq[i];
    __syncthreads();
    for (int k = tid; k < 128; k += 256) {
        float s = 0.f;
        #pragma unroll 8
        for (int d = 0; d < 64; d++) { float v = sCB[k*64+d]; s = fmaf(v, v, s); }
        sCn[k] = s;
    }
    __syncthreads();
    int p = chunk*256 + tid;
    u64 z2[32];
    #pragma unroll
    for (int i = 0; i < 32; i++) z2[i] = g_z2[(size_t)i*131072 + p];
    const ulonglong2* sCB2 = reinterpret_cast<const ulonglong2*>(sCB);
    float best = 3.4e38f;
    int bi = 0;
    #pragma unroll 1
    for (int k = 0; k < 128; k++) {
        const ulonglong2* ck = sCB2 + k*16;
        u64 a0 = 0, a1 = 0;
        #pragma unroll
        for (int qq = 0; qq < 16; qq++) {
            ulonglong2 cq = ck[qq];
            fma2(a0, z2[2*qq],   cq.x);
            fma2(a1, z2[2*qq+1], cq.y);
        }
        u64 sa = add2(a0, a1);
        float la, ha;
        upk2(sa, la, ha);
        float s = sCn[k] - 2.f*(la + ha);
        if (s < best) { best = s; bi = k; }
    }
    u64 key = ((u64)ordf(best) << 32) | (u32)(q*128 + bi);
    atomicMin(&g_vqkey[p], key);
}

// ---------------- vqfin: unpack idx + accumulate best scores ----------------
__global__ __launch_bounds__(256) void k_vqfin()
{
    int p = blockIdx.x*256 + threadIdx.x;
    u64 key = g_vqkey[p];
    g_idx[p] = (int)(u32)key;
    u32 os = (u32)(key >> 32);
    u32 u = (os & 0x80000000u) ? (os ^ 0x80000000u) : ~os;
    float s = __uint_as_float(u);
    #pragma unroll
    for (int off = 16; off > 0; off >>= 1)
        s += __shfl_down_sync(0xffffffffu, s, off);
    if ((threadIdx.x & 31) == 0) atomicAdd(&g_loss, s);
}

__global__ void k_loss_out(float* __restrict__ out)
{
    float v = g_loss * (1.f/8388608.f);
    out[0] = v;
    out[1] = v;
}

// ---------------- dec1 (unchanged) ----------------
__global__ __launch_bounds__(256) void k_dec1(const float* __restrict__ cb,
                                              const float* __restrict__ w,
                                              const float* __restrict__ bias)
{
    __shared__ __align__(16) float sW[32*64];
    __shared__ __align__(16) float sB[32];
    int tid = threadIdx.x;
    for (int i = tid; i < 2048; i += 256) sW[i] = w[i];
    if (tid < 32) sB[tid] = bias[tid];
    __syncthreads();
    int p = blockIdx.x*256 + tid;
    int ki = g_idx[p];
    float c[64];
    const float4* cp = reinterpret_cast<const float4*>(cb + (size_t)ki*64);
    #pragma unroll
    for (int q = 0; q < 16; q++) {
        float4 v = cp[q];
        c[4*q] = v.x; c[4*q+1] = v.y; c[4*q+2] = v.z; c[4*q+3] = v.w;
    }
    int img = p >> 12;
    int rem = p & 4095;
    float* dp = g_d1 + (size_t)img*32*4096 + rem;
    const float4* sW4 = reinterpret_cast<const float4*>(sW);
    #pragma unroll 1
    for (int oc = 0; oc < 32; oc++) {
        float a0 = 0.f, a1 = 0.f, a2 = 0.f, a3 = 0.f;
        #pragma unroll
        for (int q = 0; q < 16; q++) {
            float4 wv = sW4[oc*16 + q];
            a0 = fmaf(wv.x, c[4*q],   a0);
            a1 = fmaf(wv.y, c[4*q+1], a1);
            a2 = fmaf(wv.z, c[4*q+2], a2);
            a3 = fmaf(wv.w, c[4*q+3], a3);
        }
        float v = sB[oc] + ((a0+a1) + (a2+a3));
        dp[(size_t)oc*4096] = fmaxf(v, 0.f);
    }
}

// ---------------- dec2 main mma (unchanged from R12) ----------
__global__ __launch_bounds__(128) void k_dec2_mma(const float* __restrict__ bias)
{
    extern __shared__ __align__(16) float smx[];
    float* sA = smx;
    float* sX = smx + 64*292;
    int*   sK = (int*)(smx + 64*292 + 5760);
    int b = blockIdx.x;
    int mb = b & 3;
    int t = (b >> 2) & 31;
    int img = b >> 7;
    int tx0 = (t & 3) * 16;
    int ty0 = (t >> 2) * 8;
    int tid = threadIdx.x;
    {
        const float4* src = reinterpret_cast<const float4*>(g_weff2 + mb*64*288);
        for (int i = tid; i < 64*72; i += 128) {
            int r = i / 72, kq = (i - r*72)*4;
            float4 v = src[i];
            float* d = sA + r*292 + kq;
            d[0] = v.x; d[1] = v.y; d[2] = v.z; d[3] = v.w;
        }
    }
    for (int k = tid; k < 288; k += 128) {
        int cin = k / 9, rr = k - cin*9;
        sK[k] = cin*180 + (rr/3)*18 + (rr - (rr/3)*3);
    }
    const float* simg = g_d1 + (size_t)img*32*4096;
    for (int i = tid; i < 5760; i += 128) {
        int cin = i / 180;
        int rem = i - cin*180;
        int r = rem / 18, c = rem - r*18;
        int sy = ty0 - 1 + r; sy = max(0, min(63, sy));
        int sx = tx0 - 1 + c; sx = max(0, min(63, sx));
        sX[i] = __uint_as_float(to_tf32(simg[cin*4096 + sy*64 + sx]));
    }
    __syncthreads();
    int wid = tid >> 5, lane = tid & 31;
    int wm = wid & 1, wn = wid >> 1;
    int lg = lane >> 2, lig = lane & 3;
    float acc[2][8][4];
    #pragma unroll
    for (int mt = 0; mt < 2; mt++)
        #pragma unroll
        for (int nt = 0; nt < 8; nt++)
            #pragma unroll
            for (int c = 0; c < 4; c++) acc[mt][nt][c] = 0.f;
    int pb[8];
    #pragma unroll
    for (int nt = 0; nt < 8; nt++) {
        int n = wn*64 + nt*8 + lg;
        pb[nt] = (n >> 4)*18 + (n & 15);
    }
    const float* arow0 = sA + (wm*32 + lg)*292 + lig;
    const float* arow1 = arow0 + 16*292;
    u32 abuf[2][2][4];
    u32 bbuf[2][8][2];
    {
        int ko0 = sK[lig];
        int ko1 = sK[lig + 4];
        abuf[0][0][0] = __float_as_uint(arow0[0]);
        abuf[0][0][1] = __float_as_uint(arow0[8*292]);
        abuf[0][0][2] = __float_as_uint(arow0[4]);
        abuf[0][0][3] = __float_as_uint(arow0[8*292 + 4]);
        abuf[0][1][0] = __float_as_uint(arow1[0]);
        abuf[0][1][1] = __float_as_uint(arow1[8*292]);
        abuf[0][1][2] = __float_as_uint(arow1[4]);
        abuf[0][1][3] = __float_as_uint(arow1[8*292 + 4]);
        #pragma unroll
        for (int nt = 0; nt < 8; nt++) {
            bbuf[0][nt][0] = __float_as_uint(sX[ko0 + pb[nt]]);
            bbuf[0][nt][1] = __float_as_uint(sX[ko1 + pb[nt]]);
        }
    }
    #pragma unroll 2
    for (int ks = 0; ks < 36; ks++) {
        int cur = ks & 1, nxt = cur ^ 1;
        if (ks < 35) {
            int kb = (ks+1)*8;
            int ko0 = sK[kb + lig];
            int ko1 = sK[kb + lig + 4];
            const float* a0p = arow0 + kb;
            const float* a1p = arow1 + kb;
            abuf[nxt][0][0] = __float_as_uint(a0p[0]);
            abuf[nxt][0][1] = __float_as_uint(a0p[8*292]);
            abuf[nxt][0][2] = __float_as_uint(a0p[4]);
            abuf[nxt][0][3] = __float_as_uint(a0p[8*292 + 4]);
            abuf[nxt][1][0] = __float_as_uint(a1p[0]);
            abuf[nxt][1][1] = __float_as_uint(a1p[8*292]);
            abuf[nxt][1][2] = __float_as_uint(a1p[4]);
            abuf[nxt][1][3] = __float_as_uint(a1p[8*292 + 4]);
            #pragma unroll
            for (int nt = 0; nt < 8; nt++) {
                bbuf[nxt][nt][0] = __float_as_uint(sX[ko0 + pb[nt]]);
                bbuf[nxt][nt][1] = __float_as_uint(sX[ko1 + pb[nt]]);
            }
        }
        #pragma unroll
        for (int nt = 0; nt < 8; nt++) {
            mma_tf32(acc[0][nt], abuf[cur][0], bbuf[cur][nt][0], bbuf[cur][nt][1]);
            mma_tf32(acc[1][nt], abuf[cur][1], bbuf[cur][nt][0], bbuf[cur][nt][1]);
        }
    }
    #pragma unroll
    for (int mt = 0; mt < 2; mt++) {
        int mbase = mb*64 + wm*32 + mt*16 + lg;
        float bv0 = bias[mbase >> 2];
        float bv2 = bias[(mbase + 8) >> 2];
        #pragma unroll
        for (int nt = 0; nt < 8; nt++) {
            #pragma unroll
            for (int c = 0; c < 4; c++) {
                int m = mbase + ((c >= 2) ? 8 : 0);
                int n = wn*64 + nt*8 + 2*lig + (c & 1);
                int oc = m >> 2, ap = (m >> 1) & 1, bp2 = m & 1;
                int py = n >> 4, px = n & 15;
                int uy = 2*(ty0 + py) + ap, ux = 2*(tx0 + px) + bp2;
                float v = acc[mt][nt][c] + ((c >= 2) ? bv2 : bv0);
                g_d2[((size_t)(img*64 + oc)*128 + uy)*128 + ux] = fmaxf(v, 0.f);
            }
        }
    }
}

// ---------------- dec2 border fixup (unchanged) ----------------
__global__ __launch_bounds__(256) void k_dec2_fix(const float* __restrict__ w,
                                                  const float* __restrict__ bias)
{
    extern __shared__ __align__(16) float sf[];
    float* sW = sf;
    float* sT = sf + 18432;
    int side = blockIdx.x & 3;
    int img = blockIdx.x >> 2;
    int tid = threadIdx.x;
    for (int i = tid; i < 18432; i += 256) sW[i] = w[i];
    const float* xi = g_d1 + (size_t)img*32*4096;
    for (int i = tid; i < 32*2*130; i += 256) {
        int cin = i / 260;
        int rem = i - cin*260;
        int s = rem / 130, c = rem - s*130;
        const float* xp = xi + cin*4096;
        float v = 0.f;
        int u = c - 1;
        if (u >= 0 && u < 128) {
            int j = u >> 1;
            int ja, jb; float wa, wb;
            if (u & 1) { ja = j; jb = min(j+1, 63); wa = 0.75f; wb = 0.25f; }
            else       { ja = max(j-1, 0); jb = j;  wa = 0.25f; wb = 0.75f; }
            float xa, xb;
            if (side == 0) {
                if (s == 0) { xa = xp[ja]; xb = xp[jb]; }
                else { xa = 0.75f*xp[ja] + 0.25f*xp[64+ja];
                       xb = 0.75f*xp[jb] + 0.25f*xp[64+jb]; }
            } else if (side == 1) {
                const float* r62 = xp + 62*64; const float* r63 = xp + 63*64;
                if (s == 0) { xa = 0.25f*r62[ja] + 0.75f*r63[ja];
                              xb = 0.25f*r62[jb] + 0.75f*r63[jb]; }
                else { xa = r63[ja]; xb = r63[jb]; }
            } else if (side == 2) {
                if (s == 0) { xa = xp[ja*64]; xb = xp[jb*64]; }
                else { xa = 0.75f*xp[ja*64] + 0.25f*xp[ja*64+1];
                       xb = 0.75f*xp[jb*64] + 0.25f*xp[jb*64+1]; }
            } else {
                if (s == 0) { xa = 0.25f*xp[ja*64+62] + 0.75f*xp[ja*64+63];
                              xb = 0.25f*xp[jb*64+62] + 0.75f*xp[jb*64+63]; }
                else { xa = xp[ja*64+63]; xb = xp[jb*64+63]; }
            }
            v = wa*xa + wb*xb;
        }
        sT[i] = v;
    }
    __syncthreads();
    int oc = tid >> 2;
    int q = tid & 3;
    if (side <= 1) {
        int uy = (side == 0) ? 0 : 127;
        int ky0 = (side == 0) ? 1 : 0;
        for (int ux = q; ux < 128; ux += 4) {
            float acc = bias[oc];
            for (int cin = 0; cin < 32; cin++) {
                const float* wp = sW + (oc*32 + cin)*9;
                const float* tp = sT + cin*260;
                #pragma unroll
                for (int s = 0; s < 2; s++)
                    #pragma unroll
                    for (int kx = 0; kx < 3; kx++)
                        acc += wp[(ky0+s)*3 + kx] * tp[s*130 + ux + kx];
            }
            g_d2[((size_t)(img*64 + oc)*128 + uy)*128 + ux] = fmaxf(acc, 0.f);
        }
    } else {
        int ux = (side == 2) ? 0 : 127;
        int kx0 = (side == 2) ? 1 : 0;
        for (int uy = 1 + q; uy < 127; uy += 4) {
            float acc = bias[oc];
            for (int cin = 0; cin < 32; cin++) {
                const float* wp = sW + (oc*32 + cin)*9;
                const float* tp = sT + cin*260;
                #pragma unroll
                for (int s = 0; s < 2; s++)
                    #pragma unroll
                    for (int ky = 0; ky < 3; ky++)
                        acc += wp[ky*3 + kx0 + s] * tp[s*130 + uy + ky];
            }
            g_d2[((size_t)(img*64 + oc)*128 + uy)*128 + ux] = fmaxf(acc, 0.f);
        }
    }
}

// ---------------- dec3 main mma (unchanged from R12) ----------
__global__ __launch_bounds__(128) void k_dec3_mma(const float* __restrict__ bias,
                                                  float* __restrict__ dst)
{
    extern __shared__ __align__(16) float sm3[];
    float* sA = sm3;
    float* sX = sm3 + 16*580;
    int*   sK = (int*)(sm3 + 16*580 + 11520);
    __shared__ float sB3[3];
    int b = blockIdx.x;
    int txt = b & 7;
    int tyt = (b >> 3) & 15;
    int img = b >> 7;
    int tx0 = txt * 16;
    int ty0 = tyt * 8;
    int tid = threadIdx.x;
    {
        const float4* src = reinterpret_cast<const float4*>(g_weff3);
        for (int i = tid; i < 16*144; i += 128) {
            int r = i / 144, kq = (i - r*144)*4;
            float4 v = src[i];
            float* d = sA + r*580 + kq;
            d[0] = v.x; d[1] = v.y; d[2] = v.z; d[3] = v.w;
        }
    }
    for (int k = tid; k < 576; k += 128) {
        int cin = k / 9, rr = k - cin*9;
        sK[k] = cin*180 + (rr/3)*18 + (rr - (rr/3)*3);
    }
    if (tid < 3) sB3[tid] = bias[tid];
    const float* simg = g_d2 + (size_t)img*64*16384;
    for (int i = tid; i < 11520; i += 128) {
        int cin = i / 180;
        int rem = i - cin*180;
        int r = rem / 18, c = rem - r*18;
        int sy = ty0 - 1 + r; sy = max(0, min(127, sy));
        int sx = tx0 - 1 + c; sx = max(0, min(127, sx));
        sX[i] = __uint_as_float(to_tf32(simg[cin*16384 + sy*128 + sx]));
    }
    __syncthreads();
    int wn = tid >> 5, lane = tid & 31;
    int lg = lane >> 2, lig = lane & 3;
    float acc[4][4];
    #pragma unroll
    for (int nt = 0; nt < 4; nt++)
        #pragma unroll
        for (int c = 0; c < 4; c++) acc[nt][c] = 0.f;
    int pb[4];
    #pragma unroll
    for (int nt = 0; nt < 4; nt++) {
        int n = wn*32 + nt*8 + lg;
        pb[nt] = (n >> 4)*18 + (n & 15);
    }
    const float* arow = sA + lg*580 + lig;
    u32 abuf[2][4];
    u32 bbuf[2][4][2];
    {
        int ko0 = sK[lig];
        int ko1 = sK[lig + 4];
        abuf[0][0] = __float_as_uint(arow[0]);
        abuf[0][1] = __float_as_uint(arow[8*580]);
        abuf[0][2] = __float_as_uint(arow[4]);
        abuf[0][3] = __float_as_uint(arow[8*580 + 4]);
        #pragma unroll
        for (int nt = 0; nt < 4; nt++) {
            bbuf[0][nt][0] = __float_as_uint(sX[ko0 + pb[nt]]);
            bbuf[0][nt][1] = __float_as_uint(sX[ko1 + pb[nt]]);
        }
    }
    #pragma unroll 2
    for (int ks = 0; ks < 72; ks++) {
        int cur = ks & 1, nxt = cur ^ 1;
        if (ks < 71) {
            int kb = (ks+1)*8;
            int ko0 = sK[kb + lig];
            int ko1 = sK[kb + lig + 4];
            const float* ap = arow + kb;
            abuf[nxt][0] = __float_as_uint(ap[0]);
            abuf[nxt][1] = __float_as_uint(ap[8*580]);
            abuf[nxt][2] = __float_as_uint(ap[4]);
            abuf[nxt][3] = __float_as_uint(ap[8*580 + 4]);
            #pragma unroll
            for (int nt = 0; nt < 4; nt++) {
                bbuf[nxt][nt][0] = __float_as_uint(sX[ko0 + pb[nt]]);
                bbuf[nxt][nt][1] = __float_as_uint(sX[ko1 + pb[nt]]);
            }
        }
        #pragma unroll
        for (int nt = 0; nt < 4; nt++)
            mma_tf32(acc[nt], abuf[cur], bbuf[cur][nt][0], bbuf[cur][nt][1]);
    }
    #pragma unroll
    for (int nt = 0; nt < 4; nt++) {
        #pragma unroll
        for (int c = 0; c < 4; c++) {
            int m = lg + ((c >= 2) ? 8 : 0);
            if (m < 12) {
                int oc = m >> 2, ap = (m >> 1) & 1, bp = m & 1;
                int n = wn*32 + nt*8 + 2*lig + (c & 1);
                int uy = 2*(ty0 + (n >> 4)) + ap;
                int ux = 2*(tx0 + (n & 15)) + bp;
                dst[(((size_t)(img*3 + oc)) << 16) + uy*256 + ux] = acc[nt][c] + sB3[oc];
            }
        }
    }
}

// ---------------- dec3 border fixup (unchanged) ---------
__global__ __launch_bounds__(256) void k_dec3_fix(const float* __restrict__ w,
                                                  const float* __restrict__ bias,
                                                  float* __restrict__ dst)
{
    extern __shared__ __align__(16) float sf3[];
    float* sW = sf3;
    float* sT = sf3 + 1728;
    int side = blockIdx.x & 3;
    int img = blockIdx.x >> 2;
    int tid = threadIdx.x;
    for (int i = tid; i < 1728; i += 256) sW[i] = w[i];
    const float* xi = g_d2 + (size_t)img*64*16384;
    for (int i = tid; i < 64*2*258; i += 256) {
        int cin = i / 516;
        int rem = i - cin*516;
        int s = rem / 258, c = rem - s*258;
        const float* xp = xi + cin*16384;
        float v = 0.f;
        int u = c - 1;
        if (u >= 0 && u < 256) {
            int j = u >> 1;
            int ja, jb; float wa, wb;
            if (u & 1) { ja = j; jb = min(j+1, 127); wa = 0.75f; wb = 0.25f; }
            else       { ja = max(j-1, 0); jb = j;   wa = 0.25f; wb = 0.75f; }
            float xa, xb;
            if (side == 0) {
                if (s == 0) { xa = xp[ja]; xb = xp[jb]; }
                else { xa = 0.75f*xp[ja] + 0.25f*xp[128+ja];
                       xb = 0.75f*xp[jb] + 0.25f*xp[128+jb]; }
            } else if (side == 1) {
                const float* rA = xp + 126*128; const float* rB = xp + 127*128;
                if (s == 0) { xa = 0.25f*rA[ja] + 0.75f*rB[ja];
                              xb = 0.25f*rA[jb] + 0.75f*rB[jb]; }
                else { xa = rB[ja]; xb = rB[jb]; }
            } else if (side == 2) {
                if (s == 0) { xa = xp[ja*128]; xb = xp[jb*128]; }
                else { xa = 0.75f*xp[ja*128] + 0.25f*xp[ja*128+1];
                       xb = 0.75f*xp[jb*128] + 0.25f*xp[jb*128+1]; }
            } else {
                if (s == 0) { xa = 0.25f*xp[ja*128+126] + 0.75f*xp[ja*128+127];
                              xb = 0.25f*xp[jb*128+126] + 0.75f*xp[jb*128+127]; }
                else { xa = xp[ja*128+127]; xb = xp[jb*128+127]; }
            }
            v = wa*xa + wb*xb;
        }
        sT[i] = v;
    }
    __syncthreads();
    if (side <= 1) {
        int uy = (side == 0) ? 0 : 255;
        int ky0 = (side == 0) ? 1 : 0;
        for (int idx = tid; idx < 3*256; idx += 256) {
            int oc = idx >> 8, ux = idx & 255;
            float acc = bias[oc];
            for (int cin = 0; cin < 64; cin++) {
                const float* wp = sW + (oc*64 + cin)*9;
                const float* tp = sT + cin*516;
                #pragma unroll
                for (int s = 0; s < 2; s++)
                    #pragma unroll
                    for (int kx = 0; kx < 3; kx++)
                        acc += wp[(ky0+s)*3 + kx] * tp[s*258 + ux + kx];
            }
            dst[(((size_t)(img*3 + oc)) << 16) + uy*256 + ux] = acc;
        }
    } else {
        int ux = (side == 2) ? 0 : 255;
        int kx0 = (side == 2) ? 1 : 0;
        for (int idx = tid; idx < 3*254; idx += 256) {
            int oc = idx / 254;
            int uy = 1 + idx - oc*254;
            float acc = bias[oc];
            for (int cin = 0; cin < 64; cin++) {
                const float* wp = sW + (oc*64 + cin)*9;
                const float* tp = sT + cin*516;
                #pragma unroll
                for (int s = 0; s < 2; s++)
                    #pragma unroll
                    for (int ky = 0; ky < 3; ky++)
                        acc += wp[ky*3 + kx0 + s] * tp[s*258 + uy + ky];
            }
            dst[(((size_t)(img*3 + oc)) << 16) + uy*256 + ux] = acc;
        }
    }
}

// ---------------- host launch ----------------
extern "C" void kernel_launch(void* const* d_in, const int* in_sizes, int n_in,
                              void* d_out, int out_size) {
    const float* x   = (const float*)d_in[0];
    const float* cb  = (const float*)d_in[1];
    const float* ew1 = (const float*)d_in[2];
    const float* eb1 = (const float*)d_in[3];
    const float* ew2 = (const float*)d_in[4];
    const float* eb2 = (const float*)d_in[5];
    const float* ew3 = (const float*)d_in[6];
    const float* eb3 = (const float*)d_in[7];
    const float* dw1 = (const float*)d_in[8];
    const float* db1 = (const float*)d_in[9];
    const float* dw2 = (const float*)d_in[10];
    const float* db2 = (const float*)d_in[11];
    const float* dw3 = (const float*)d_in[12];
    const float* db3 = (const float*)d_in[13];
    float* out = (float*)d_out;

    cudaFuncSetAttribute(k_enc2, cudaFuncAttributeMaxDynamicSharedMemorySize, 54088);
    cudaFuncSetAttribute(k_dec2_mma, cudaFuncAttributeMaxDynamicSharedMemorySize, 98944);
    cudaFuncSetAttribute(k_dec2_fix, cudaFuncAttributeMaxDynamicSharedMemorySize, 107008);
    cudaFuncSetAttribute(k_dec3_mma, cudaFuncAttributeMaxDynamicSharedMemorySize, 85504);
    cudaFuncSetAttribute(k_dec3_fix, cudaFuncAttributeMaxDynamicSharedMemorySize, 139008);

    k_prep<<<1673, 128>>>(dw2, dw3);
    k_enc1<<<1024, 256>>>(x, ew1, eb1);
    k_enc2<<<512, 128, 54088>>>(ew2, eb2);
    k_enc3z<<<256, 256>>>(ew3, eb3);
    k_vq2<<<2048, 256>>>(cb);
    k_vqfin<<<512, 256>>>();
    k_loss_out<<<1, 1>>>(out);
    k_dec1<<<512, 256>>>(cb, dw1, db1);
    k_dec2_mma<<<4096, 128, 98944>>>(db2);
    k_dec2_fix<<<128, 256, 107008>>>(dw2, db2);
    k_dec3_mma<<<4096, 128, 85504>>>(db3, out + 2);
    k_dec3_fix<<<128, 256, 139008>>>(dw3, db3, out + 2);
}

// round 14
// speedup vs baseline: 1.0083x; 1.0083x over previous
#include <cuda_runtime.h>

typedef unsigned long long u64;
typedef unsigned int u32;
__device__ __forceinline__ u64 pk2(float lo, float hi) {
    u64 r; asm("mov.b64 %0,{%1,%2};" : "=l"(r) : "f"(lo), "f"(hi)); return r;
}
__device__ __forceinline__ void upk2(u64 v, float& lo, float& hi) {
    asm("mov.b64 {%0,%1},%2;" : "=f"(lo), "=f"(hi) : "l"(v));
}
__device__ __forceinline__ void fma2(u64& d, u64 a, u64 b) {
    asm("fma.rn.f32x2 %0,%1,%2,%0;" : "+l"(d) : "l"(a), "l"(b));
}
__device__ __forceinline__ u64 add2(u64 a, u64 b) {
    u64 r; asm("add.rn.f32x2 %0,%1,%2;" : "=l"(r) : "l"(a), "l"(b)); return r;
}
__device__ __forceinline__ u32 to_tf32(float v) {
    u32 r; asm("cvt.rna.tf32.f32 %0, %1;" : "=r"(r) : "f"(v)); return r;
}
__device__ __forceinline__ void mma_tf32(float* c, const u32* a, u32 b0, u32 b1) {
    asm("mma.sync.aligned.m16n8k8.row.col.f32.tf32.tf32.f32 "
        "{%0,%1,%2,%3}, {%4,%5,%6,%7}, {%8,%9}, {%0,%1,%2,%3};"
        : "+f"(c[0]), "+f"(c[1]), "+f"(c[2]), "+f"(c[3])
        : "r"(a[0]), "r"(a[1]), "r"(a[2]), "r"(a[3]), "r"(b0), "r"(b1));
}
__device__ __forceinline__ void cp4(u32 dst, const float* src, bool pred) {
    asm volatile("cp.async.ca.shared.global [%0], [%1], 4, %2;"
                 :: "r"(dst), "l"(src), "r"(pred ? 4 : 0));
}
#define CP_COMMIT() asm volatile("cp.async.commit_group;")
#define CP_WAIT0()  asm volatile("cp.async.wait_group 0;")

// ---------------- scratch ----------------
__device__ float g_h1[(size_t)32*64*128*128];   // enc1 out, NCHW
__device__ float g_h2[(size_t)32*64*64*32];     // enc2 out, NHWC
__device__ int   g_idx[131072];
__device__ u64   g_z2[(size_t)32*131072];       // z pair-major [pair][px]
__device__ u64   g_vqkey[131072];               // packed (ordered score, idx)
__device__ float g_d1[(size_t)32*32*64*64];     // dec1 out, NCHW
__device__ float g_d2[(size_t)32*64*128*128];   // dec2 out, NCHW
__device__ float g_weff2[256*288];              // dec2 effective weights (tf32)
__device__ float g_weff3[16*576];               // dec3 effective weights (tf32)
__device__ float g_loss;

__device__ __forceinline__ u32 ordf(float f) {
    u32 u = __float_as_uint(f);
    return (u & 0x80000000u) ? ~u : (u | 0x80000000u);
}

// ---------------- parity matrices ----------------
__device__ __constant__ float c_M[2][3][3] = {
    {{0.75f,0.25f,0.f},{0.25f,0.75f,0.f},{0.f,0.75f,0.25f}},
    {{0.25f,0.75f,0.f},{0.f,0.75f,0.25f},{0.f,0.25f,0.75f}}};

// ---------------- prep: loss + weff2 + weff3 + vqkey init -------------------
__global__ void k_prep(const float* __restrict__ w2, const float* __restrict__ w3)
{
    int idx = blockIdx.x*128 + threadIdx.x;
    if (idx < 73728) {
        int m = idx / 288, k = idx - m*288;
        int oc = m >> 2, a = (m >> 1) & 1, bp = m & 1;
        int cin = k / 9, r = k - cin*9, dy = r / 3, dx = r - dy*3;
        float s = 0.f;
        #pragma unroll
        for (int ky = 0; ky < 3; ky++)
            #pragma unroll
            for (int kx = 0; kx < 3; kx++)
                s += w2[((oc*32+cin)*3+ky)*3+kx] * c_M[a][ky][dy] * c_M[bp][kx][dx];
        g_weff2[m*288 + k] = __uint_as_float(to_tf32(s));
    } else if (idx < 82944) {
        int j = idx - 73728;
        int m = j / 576, k = j - m*576;
        float s = 0.f;
        if (m < 12) {
            int oc = m >> 2, a = (m >> 1) & 1, bp = m & 1;
            int cin = k / 9, r = k - cin*9, dy = r / 3, dx = r - dy*3;
            #pragma unroll
            for (int ky = 0; ky < 3; ky++)
                #pragma unroll
                for (int kx = 0; kx < 3; kx++)
                    s += w3[((oc*64+cin)*3+ky)*3+kx] * c_M[a][ky][dy] * c_M[bp][kx][dx];
        }
        g_weff3[m*576 + k] = __uint_as_float(to_tf32(s));
    } else if (idx == 82944) {
        g_loss = 0.f;
    } else if (idx >= 82945 && idx < 82945 + 131072) {
        g_vqkey[idx - 82945] = 0xFFFFFFFFFFFFFFFFull;
    }
}

// ---------------- enc1 (unchanged) ----------------
__global__ __launch_bounds__(256) void k_enc1(const float* __restrict__ x,
                                              const float* __restrict__ w,
                                              const float* __restrict__ bias)
{
    __shared__ __align__(16) float sWt[27*64];
    __shared__ __align__(16) float sIn[3*33*65];
    __shared__ __align__(16) float sB[64];
    int blk = blockIdx.x;
    int img = blk >> 5;
    int tile = blk & 31;
    int tx0 = (tile & 3) * 32;
    int ty0 = (tile >> 2) * 16;
    int tid = threadIdx.x;
    for (int i = tid; i < 27*64; i += 256) {
        int t = i >> 6, o = i & 63;
        sWt[i] = w[o*27 + t];
    }
    if (tid < 64) sB[tid] = bias[tid];
    int iy0 = 2*ty0 - 1, ix0 = 2*tx0 - 1;
    const float* xim = x + (size_t)img*3*65536;
    for (int i = tid; i < 3*33*65; i += 256) {
        int c = i / (33*65); int rem = i - c*(33*65);
        int r = rem / 65; int cc = rem - r*65;
        int gy = iy0 + r, gx = ix0 + cc;
        float v = 0.f;
        if (gy >= 0 && gy < 256 && gx >= 0 && gx < 256)
            v = xim[(size_t)c*65536 + gy*256 + gx];
        sIn[i] = v;
    }
    __syncthreads();
    int tx = tid & 31, tyq = tid >> 5;
    float in[3][5][3];
    int lr0 = 4*tyq, lc0 = 2*tx;
    #pragma unroll
    for (int c = 0; c < 3; c++)
        #pragma unroll
        for (int r = 0; r < 5; r++)
            #pragma unroll
            for (int cc = 0; cc < 3; cc++)
                in[c][r][cc] = sIn[c*(33*65) + (lr0+r)*65 + lc0+cc];
    float* h1o = g_h1 + (size_t)img*64*16384;
    int oy = ty0 + 2*tyq, ox = tx0 + tx;
    #pragma unroll 1
    for (int half = 0; half < 2; half++) {
        int ocg = half * 32;
        u64 a0[16], a1[16];
        #pragma unroll
        for (int i = 0; i < 16; i++) {
            a0[i] = pk2(sB[ocg+2*i], sB[ocg+2*i+1]);
            a1[i] = a0[i];
        }
        #pragma unroll
        for (int c = 0; c < 3; c++)
            #pragma unroll
            for (int ky = 0; ky < 3; ky++)
                #pragma unroll
                for (int kx = 0; kx < 3; kx++) {
                    u64 vv0 = pk2(in[c][ky][kx], in[c][ky][kx]);
                    u64 vv1 = pk2(in[c][ky+2][kx], in[c][ky+2][kx]);
                    const ulonglong2* wp = reinterpret_cast<const ulonglong2*>(&sWt[(c*9+ky*3+kx)*64 + ocg]);
                    #pragma unroll
                    for (int q = 0; q < 8; q++) {
                        ulonglong2 wq = wp[q];
                        fma2(a0[2*q],   vv0, wq.x);
                        fma2(a0[2*q+1], vv0, wq.y);
                        fma2(a1[2*q],   vv1, wq.x);
                        fma2(a1[2*q+1], vv1, wq.y);
                    }
                }
        #pragma unroll
        for (int i = 0; i < 16; i++) {
            float l0, h0v, l1, h1v;
            upk2(a0[i], l0, h0v);
            upk2(a1[i], l1, h1v);
            h1o[(size_t)(ocg+2*i)*16384   + (size_t)oy*128 + ox]     = fmaxf(l0, 0.f);
            h1o[(size_t)(ocg+2*i+1)*16384 + (size_t)oy*128 + ox]     = fmaxf(h0v, 0.f);
            h1o[(size_t)(ocg+2*i)*16384   + (size_t)(oy+1)*128 + ox] = fmaxf(l1, 0.f);
            h1o[(size_t)(ocg+2*i+1)*16384 + (size_t)(oy+1)*128 + ox] = fmaxf(h1v, 0.f);
        }
    }
}

// ---------------- enc2: cp.async double-buffered (unchanged) ----------------
__global__ __launch_bounds__(128) void k_enc2(const float* __restrict__ w,
                                              const float* __restrict__ bias)
{
    extern __shared__ __align__(16) float se2[];
    float* sWt = se2;
    float* sInb[2] = { se2 + 9216, se2 + 9216 + 2145 };
    float* sB  = se2 + 9216 + 4290;
    int b = blockIdx.x;
    int og = b & 1;
    int t = (b >> 1) & 7;
    int img = b >> 4;
    int ox0 = (t & 1) * 32;
    int oy0 = (t >> 1) * 16;
    int tid = threadIdx.x;
    for (int i = tid; i < 9216; i += 128) {
        int o = i & 15, rc = i >> 4;
        sWt[i] = w[(og*16 + o)*576 + rc];
    }
    if (tid < 16) sB[tid] = bias[og*16 + tid];
    const float* h1im = g_h1 + (size_t)img*64*16384;
    int iy0 = 2*oy0 - 1, ix0 = 2*ox0 - 1;
    {
        u32 dst0 = (u32)__cvta_generic_to_shared(sInb[0]);
        for (int i = tid; i < 2145; i += 128) {
            int r = i / 65, cc = i - r*65;
            int gy = iy0 + r, gx = ix0 + cc;
            bool ok = (gy >= 0 && gy < 128 && gx >= 0 && gx < 128);
            cp4(dst0 + 4u*i, h1im + ((size_t)gy*128 + gx), ok);
        }
        CP_COMMIT();
    }
    int ttx = tid & 15, tty = tid >> 4;
    u64 acc[2][2][8];
    #pragma unroll 1
    for (int cin = 0; cin < 64; cin++) {
        float* cur = sInb[cin & 1];
        float* nxt = sInb[(cin & 1) ^ 1];
        CP_WAIT0();
        __syncthreads();
        if (cin == 0) {
            #pragma unroll
            for (int r = 0; r < 2; r++)
                #pragma unroll
                for (int cc = 0; cc < 2; cc++)
                    #pragma unroll
                    for (int p = 0; p < 8; p++) acc[r][cc][p] = pk2(sB[2*p], sB[2*p+1]);
        }
        if (cin < 63) {
            const float* hp = h1im + (size_t)(cin+1)*16384;
            u32 dstn = (u32)__cvta_generic_to_shared(nxt);
            for (int i = tid; i < 2145; i += 128) {
                int r = i / 65, cc = i - r*65;
                int gy = iy0 + r, gx = ix0 + cc;
                bool ok = (gy >= 0 && gy < 128 && gx >= 0 && gx < 128);
                cp4(dstn + 4u*i, hp + ((size_t)gy*128 + gx), ok);
            }
        }
        CP_COMMIT();
        float in[5][5];
        #pragma unroll
        for (int r = 0; r < 5; r++)
            #pragma unroll
            for (int c = 0; c < 5; c++)
                in[r][c] = cur[(4*tty + r)*65 + 4*ttx + c];
        #pragma unroll
        for (int ky = 0; ky < 3; ky++)
            #pragma unroll
            for (int kx = 0; kx < 3; kx++) {
                u64 vv[2][2];
                #pragma unroll
                for (int r = 0; r < 2; r++)
                    #pragma unroll
                    for (int cc = 0; cc < 2; cc++) {
                        float v = in[2*r+ky][2*cc+kx];
                        vv[r][cc] = pk2(v, v);
                    }
                const ulonglong2* wp = reinterpret_cast<const ulonglong2*>(&sWt[(cin*9+ky*3+kx)*16]);
                #pragma unroll
                for (int q = 0; q < 4; q++) {
                    ulonglong2 wq = wp[q];
                    #pragma unroll
                    for (int r = 0; r < 2; r++)
                        #pragma unroll
                        for (int cc = 0; cc < 2; cc++) {
                            fma2(acc[r][cc][2*q],   vv[r][cc], wq.x);
                            fma2(acc[r][cc][2*q+1], vv[r][cc], wq.y);
                        }
                }
            }
    }
    #pragma unroll
    for (int r = 0; r < 2; r++)
        #pragma unroll
        for (int cc = 0; cc < 2; cc++) {
            int oy = oy0 + 2*tty + r, ox = ox0 + 2*ttx + cc;
            float* dp = g_h2 + ((size_t)(img*64 + oy)*64 + ox)*32 + og*16;
            #pragma unroll
            for (int p = 0; p < 8; p++) {
                float lo, hi;
                upk2(acc[r][cc][p], lo, hi);
                dp[2*p]   = fmaxf(lo, 0.f);
                dp[2*p+1] = fmaxf(hi, 0.f);
            }
        }
}

// ---------------- enc3z (unchanged from R13) ----------------
__global__ __launch_bounds__(256) void k_enc3z(const float* __restrict__ w3,
                                               const float* __restrict__ b3)
{
    __shared__ __align__(16) float sW[2048];
    __shared__ __align__(16) float sB[64];
    int tid = threadIdx.x;
    for (int i = tid; i < 2048; i += 256) sW[i] = w3[i];
    if (tid < 64) sB[tid] = b3[tid];
    __syncthreads();
    int p0 = blockIdx.x*512 + tid;
    int p1 = p0 + 256;
    float h0[32], h1[32];
    {
        const float4* hp0 = reinterpret_cast<const float4*>(g_h2 + (size_t)p0*32);
        const float4* hp1 = reinterpret_cast<const float4*>(g_h2 + (size_t)p1*32);
        #pragma unroll
        for (int q = 0; q < 8; q++) {
            float4 v0 = hp0[q];
            h0[4*q] = v0.x; h0[4*q+1] = v0.y; h0[4*q+2] = v0.z; h0[4*q+3] = v0.w;
            float4 v1 = hp1[q];
            h1[4*q] = v1.x; h1[4*q+1] = v1.y; h1[4*q+2] = v1.z; h1[4*q+3] = v1.w;
        }
    }
    const float4* sW4 = reinterpret_cast<const float4*>(sW);
    u64 n0 = 0, n1 = 0;
    #pragma unroll 2
    for (int i = 0; i < 32; i++) {
        float a0 = 0.f, a1 = 0.f, b0 = 0.f, b1 = 0.f;
        #pragma unroll
        for (int q = 0; q < 8; q++) {
            float4 wa = sW4[(2*i)*8 + q];
            float4 wb = sW4[(2*i+1)*8 + q];
            a0 = fmaf(wa.x, h0[4*q],   a0); a0 = fmaf(wa.y, h0[4*q+1], a0);
            a0 = fmaf(wa.z, h0[4*q+2], a0); a0 = fmaf(wa.w, h0[4*q+3], a0);
            a1 = fmaf(wa.x, h1[4*q],   a1); a1 = fmaf(wa.y, h1[4*q+1], a1);
            a1 = fmaf(wa.z, h1[4*q+2], a1); a1 = fmaf(wa.w, h1[4*q+3], a1);
            b0 = fmaf(wb.x, h0[4*q],   b0); b0 = fmaf(wb.y, h0[4*q+1], b0);
            b0 = fmaf(wb.z, h0[4*q+2], b0); b0 = fmaf(wb.w, h0[4*q+3], b0);
            b1 = fmaf(wb.x, h1[4*q],   b1); b1 = fmaf(wb.y, h1[4*q+1], b1);
            b1 = fmaf(wb.z, h1[4*q+2], b1); b1 = fmaf(wb.w, h1[4*q+3], b1);
        }
        u64 z0 = pk2(sB[2*i] + a0, sB[2*i+1] + b0);
        u64 z1 = pk2(sB[2*i] + a1, sB[2*i+1] + b1);
        g_z2[(size_t)i*131072 + p0] = z0;
        g_z2[(size_t)i*131072 + p1] = z1;
        fma2(n0, z0, z0);
        fma2(n1, z1, z1);
    }
    float l0, h0v, l1, h1v;
    upk2(n0, l0, h0v);
    upk2(n1, l1, h1v);
    float s = (l0 + h0v) + (l1 + h1v);
    #pragma unroll
    for (int off = 16; off > 0; off >>= 1)
        s += __shfl_down_sync(0xffffffffu, s, off);
    if ((tid & 31) == 0) atomicAdd(&g_loss, s);
}

// ---------------- vq2: quartered argmin, 2 px/thread ------------------------
// grid 2048 = 512 px-chunks(256px) x 4 quarters; 128 thr, 2 px/thread.
__global__ __launch_bounds__(128) void k_vq2(const float* __restrict__ cb)
{
    __shared__ __align__(16) float sCB[128*64];   // 32 KB quarter
    __shared__ float sCn[128];
    int q = blockIdx.x & 3;
    int chunk = blockIdx.x >> 2;
    int tid = threadIdx.x;
    const float* cbq = cb + (size_t)q*128*64;
    {
        const float4* s4 = reinterpret_cast<const float4*>(cbq);
        float4* d4 = reinterpret_cast<float4*>(sCB);
        for (int i = tid; i < 2048; i += 128) d4[i] = s4[i];
    }
    __syncthreads();
    if (tid < 128) {
        float s = 0.f;
        #pragma unroll 8
        for (int d = 0; d < 64; d++) { float v = sCB[tid*64+d]; s = fmaf(v, v, s); }
        sCn[tid] = s;
    }
    __syncthreads();
    int p0 = chunk*256 + tid;
    int p1 = p0 + 128;
    u64 z20[32], z21[32];
    #pragma unroll
    for (int i = 0; i < 32; i++) {
        z20[i] = g_z2[(size_t)i*131072 + p0];
        z21[i] = g_z2[(size_t)i*131072 + p1];
    }
    const ulonglong2* sCB2 = reinterpret_cast<const ulonglong2*>(sCB);
    float best0 = 3.4e38f, best1 = 3.4e38f;
    int bi0 = 0, bi1 = 0;
    #pragma unroll 1
    for (int k = 0; k < 128; k++) {
        const ulonglong2* ck = sCB2 + k*16;
        u64 a0 = 0, a1 = 0, b0 = 0, b1 = 0;
        #pragma unroll
        for (int qq = 0; qq < 16; qq++) {
            ulonglong2 cq = ck[qq];
            fma2(a0, z20[2*qq],   cq.x);
            fma2(a1, z20[2*qq+1], cq.y);
            fma2(b0, z21[2*qq],   cq.x);
            fma2(b1, z21[2*qq+1], cq.y);
        }
        float cn = sCn[k];
        u64 sa = add2(a0, a1);
        u64 sb = add2(b0, b1);
        float la, ha, lb, hb;
        upk2(sa, la, ha);
        upk2(sb, lb, hb);
        float s0 = cn - 2.f*(la + ha);
        float s1 = cn - 2.f*(lb + hb);
        if (s0 < best0) { best0 = s0; bi0 = k; }
        if (s1 < best1) { best1 = s1; bi1 = k; }
    }
    u64 key0 = ((u64)ordf(best0) << 32) | (u32)(q*128 + bi0);
    u64 key1 = ((u64)ordf(best1) << 32) | (u32)(q*128 + bi1);
    atomicMin(&g_vqkey[p0], key0);
    atomicMin(&g_vqkey[p1], key1);
}

// ---------------- vqfin (unchanged) ----------------
__global__ __launch_bounds__(256) void k_vqfin()
{
    int p = blockIdx.x*256 + threadIdx.x;
    u64 key = g_vqkey[p];
    g_idx[p] = (int)(u32)key;
    u32 os = (u32)(key >> 32);
    u32 u = (os & 0x80000000u) ? (os ^ 0x80000000u) : ~os;
    float s = __uint_as_float(u);
    #pragma unroll
    for (int off = 16; off > 0; off >>= 1)
        s += __shfl_down_sync(0xffffffffu, s, off);
    if ((threadIdx.x & 31) == 0) atomicAdd(&g_loss, s);
}

__global__ void k_loss_out(float* __restrict__ out)
{
    float v = g_loss * (1.f/8388608.f);
    out[0] = v;
    out[1] = v;
}

// ---------------- dec1 (unchanged) ----------------
__global__ __launch_bounds__(256) void k_dec1(const float* __restrict__ cb,
                                              const float* __restrict__ w,
                                              const float* __restrict__ bias)
{
    __shared__ __align__(16) float sW[32*64];
    __shared__ __align__(16) float sB[32];
    int tid = threadIdx.x;
    for (int i = tid; i < 2048; i += 256) sW[i] = w[i];
    if (tid < 32) sB[tid] = bias[tid];
    __syncthreads();
    int p = blockIdx.x*256 + tid;
    int ki = g_idx[p];
    float c[64];
    const float4* cp = reinterpret_cast<const float4*>(cb + (size_t)ki*64);
    #pragma unroll
    for (int q = 0; q < 16; q++) {
        float4 v = cp[q];
        c[4*q] = v.x; c[4*q+1] = v.y; c[4*q+2] = v.z; c[4*q+3] = v.w;
    }
    int img = p >> 12;
    int rem = p & 4095;
    float* dp = g_d1 + (size_t)img*32*4096 + rem;
    const float4* sW4 = reinterpret_cast<const float4*>(sW);
    #pragma unroll 1
    for (int oc = 0; oc < 32; oc++) {
        float a0 = 0.f, a1 = 0.f, a2 = 0.f, a3 = 0.f;
        #pragma unroll
        for (int q = 0; q < 16; q++) {
            float4 wv = sW4[oc*16 + q];
            a0 = fmaf(wv.x, c[4*q],   a0);
            a1 = fmaf(wv.y, c[4*q+1], a1);
            a2 = fmaf(wv.z, c[4*q+2], a2);
            a3 = fmaf(wv.w, c[4*q+3], a3);
        }
        float v = sB[oc] + ((a0+a1) + (a2+a3));
        dp[(size_t)oc*4096] = fmaxf(v, 0.f);
    }
}

// ---------------- dec2 main mma (unchanged) ----------
__global__ __launch_bounds__(128) void k_dec2_mma(const float* __restrict__ bias)
{
    extern __shared__ __align__(16) float smx[];
    float* sA = smx;
    float* sX = smx + 64*292;
    int*   sK = (int*)(smx + 64*292 + 5760);
    int b = blockIdx.x;
    int mb = b & 3;
    int t = (b >> 2) & 31;
    int img = b >> 7;
    int tx0 = (t & 3) * 16;
    int ty0 = (t >> 2) * 8;
    int tid = threadIdx.x;
    {
        const float4* src = reinterpret_cast<const float4*>(g_weff2 + mb*64*288);
        for (int i = tid; i < 64*72; i += 128) {
            int r = i / 72, kq = (i - r*72)*4;
            float4 v = src[i];
            float* d = sA + r*292 + kq;
            d[0] = v.x; d[1] = v.y; d[2] = v.z; d[3] = v.w;
        }
    }
    for (int k = tid; k < 288; k += 128) {
        int cin = k / 9, rr = k - cin*9;
        sK[k] = cin*180 + (rr/3)*18 + (rr - (rr/3)*3);
    }
    const float* simg = g_d1 + (size_t)img*32*4096;
    for (int i = tid; i < 5760; i += 128) {
        int cin = i / 180;
        int rem = i - cin*180;
        int r = rem / 18, c = rem - r*18;
        int sy = ty0 - 1 + r; sy = max(0, min(63, sy));
        int sx = tx0 - 1 + c; sx = max(0, min(63, sx));
        sX[i] = __uint_as_float(to_tf32(simg[cin*4096 + sy*64 + sx]));
    }
    __syncthreads();
    int wid = tid >> 5, lane = tid & 31;
    int wm = wid & 1, wn = wid >> 1;
    int lg = lane >> 2, lig = lane & 3;
    float acc[2][8][4];
    #pragma unroll
    for (int mt = 0; mt < 2; mt++)
        #pragma unroll
        for (int nt = 0; nt < 8; nt++)
            #pragma unroll
            for (int c = 0; c < 4; c++) acc[mt][nt][c] = 0.f;
    int pb[8];
    #pragma unroll
    for (int nt = 0; nt < 8; nt++) {
        int n = wn*64 + nt*8 + lg;
        pb[nt] = (n >> 4)*18 + (n & 15);
    }
    const float* arow0 = sA + (wm*32 + lg)*292 + lig;
    const float* arow1 = arow0 + 16*292;
    u32 abuf[2][2][4];
    u32 bbuf[2][8][2];
    {
        int ko0 = sK[lig];
        int ko1 = sK[lig + 4];
        abuf[0][0][0] = __float_as_uint(arow0[0]);
        abuf[0][0][1] = __float_as_uint(arow0[8*292]);
        abuf[0][0][2] = __float_as_uint(arow0[4]);
        abuf[0][0][3] = __float_as_uint(arow0[8*292 + 4]);
        abuf[0][1][0] = __float_as_uint(arow1[0]);
        abuf[0][1][1] = __float_as_uint(arow1[8*292]);
        abuf[0][1][2] = __float_as_uint(arow1[4]);
        abuf[0][1][3] = __float_as_uint(arow1[8*292 + 4]);
        #pragma unroll
        for (int nt = 0; nt < 8; nt++) {
            bbuf[0][nt][0] = __float_as_uint(sX[ko0 + pb[nt]]);
            bbuf[0][nt][1] = __float_as_uint(sX[ko1 + pb[nt]]);
        }
    }
    #pragma unroll 2
    for (int ks = 0; ks < 36; ks++) {
        int cur = ks & 1, nxt = cur ^ 1;
        if (ks < 35) {
            int kb = (ks+1)*8;
            int ko0 = sK[kb + lig];
            int ko1 = sK[kb + lig + 4];
            const float* a0p = arow0 + kb;
            const float* a1p = arow1 + kb;
            abuf[nxt][0][0] = __float_as_uint(a0p[0]);
            abuf[nxt][0][1] = __float_as_uint(a0p[8*292]);
            abuf[nxt][0][2] = __float_as_uint(a0p[4]);
            abuf[nxt][0][3] = __float_as_uint(a0p[8*292 + 4]);
            abuf[nxt][1][0] = __float_as_uint(a1p[0]);
            abuf[nxt][1][1] = __float_as_uint(a1p[8*292]);
            abuf[nxt][1][2] = __float_as_uint(a1p[4]);
            abuf[nxt][1][3] = __float_as_uint(a1p[8*292 + 4]);
            #pragma unroll
            for (int nt = 0; nt < 8; nt++) {
                bbuf[nxt][nt][0] = __float_as_uint(sX[ko0 + pb[nt]]);
                bbuf[nxt][nt][1] = __float_as_uint(sX[ko1 + pb[nt]]);
            }
        }
        #pragma unroll
        for (int nt = 0; nt < 8; nt++) {
            mma_tf32(acc[0][nt], abuf[cur][0], bbuf[cur][nt][0], bbuf[cur][nt][1]);
            mma_tf32(acc[1][nt], abuf[cur][1], bbuf[cur][nt][0], bbuf[cur][nt][1]);
        }
    }
    #pragma unroll
    for (int mt = 0; mt < 2; mt++) {
        int mbase = mb*64 + wm*32 + mt*16 + lg;
        float bv0 = bias[mbase >> 2];
        float bv2 = bias[(mbase + 8) >> 2];
        #pragma unroll
        for (int nt = 0; nt < 8; nt++) {
            #pragma unroll
            for (int c = 0; c < 4; c++) {
                int m = mbase + ((c >= 2) ? 8 : 0);
                int n = wn*64 + nt*8 + 2*lig + (c & 1);
                int oc = m >> 2, ap = (m >> 1) & 1, bp2 = m & 1;
                int py = n >> 4, px = n & 15;
                int uy = 2*(ty0 + py) + ap, ux = 2*(tx0 + px) + bp2;
                float v = acc[mt][nt][c] + ((c >= 2) ? bv2 : bv0);
                g_d2[((size_t)(img*64 + oc)*128 + uy)*128 + ux] = fmaxf(v, 0.f);
            }
        }
    }
}

// ---------------- dec2 border fixup (unchanged) ----------------
__global__ __launch_bounds__(256) void k_dec2_fix(const float* __restrict__ w,
                                                  const float* __restrict__ bias)
{
    extern __shared__ __align__(16) float sf[];
    float* sW = sf;
    float* sT = sf + 18432;
    int side = blockIdx.x & 3;
    int img = blockIdx.x >> 2;
    int tid = threadIdx.x;
    for (int i = tid; i < 18432; i += 256) sW[i] = w[i];
    const float* xi = g_d1 + (size_t)img*32*4096;
    for (int i = tid; i < 32*2*130; i += 256) {
        int cin = i / 260;
        int rem = i - cin*260;
        int s = rem / 130, c = rem - s*130;
        const float* xp = xi + cin*4096;
        float v = 0.f;
        int u = c - 1;
        if (u >= 0 && u < 128) {
            int j = u >> 1;
            int ja, jb; float wa, wb;
            if (u & 1) { ja = j; jb = min(j+1, 63); wa = 0.75f; wb = 0.25f; }
            else       { ja = max(j-1, 0); jb = j;  wa = 0.25f; wb = 0.75f; }
            float xa, xb;
            if (side == 0) {
                if (s == 0) { xa = xp[ja]; xb = xp[jb]; }
                else { xa = 0.75f*xp[ja] + 0.25f*xp[64+ja];
                       xb = 0.75f*xp[jb] + 0.25f*xp[64+jb]; }
            } else if (side == 1) {
                const float* r62 = xp + 62*64; const float* r63 = xp + 63*64;
                if (s == 0) { xa = 0.25f*r62[ja] + 0.75f*r63[ja];
                              xb = 0.25f*r62[jb] + 0.75f*r63[jb]; }
                else { xa = r63[ja]; xb = r63[jb]; }
            } else if (side == 2) {
                if (s == 0) { xa = xp[ja*64]; xb = xp[jb*64]; }
                else { xa = 0.75f*xp[ja*64] + 0.25f*xp[ja*64+1];
                       xb = 0.75f*xp[jb*64] + 0.25f*xp[jb*64+1]; }
            } else {
                if (s == 0) { xa = 0.25f*xp[ja*64+62] + 0.75f*xp[ja*64+63];
                              xb = 0.25f*xp[jb*64+62] + 0.75f*xp[jb*64+63]; }
                else { xa = xp[ja*64+63]; xb = xp[jb*64+63]; }
            }
            v = wa*xa + wb*xb;
        }
        sT[i] = v;
    }
    __syncthreads();
    int oc = tid >> 2;
    int q = tid & 3;
    if (side <= 1) {
        int uy = (side == 0) ? 0 : 127;
        int ky0 = (side == 0) ? 1 : 0;
        for (int ux = q; ux < 128; ux += 4) {
            float acc = bias[oc];
            for (int cin = 0; cin < 32; cin++) {
                const float* wp = sW + (oc*32 + cin)*9;
                const float* tp = sT + cin*260;
                #pragma unroll
                for (int s = 0; s < 2; s++)
                    #pragma unroll
                    for (int kx = 0; kx < 3; kx++)
                        acc += wp[(ky0+s)*3 + kx] * tp[s*130 + ux + kx];
            }
            g_d2[((size_t)(img*64 + oc)*128 + uy)*128 + ux] = fmaxf(acc, 0.f);
        }
    } else {
        int ux = (side == 2) ? 0 : 127;
        int kx0 = (side == 2) ? 1 : 0;
        for (int uy = 1 + q; uy < 127; uy += 4) {
            float acc = bias[oc];
            for (int cin = 0; cin < 32; cin++) {
                const float* wp = sW + (oc*32 + cin)*9;
                const float* tp = sT + cin*260;
                #pragma unroll
                for (int s = 0; s < 2; s++)
                    #pragma unroll
                    for (int ky = 0; ky < 3; ky++)
                        acc += wp[ky*3 + kx0 + s] * tp[s*130 + uy + ky];
            }
            g_d2[((size_t)(img*64 + oc)*128 + uy)*128 + ux] = fmaxf(acc, 0.f);
        }
    }
}

// ---------------- dec3 main mma (unchanged) ----------
__global__ __launch_bounds__(128) void k_dec3_mma(const float* __restrict__ bias,
                                                  float* __restrict__ dst)
{
    extern __shared__ __align__(16) float sm3[];
    float* sA = sm3;
    float* sX = sm3 + 16*580;
    int*   sK = (int*)(sm3 + 16*580 + 11520);
    __shared__ float sB3[3];
    int b = blockIdx.x;
    int txt = b & 7;
    int tyt = (b >> 3) & 15;
    int img = b >> 7;
    int tx0 = txt * 16;
    int ty0 = tyt * 8;
    int tid = threadIdx.x;
    {
        const float4* src = reinterpret_cast<const float4*>(g_weff3);
        for (int i = tid; i < 16*144; i += 128) {
            int r = i / 144, kq = (i - r*144)*4;
            float4 v = src[i];
            float* d = sA + r*580 + kq;
            d[0] = v.x; d[1] = v.y; d[2] = v.z; d[3] = v.w;
        }
    }
    for (int k = tid; k < 576; k += 128) {
        int cin = k / 9, rr = k - cin*9;
        sK[k] = cin*180 + (rr/3)*18 + (rr - (rr/3)*3);
    }
    if (tid < 3) sB3[tid] = bias[tid];
    const float* simg = g_d2 + (size_t)img*64*16384;
    for (int i = tid; i < 11520; i += 128) {
        int cin = i / 180;
        int rem = i - cin*180;
        int r = rem / 18, c = rem - r*18;
        int sy = ty0 - 1 + r; sy = max(0, min(127, sy));
        int sx = tx0 - 1 + c; sx = max(0, min(127, sx));
        sX[i] = __uint_as_float(to_tf32(simg[cin*16384 + sy*128 + sx]));
    }
    __syncthreads();
    int wn = tid >> 5, lane = tid & 31;
    int lg = lane >> 2, lig = lane & 3;
    float acc[4][4];
    #pragma unroll
    for (int nt = 0; nt < 4; nt++)
        #pragma unroll
        for (int c = 0; c < 4; c++) acc[nt][c] = 0.f;
    int pb[4];
    #pragma unroll
    for (int nt = 0; nt < 4; nt++) {
        int n = wn*32 + nt*8 + lg;
        pb[nt] = (n >> 4)*18 + (n & 15);
    }
    const float* arow = sA + lg*580 + lig;
    u32 abuf[2][4];
    u32 bbuf[2][4][2];
    {
        int ko0 = sK[lig];
        int ko1 = sK[lig + 4];
        abuf[0][0] = __float_as_uint(arow[0]);
        abuf[0][1] = __float_as_uint(arow[8*580]);
        abuf[0][2] = __float_as_uint(arow[4]);
        abuf[0][3] = __float_as_uint(arow[8*580 + 4]);
        #pragma unroll
        for (int nt = 0; nt < 4; nt++) {
            bbuf[0][nt][0] = __float_as_uint(sX[ko0 + pb[nt]]);
            bbuf[0][nt][1] = __float_as_uint(sX[ko1 + pb[nt]]);
        }
    }
    #pragma unroll 2
    for (int ks = 0; ks < 72; ks++) {
        int cur = ks & 1, nxt = cur ^ 1;
        if (ks < 71) {
            int kb = (ks+1)*8;
            int ko0 = sK[kb + lig];
            int ko1 = sK[kb + lig + 4];
            const float* ap = arow + kb;
            abuf[nxt][0] = __float_as_uint(ap[0]);
            abuf[nxt][1] = __float_as_uint(ap[8*580]);
            abuf[nxt][2] = __float_as_uint(ap[4]);
            abuf[nxt][3] = __float_as_uint(ap[8*580 + 4]);
            #pragma unroll
            for (int nt = 0; nt < 4; nt++) {
                bbuf[nxt][nt][0] = __float_as_uint(sX[ko0 + pb[nt]]);
                bbuf[nxt][nt][1] = __float_as_uint(sX[ko1 + pb[nt]]);
            }
        }
        #pragma unroll
        for (int nt = 0; nt < 4; nt++)
            mma_tf32(acc[nt], abuf[cur], bbuf[cur][nt][0], bbuf[cur][nt][1]);
    }
    #pragma unroll
    for (int nt = 0; nt < 4; nt++) {
        #pragma unroll
        for (int c = 0; c < 4; c++) {
            int m = lg + ((c >= 2) ? 8 : 0);
            if (m < 12) {
                int oc = m >> 2, ap = (m >> 1) & 1, bp = m & 1;
                int n = wn*32 + nt*8 + 2*lig + (c & 1);
                int uy = 2*(ty0 + (n >> 4)) + ap;
                int ux = 2*(tx0 + (n & 15)) + bp;
                dst[(((size_t)(img*3 + oc)) << 16) + uy*256 + ux] = acc[nt][c] + sB3[oc];
            }
        }
    }
}

// ---------------- dec3 border fixup (unchanged) ---------
__global__ __launch_bounds__(256) void k_dec3_fix(const float* __restrict__ w,
                                                  const float* __restrict__ bias,
                                                  float* __restrict__ dst)
{
    extern __shared__ __align__(16) float sf3[];
    float* sW = sf3;
    float* sT = sf3 + 1728;
    int side = blockIdx.x & 3;
    int img = blockIdx.x >> 2;
    int tid = threadIdx.x;
    for (int i = tid; i < 1728; i += 256) sW[i] = w[i];
    const float* xi = g_d2 + (size_t)img*64*16384;
    for (int i = tid; i < 64*2*258; i += 256) {
        int cin = i / 516;
        int rem = i - cin*516;
        int s = rem / 258, c = rem - s*258;
        const float* xp = xi + cin*16384;
        float v = 0.f;
        int u = c - 1;
        if (u >= 0 && u < 256) {
            int j = u >> 1;
            int ja, jb; float wa, wb;
            if (u & 1) { ja = j; jb = min(j+1, 127); wa = 0.75f; wb = 0.25f; }
            else       { ja = max(j-1, 0); jb = j;   wa = 0.25f; wb = 0.75f; }
            float xa, xb;
            if (side == 0) {
                if (s == 0) { xa = xp[ja]; xb = xp[jb]; }
                else { xa = 0.75f*xp[ja] + 0.25f*xp[128+ja];
                       xb = 0.75f*xp[jb] + 0.25f*xp[128+jb]; }
            } else if (side == 1) {
                const float* rA = xp + 126*128; const float* rB = xp + 127*128;
                if (s == 0) { xa = 0.25f*rA[ja] + 0.75f*rB[ja];
                              xb = 0.25f*rA[jb] + 0.75f*rB[jb]; }
                else { xa = rB[ja]; xb = rB[jb]; }
            } else if (side == 2) {
                if (s == 0) { xa = xp[ja*128]; xb = xp[jb*128]; }
                else { xa = 0.75f*xp[ja*128] + 0.25f*xp[ja*128+1];
                       xb = 0.75f*xp[jb*128] + 0.25f*xp[jb*128+1]; }
            } else {
                if (s == 0) { xa = 0.25f*xp[ja*128+126] + 0.75f*xp[ja*128+127];
                              xb = 0.25f*xp[jb*128+126] + 0.75f*xp[jb*128+127]; }
                else { xa = xp[ja*128+127]; xb = xp[jb*128+127]; }
            }
            v = wa*xa + wb*xb;
        }
        sT[i] = v;
    }
    __syncthreads();
    if (side <= 1) {
        int uy = (side == 0) ? 0 : 255;
        int ky0 = (side == 0) ? 1 : 0;
        for (int idx = tid; idx < 3*256; idx += 256) {
            int oc = idx >> 8, ux = idx & 255;
            float acc = bias[oc];
            for (int cin = 0; cin < 64; cin++) {
                const float* wp = sW + (oc*64 + cin)*9;
                const float* tp = sT + cin*516;
                #pragma unroll
                for (int s = 0; s < 2; s++)
                    #pragma unroll
                    for (int kx = 0; kx < 3; kx++)
                        acc += wp[(ky0+s)*3 + kx] * tp[s*258 + ux + kx];
            }
            dst[(((size_t)(img*3 + oc)) << 16) + uy*256 + ux] = acc;
        }
    } else {
        int ux = (side == 2) ? 0 : 255;
        int kx0 = (side == 2) ? 1 : 0;
        for (int idx = tid; idx < 3*254; idx += 256) {
            int oc = idx / 254;
            int uy = 1 + idx - oc*254;
            float acc = bias[oc];
            for (int cin = 0; cin < 64; cin++) {
                const float* wp = sW + (oc*64 + cin)*9;
                const float* tp = sT + cin*516;
                #pragma unroll
                for (int s = 0; s < 2; s++)
                    #pragma unroll
                    for (int ky = 0; ky < 3; ky++)
                        acc += wp[ky*3 + kx0 + s] * tp[s*258 + uy + ky];
            }
            dst[(((size_t)(img*3 + oc)) << 16) + uy*256 + ux] = acc;
        }
    }
}

// ---------------- host launch ----------------
extern "C" void kernel_launch(void* const* d_in, const int* in_sizes, int n_in,
                              void* d_out, int out_size) {
    const float* x   = (const float*)d_in[0];
    const float* cb  = (const float*)d_in[1];
    const float* ew1 = (const float*)d_in[2];
    const float* eb1 = (const float*)d_in[3];
    const float* ew2 = (const float*)d_in[4];
    const float* eb2 = (const float*)d_in[5];
    const float* ew3 = (const float*)d_in[6];
    const float* eb3 = (const float*)d_in[7];
    const float* dw1 = (const float*)d_in[8];
    const float* db1 = (const float*)d_in[9];
    const float* dw2 = (const float*)d_in[10];
    const float* db2 = (const float*)d_in[11];
    const float* dw3 = (const float*)d_in[12];
    const float* db3 = (const float*)d_in[13];
    float* out = (float*)d_out;

    cudaFuncSetAttribute(k_enc2, cudaFuncAttributeMaxDynamicSharedMemorySize, 54088);
    cudaFuncSetAttribute(k_dec2_mma, cudaFuncAttributeMaxDynamicSharedMemorySize, 98944);
    cudaFuncSetAttribute(k_dec2_fix, cudaFuncAttributeMaxDynamicSharedMemorySize, 107008);
    cudaFuncSetAttribute(k_dec3_mma, cudaFuncAttributeMaxDynamicSharedMemorySize, 85504);
    cudaFuncSetAttribute(k_dec3_fix, cudaFuncAttributeMaxDynamicSharedMemorySize, 139008);

    k_prep<<<1673, 128>>>(dw2, dw3);
    k_enc1<<<1024, 256>>>(x, ew1, eb1);
    k_enc2<<<512, 128, 54088>>>(ew2, eb2);
    k_enc3z<<<256, 256>>>(ew3, eb3);
    k_vq2<<<2048, 128>>>(cb);
    k_vqfin<<<512, 256>>>();
    k_loss_out<<<1, 1>>>(out);
    k_dec1<<<512, 256>>>(cb, dw1, db1);
    k_dec2_mma<<<4096, 128, 98944>>>(db2);
    k_dec2_fix<<<128, 256, 107008>>>(dw2, db2);
    k_dec3_mma<<<4096, 128, 85504>>>(db3, out + 2);
    k_dec3_fix<<<128, 256, 139008>>>(dw3, db3, out + 2);
}

// round 15
// speedup vs baseline: 1.0396x; 1.0310x over previous
#include <cuda_runtime.h>

typedef unsigned long long u64;
typedef unsigned int u32;
__device__ __forceinline__ u64 pk2(float lo, float hi) {
    u64 r; asm("mov.b64 %0,{%1,%2};" : "=l"(r) : "f"(lo), "f"(hi)); return r;
}
__device__ __forceinline__ void upk2(u64 v, float& lo, float& hi) {
    asm("mov.b64 {%0,%1},%2;" : "=f"(lo), "=f"(hi) : "l"(v));
}
__device__ __forceinline__ void fma2(u64& d, u64 a, u64 b) {
    asm("fma.rn.f32x2 %0,%1,%2,%0;" : "+l"(d) : "l"(a), "l"(b));
}
__device__ __forceinline__ u64 add2(u64 a, u64 b) {
    u64 r; asm("add.rn.f32x2 %0,%1,%2;" : "=l"(r) : "l"(a), "l"(b)); return r;
}
__device__ __forceinline__ u32 to_tf32(float v) {
    u32 r; asm("cvt.rna.tf32.f32 %0, %1;" : "=r"(r) : "f"(v)); return r;
}
__device__ __forceinline__ void mma_tf32(float* c, const u32* a, u32 b0, u32 b1) {
    asm("mma.sync.aligned.m16n8k8.row.col.f32.tf32.tf32.f32 "
        "{%0,%1,%2,%3}, {%4,%5,%6,%7}, {%8,%9}, {%0,%1,%2,%3};"
        : "+f"(c[0]), "+f"(c[1]), "+f"(c[2]), "+f"(c[3])
        : "r"(a[0]), "r"(a[1]), "r"(a[2]), "r"(a[3]), "r"(b0), "r"(b1));
}
__device__ __forceinline__ void cp4(u32 dst, const float* src, bool pred) {
    asm volatile("cp.async.ca.shared.global [%0], [%1], 4, %2;"
                 :: "r"(dst), "l"(src), "r"(pred ? 4 : 0));
}
#define CP_COMMIT() asm volatile("cp.async.commit_group;")
#define CP_WAIT0()  asm volatile("cp.async.wait_group 0;")

// ---------------- scratch ----------------
__device__ float g_h1[(size_t)32*64*128*128];   // enc1 out, NCHW
__device__ float g_h2[(size_t)32*64*64*32];     // enc2 out, NHWC
__device__ int   g_idx[131072];
__device__ float g_d1[(size_t)32*32*64*64];     // dec1 out, NCHW
__device__ float g_d2[(size_t)32*64*128*128];   // dec2 out, NCHW
__device__ float g_weff2[256*288];              // dec2 effective weights (tf32)
__device__ float g_weff3[16*576];               // dec3 effective weights (tf32)
__device__ float g_loss;

// ---------------- parity matrices ----------------
__device__ __constant__ float c_M[2][3][3] = {
    {{0.75f,0.25f,0.f},{0.25f,0.75f,0.f},{0.f,0.75f,0.25f}},
    {{0.25f,0.75f,0.f},{0.f,0.75f,0.25f},{0.f,0.25f,0.75f}}};

// ---------------- prep: zero loss + weff2 + weff3 ----------------
__global__ void k_prep(const float* __restrict__ w2, const float* __restrict__ w3)
{
    int idx = blockIdx.x*128 + threadIdx.x;
    if (idx < 73728) {
        int m = idx / 288, k = idx - m*288;
        int oc = m >> 2, a = (m >> 1) & 1, bp = m & 1;
        int cin = k / 9, r = k - cin*9, dy = r / 3, dx = r - dy*3;
        float s = 0.f;
        #pragma unroll
        for (int ky = 0; ky < 3; ky++)
            #pragma unroll
            for (int kx = 0; kx < 3; kx++)
                s += w2[((oc*32+cin)*3+ky)*3+kx] * c_M[a][ky][dy] * c_M[bp][kx][dx];
        g_weff2[m*288 + k] = __uint_as_float(to_tf32(s));
    } else if (idx < 82944) {
        int j = idx - 73728;
        int m = j / 576, k = j - m*576;
        float s = 0.f;
        if (m < 12) {
            int oc = m >> 2, a = (m >> 1) & 1, bp = m & 1;
            int cin = k / 9, r = k - cin*9, dy = r / 3, dx = r - dy*3;
            #pragma unroll
            for (int ky = 0; ky < 3; ky++)
                #pragma unroll
                for (int kx = 0; kx < 3; kx++)
                    s += w3[((oc*64+cin)*3+ky)*3+kx] * c_M[a][ky][dy] * c_M[bp][kx][dx];
        }
        g_weff3[m*576 + k] = __uint_as_float(to_tf32(s));
    } else if (idx == 82944) {
        g_loss = 0.f;
    }
}

// ---------------- enc1: 2 CTA/SM via launch bounds ----------------
__global__ __launch_bounds__(256, 2) void k_enc1(const float* __restrict__ x,
                                                 const float* __restrict__ w,
                                                 const float* __restrict__ bias)
{
    __shared__ __align__(16) float sWt[27*64];
    __shared__ __align__(16) float sIn[3*33*65];
    __shared__ __align__(16) float sB[64];
    int blk = blockIdx.x;
    int img = blk >> 5;
    int tile = blk & 31;
    int tx0 = (tile & 3) * 32;
    int ty0 = (tile >> 2) * 16;
    int tid = threadIdx.x;
    for (int i = tid; i < 27*64; i += 256) {
        int t = i >> 6, o = i & 63;
        sWt[i] = w[o*27 + t];
    }
    if (tid < 64) sB[tid] = bias[tid];
    int iy0 = 2*ty0 - 1, ix0 = 2*tx0 - 1;
    const float* xim = x + (size_t)img*3*65536;
    for (int i = tid; i < 3*33*65; i += 256) {
        int c = i / (33*65); int rem = i - c*(33*65);
        int r = rem / 65; int cc = rem - r*65;
        int gy = iy0 + r, gx = ix0 + cc;
        float v = 0.f;
        if (gy >= 0 && gy < 256 && gx >= 0 && gx < 256)
            v = xim[(size_t)c*65536 + gy*256 + gx];
        sIn[i] = v;
    }
    __syncthreads();
    int tx = tid & 31, tyq = tid >> 5;
    float in[3][5][3];
    int lr0 = 4*tyq, lc0 = 2*tx;
    #pragma unroll
    for (int c = 0; c < 3; c++)
        #pragma unroll
        for (int r = 0; r < 5; r++)
            #pragma unroll
            for (int cc = 0; cc < 3; cc++)
                in[c][r][cc] = sIn[c*(33*65) + (lr0+r)*65 + lc0+cc];
    float* h1o = g_h1 + (size_t)img*64*16384;
    int oy = ty0 + 2*tyq, ox = tx0 + tx;
    #pragma unroll 1
    for (int half = 0; half < 2; half++) {
        int ocg = half * 32;
        u64 a0[16], a1[16];
        #pragma unroll
        for (int i = 0; i < 16; i++) {
            a0[i] = pk2(sB[ocg+2*i], sB[ocg+2*i+1]);
            a1[i] = a0[i];
        }
        #pragma unroll
        for (int c = 0; c < 3; c++)
            #pragma unroll
            for (int ky = 0; ky < 3; ky++)
                #pragma unroll
                for (int kx = 0; kx < 3; kx++) {
                    u64 vv0 = pk2(in[c][ky][kx], in[c][ky][kx]);
                    u64 vv1 = pk2(in[c][ky+2][kx], in[c][ky+2][kx]);
                    const ulonglong2* wp = reinterpret_cast<const ulonglong2*>(&sWt[(c*9+ky*3+kx)*64 + ocg]);
                    #pragma unroll
                    for (int q = 0; q < 8; q++) {
                        ulonglong2 wq = wp[q];
                        fma2(a0[2*q],   vv0, wq.x);
                        fma2(a0[2*q+1], vv0, wq.y);
                        fma2(a1[2*q],   vv1, wq.x);
                        fma2(a1[2*q+1], vv1, wq.y);
                    }
                }
        #pragma unroll
        for (int i = 0; i < 16; i++) {
            float l0, h0v, l1, h1v;
            upk2(a0[i], l0, h0v);
            upk2(a1[i], l1, h1v);
            h1o[(size_t)(ocg+2*i)*16384   + (size_t)oy*128 + ox]     = fmaxf(l0, 0.f);
            h1o[(size_t)(ocg+2*i+1)*16384 + (size_t)oy*128 + ox]     = fmaxf(h0v, 0.f);
            h1o[(size_t)(ocg+2*i)*16384   + (size_t)(oy+1)*128 + ox] = fmaxf(l1, 0.f);
            h1o[(size_t)(ocg+2*i+1)*16384 + (size_t)(oy+1)*128 + ox] = fmaxf(h1v, 0.f);
        }
    }
}

// ---------------- enc2: cp.async double-buffered (R12, unchanged) -----------
__global__ __launch_bounds__(128) void k_enc2(const float* __restrict__ w,
                                              const float* __restrict__ bias)
{
    extern __shared__ __align__(16) float se2[];
    float* sWt = se2;
    float* sInb[2] = { se2 + 9216, se2 + 9216 + 2145 };
    float* sB  = se2 + 9216 + 4290;
    int b = blockIdx.x;
    int og = b & 1;
    int t = (b >> 1) & 7;
    int img = b >> 4;
    int ox0 = (t & 1) * 32;
    int oy0 = (t >> 1) * 16;
    int tid = threadIdx.x;
    for (int i = tid; i < 9216; i += 128) {
        int o = i & 15, rc = i >> 4;
        sWt[i] = w[(og*16 + o)*576 + rc];
    }
    if (tid < 16) sB[tid] = bias[og*16 + tid];
    const float* h1im = g_h1 + (size_t)img*64*16384;
    int iy0 = 2*oy0 - 1, ix0 = 2*ox0 - 1;
    {
        u32 dst0 = (u32)__cvta_generic_to_shared(sInb[0]);
        for (int i = tid; i < 2145; i += 128) {
            int r = i / 65, cc = i - r*65;
            int gy = iy0 + r, gx = ix0 + cc;
            bool ok = (gy >= 0 && gy < 128 && gx >= 0 && gx < 128);
            cp4(dst0 + 4u*i, h1im + ((size_t)gy*128 + gx), ok);
        }
        CP_COMMIT();
    }
    int ttx = tid & 15, tty = tid >> 4;
    u64 acc[2][2][8];
    #pragma unroll 1
    for (int cin = 0; cin < 64; cin++) {
        float* cur = sInb[cin & 1];
        float* nxt = sInb[(cin & 1) ^ 1];
        CP_WAIT0();
        __syncthreads();
        if (cin == 0) {
            #pragma unroll
            for (int r = 0; r < 2; r++)
                #pragma unroll
                for (int cc = 0; cc < 2; cc++)
                    #pragma unroll
                    for (int p = 0; p < 8; p++) acc[r][cc][p] = pk2(sB[2*p], sB[2*p+1]);
        }
        if (cin < 63) {
            const float* hp = h1im + (size_t)(cin+1)*16384;
            u32 dstn = (u32)__cvta_generic_to_shared(nxt);
            for (int i = tid; i < 2145; i += 128) {
                int r = i / 65, cc = i - r*65;
                int gy = iy0 + r, gx = ix0 + cc;
                bool ok = (gy >= 0 && gy < 128 && gx >= 0 && gx < 128);
                cp4(dstn + 4u*i, hp + ((size_t)gy*128 + gx), ok);
            }
        }
        CP_COMMIT();
        float in[5][5];
        #pragma unroll
        for (int r = 0; r < 5; r++)
            #pragma unroll
            for (int c = 0; c < 5; c++)
                in[r][c] = cur[(4*tty + r)*65 + 4*ttx + c];
        #pragma unroll
        for (int ky = 0; ky < 3; ky++)
            #pragma unroll
            for (int kx = 0; kx < 3; kx++) {
                u64 vv[2][2];
                #pragma unroll
                for (int r = 0; r < 2; r++)
                    #pragma unroll
                    for (int cc = 0; cc < 2; cc++) {
                        float v = in[2*r+ky][2*cc+kx];
                        vv[r][cc] = pk2(v, v);
                    }
                const ulonglong2* wp = reinterpret_cast<const ulonglong2*>(&sWt[(cin*9+ky*3+kx)*16]);
                #pragma unroll
                for (int q = 0; q < 4; q++) {
                    ulonglong2 wq = wp[q];
                    #pragma unroll
                    for (int r = 0; r < 2; r++)
                        #pragma unroll
                        for (int cc = 0; cc < 2; cc++) {
                            fma2(acc[r][cc][2*q],   vv[r][cc], wq.x);
                            fma2(acc[r][cc][2*q+1], vv[r][cc], wq.y);
                        }
                }
            }
    }
    #pragma unroll
    for (int r = 0; r < 2; r++)
        #pragma unroll
        for (int cc = 0; cc < 2; cc++) {
            int oy = oy0 + 2*tty + r, ox = ox0 + 2*ttx + cc;
            float* dp = g_h2 + ((size_t)(img*64 + oy)*64 + ox)*32 + og*16;
            #pragma unroll
            for (int p = 0; p < 8; p++) {
                float lo, hi;
                upk2(acc[r][cc][p], lo, hi);
                dp[2*p]   = fmaxf(lo, 0.f);
                dp[2*p+1] = fmaxf(hi, 0.f);
            }
        }
}

// ---------------- enc3 + VQ: R12 monolithic (best measured) ----------------
__global__ __launch_bounds__(256) void k_enc3_vq(const float* __restrict__ w3,
                                                 const float* __restrict__ b3,
                                                 const float* __restrict__ cb)
{
    extern __shared__ __align__(16) float sm[];
    float* sCB = sm;
    float* sCn = sm + 32768;
    float* sW  = sm + 33280;
    float* sB  = sm + 35328;
    int tid = threadIdx.x;
    for (int i = tid; i < 32768; i += 256) sCB[i] = cb[i];
    for (int i = tid; i < 2048; i += 256) sW[i] = w3[i];
    if (tid < 64) sB[tid] = b3[tid];
    __syncthreads();
    for (int k = tid; k < 512; k += 256) {
        float s = 0.f;
        #pragma unroll 8
        for (int d = 0; d < 64; d++) { float v = sCB[k*64+d]; s = fmaf(v, v, s); }
        sCn[k] = s;
    }
    __syncthreads();
    int p0 = blockIdx.x*512 + tid;
    int p1 = p0 + 256;
    float h0[32], h1[32];
    {
        const float4* hp0 = reinterpret_cast<const float4*>(g_h2 + (size_t)p0*32);
        const float4* hp1 = reinterpret_cast<const float4*>(g_h2 + (size_t)p1*32);
        #pragma unroll
        for (int q = 0; q < 8; q++) {
            float4 v0 = hp0[q];
            h0[4*q] = v0.x; h0[4*q+1] = v0.y; h0[4*q+2] = v0.z; h0[4*q+3] = v0.w;
            float4 v1 = hp1[q];
            h1[4*q] = v1.x; h1[4*q+1] = v1.y; h1[4*q+2] = v1.z; h1[4*q+3] = v1.w;
        }
    }
    u64 z20[32], z21[32];
    const float4* sW4 = reinterpret_cast<const float4*>(sW);
    #pragma unroll 2
    for (int i = 0; i < 32; i++) {
        float a0 = 0.f, a1 = 0.f, b0 = 0.f, b1 = 0.f;
        #pragma unroll
        for (int q = 0; q < 8; q++) {
            float4 wa = sW4[(2*i)*8 + q];
            float4 wb = sW4[(2*i+1)*8 + q];
            a0 = fmaf(wa.x, h0[4*q],   a0); a0 = fmaf(wa.y, h0[4*q+1], a0);
            a0 = fmaf(wa.z, h0[4*q+2], a0); a0 = fmaf(wa.w, h0[4*q+3], a0);
            a1 = fmaf(wa.x, h1[4*q],   a1); a1 = fmaf(wa.y, h1[4*q+1], a1);
            a1 = fmaf(wa.z, h1[4*q+2], a1); a1 = fmaf(wa.w, h1[4*q+3], a1);
            b0 = fmaf(wb.x, h0[4*q],   b0); b0 = fmaf(wb.y, h0[4*q+1], b0);
            b0 = fmaf(wb.z, h0[4*q+2], b0); b0 = fmaf(wb.w, h0[4*q+3], b0);
            b1 = fmaf(wb.x, h1[4*q],   b1); b1 = fmaf(wb.y, h1[4*q+1], b1);
            b1 = fmaf(wb.z, h1[4*q+2], b1); b1 = fmaf(wb.w, h1[4*q+3], b1);
        }
        z20[i] = pk2(sB[2*i] + a0, sB[2*i+1] + b0);
        z21[i] = pk2(sB[2*i] + a1, sB[2*i+1] + b1);
    }
    const ulonglong2* sCB2 = reinterpret_cast<const ulonglong2*>(sCB);
    float best0 = 3.4e38f, best1 = 3.4e38f;
    int bi0 = 0, bi1 = 0;
    #pragma unroll 1
    for (int k = 0; k < 512; k++) {
        const ulonglong2* ck = sCB2 + k*16;
        u64 a0 = 0, a1 = 0, b0 = 0, b1 = 0;
        #pragma unroll
        for (int q = 0; q < 16; q++) {
            ulonglong2 cq = ck[q];
            fma2(a0, z20[2*q],   cq.x);
            fma2(a1, z20[2*q+1], cq.y);
            fma2(b0, z21[2*q],   cq.x);
            fma2(b1, z21[2*q+1], cq.y);
        }
        float cn = sCn[k];
        u64 sa = add2(a0, a1);
        u64 sb = add2(b0, b1);
        float la, ha, lb, hb;
        upk2(sa, la, ha);
        upk2(sb, lb, hb);
        float s0 = cn - 2.f*(la + ha);
        float s1 = cn - 2.f*(lb + hb);
        if (s0 < best0) { best0 = s0; bi0 = k; }
        if (s1 < best1) { best1 = s1; bi1 = k; }
    }
    g_idx[p0] = bi0;
    g_idx[p1] = bi1;
    u64 n0 = 0, n1 = 0;
    #pragma unroll
    for (int i = 0; i < 32; i++) {
        fma2(n0, z20[i], z20[i]);
        fma2(n1, z21[i], z21[i]);
    }
    float l0, h0v, l1, h1v;
    upk2(n0, l0, h0v);
    upk2(n1, l1, h1v);
    float s = (best0 + (l0 + h0v)) + (best1 + (l1 + h1v));
    #pragma unroll
    for (int off = 16; off > 0; off >>= 1)
        s += __shfl_down_sync(0xffffffffu, s, off);
    if ((tid & 31) == 0) atomicAdd(&g_loss, s);
}

__global__ void k_loss_out(float* __restrict__ out)
{
    float v = g_loss * (1.f/8388608.f);
    out[0] = v;
    out[1] = v;
}

// ---------------- dec1 (unchanged) ----------------
__global__ __launch_bounds__(256) void k_dec1(const float* __restrict__ cb,
                                              const float* __restrict__ w,
                                              const float* __restrict__ bias)
{
    __shared__ __align__(16) float sW[32*64];
    __shared__ __align__(16) float sB[32];
    int tid = threadIdx.x;
    for (int i = tid; i < 2048; i += 256) sW[i] = w[i];
    if (tid < 32) sB[tid] = bias[tid];
    __syncthreads();
    int p = blockIdx.x*256 + tid;
    int ki = g_idx[p];
    float c[64];
    const float4* cp = reinterpret_cast<const float4*>(cb + (size_t)ki*64);
    #pragma unroll
    for (int q = 0; q < 16; q++) {
        float4 v = cp[q];
        c[4*q] = v.x; c[4*q+1] = v.y; c[4*q+2] = v.z; c[4*q+3] = v.w;
    }
    int img = p >> 12;
    int rem = p & 4095;
    float* dp = g_d1 + (size_t)img*32*4096 + rem;
    const float4* sW4 = reinterpret_cast<const float4*>(sW);
    #pragma unroll 1
    for (int oc = 0; oc < 32; oc++) {
        float a0 = 0.f, a1 = 0.f, a2 = 0.f, a3 = 0.f;
        #pragma unroll
        for (int q = 0; q < 16; q++) {
            float4 wv = sW4[oc*16 + q];
            a0 = fmaf(wv.x, c[4*q],   a0);
            a1 = fmaf(wv.y, c[4*q+1], a1);
            a2 = fmaf(wv.z, c[4*q+2], a2);
            a3 = fmaf(wv.w, c[4*q+3], a3);
        }
        float v = sB[oc] + ((a0+a1) + (a2+a3));
        dp[(size_t)oc*4096] = fmaxf(v, 0.f);
    }
}

// ---------------- dec2 main mma (unchanged) ----------
__global__ __launch_bounds__(128) void k_dec2_mma(const float* __restrict__ bias)
{
    extern __shared__ __align__(16) float smx[];
    float* sA = smx;
    float* sX = smx + 64*292;
    int*   sK = (int*)(smx + 64*292 + 5760);
    int b = blockIdx.x;
    int mb = b & 3;
    int t = (b >> 2) & 31;
    int img = b >> 7;
    int tx0 = (t & 3) * 16;
    int ty0 = (t >> 2) * 8;
    int tid = threadIdx.x;
    {
        const float4* src = reinterpret_cast<const float4*>(g_weff2 + mb*64*288);
        for (int i = tid; i < 64*72; i += 128) {
            int r = i / 72, kq = (i - r*72)*4;
            float4 v = src[i];
            float* d = sA + r*292 + kq;
            d[0] = v.x; d[1] = v.y; d[2] = v.z; d[3] = v.w;
        }
    }
    for (int k = tid; k < 288; k += 128) {
        int cin = k / 9, rr = k - cin*9;
        sK[k] = cin*180 + (rr/3)*18 + (rr - (rr/3)*3);
    }
    const float* simg = g_d1 + (size_t)img*32*4096;
    for (int i = tid; i < 5760; i += 128) {
        int cin = i / 180;
        int rem = i - cin*180;
        int r = rem / 18, c = rem - r*18;
        int sy = ty0 - 1 + r; sy = max(0, min(63, sy));
        int sx = tx0 - 1 + c; sx = max(0, min(63, sx));
        sX[i] = __uint_as_float(to_tf32(simg[cin*4096 + sy*64 + sx]));
    }
    __syncthreads();
    int wid = tid >> 5, lane = tid & 31;
    int wm = wid & 1, wn = wid >> 1;
    int lg = lane >> 2, lig = lane & 3;
    float acc[2][8][4];
    #pragma unroll
    for (int mt = 0; mt < 2; mt++)
        #pragma unroll
        for (int nt = 0; nt < 8; nt++)
            #pragma unroll
            for (int c = 0; c < 4; c++) acc[mt][nt][c] = 0.f;
    int pb[8];
    #pragma unroll
    for (int nt = 0; nt < 8; nt++) {
        int n = wn*64 + nt*8 + lg;
        pb[nt] = (n >> 4)*18 + (n & 15);
    }
    const float* arow0 = sA + (wm*32 + lg)*292 + lig;
    const float* arow1 = arow0 + 16*292;
    u32 abuf[2][2][4];
    u32 bbuf[2][8][2];
    {
        int ko0 = sK[lig];
        int ko1 = sK[lig + 4];
        abuf[0][0][0] = __float_as_uint(arow0[0]);
        abuf[0][0][1] = __float_as_uint(arow0[8*292]);
        abuf[0][0][2] = __float_as_uint(arow0[4]);
        abuf[0][0][3] = __float_as_uint(arow0[8*292 + 4]);
        abuf[0][1][0] = __float_as_uint(arow1[0]);
        abuf[0][1][1] = __float_as_uint(arow1[8*292]);
        abuf[0][1][2] = __float_as_uint(arow1[4]);
        abuf[0][1][3] = __float_as_uint(arow1[8*292 + 4]);
        #pragma unroll
        for (int nt = 0; nt < 8; nt++) {
            bbuf[0][nt][0] = __float_as_uint(sX[ko0 + pb[nt]]);
            bbuf[0][nt][1] = __float_as_uint(sX[ko1 + pb[nt]]);
        }
    }
    #pragma unroll 2
    for (int ks = 0; ks < 36; ks++) {
        int cur = ks & 1, nxt = cur ^ 1;
        if (ks < 35) {
            int kb = (ks+1)*8;
            int ko0 = sK[kb + lig];
            int ko1 = sK[kb + lig + 4];
            const float* a0p = arow0 + kb;
            const float* a1p = arow1 + kb;
            abuf[nxt][0][0] = __float_as_uint(a0p[0]);
            abuf[nxt][0][1] = __float_as_uint(a0p[8*292]);
            abuf[nxt][0][2] = __float_as_uint(a0p[4]);
            abuf[nxt][0][3] = __float_as_uint(a0p[8*292 + 4]);
            abuf[nxt][1][0] = __float_as_uint(a1p[0]);
            abuf[nxt][1][1] = __float_as_uint(a1p[8*292]);
            abuf[nxt][1][2] = __float_as_uint(a1p[4]);
            abuf[nxt][1][3] = __float_as_uint(a1p[8*292 + 4]);
            #pragma unroll
            for (int nt = 0; nt < 8; nt++) {
                bbuf[nxt][nt][0] = __float_as_uint(sX[ko0 + pb[nt]]);
                bbuf[nxt][nt][1] = __float_as_uint(sX[ko1 + pb[nt]]);
            }
        }
        #pragma unroll
        for (int nt = 0; nt < 8; nt++) {
            mma_tf32(acc[0][nt], abuf[cur][0], bbuf[cur][nt][0], bbuf[cur][nt][1]);
            mma_tf32(acc[1][nt], abuf[cur][1], bbuf[cur][nt][0], bbuf[cur][nt][1]);
        }
    }
    #pragma unroll
    for (int mt = 0; mt < 2; mt++) {
        int mbase = mb*64 + wm*32 + mt*16 + lg;
        float bv0 = bias[mbase >> 2];
        float bv2 = bias[(mbase + 8) >> 2];
        #pragma unroll
        for (int nt = 0; nt < 8; nt++) {
            #pragma unroll
            for (int c = 0; c < 4; c++) {
                int m = mbase + ((c >= 2) ? 8 : 0);
                int n = wn*64 + nt*8 + 2*lig + (c & 1);
                int oc = m >> 2, ap = (m >> 1) & 1, bp2 = m & 1;
                int py = n >> 4, px = n & 15;
                int uy = 2*(ty0 + py) + ap, ux = 2*(tx0 + px) + bp2;
                float v = acc[mt][nt][c] + ((c >= 2) ? bv2 : bv0);
                g_d2[((size_t)(img*64 + oc)*128 + uy)*128 + ux] = fmaxf(v, 0.f);
            }
        }
    }
}

// ---------------- dec2 border fixup: split 2x (grid 256) ----------------
__global__ __launch_bounds__(256) void k_dec2_fix(const float* __restrict__ w,
                                                  const float* __restrict__ bias)
{
    extern __shared__ __align__(16) float sf[];
    float* sW = sf;          // 18432
    float* sT = sf + 18432;  // 32*2*130 layout (partially filled)
    int half = blockIdx.x & 1;
    int side = (blockIdx.x >> 1) & 3;
    int img = blockIdx.x >> 3;
    int tid = threadIdx.x;
    int c0 = half * 64;
    for (int i = tid; i < 18432; i += 256) sW[i] = w[i];
    const float* xi = g_d1 + (size_t)img*32*4096;
    // fill only columns [c0, c0+66] (67 columns) of each (cin, s) row
    for (int i = tid; i < 32*2*67; i += 256) {
        int cin = i / 134;
        int rem = i - cin*134;
        int s = rem / 67, cc = rem - s*67;
        int c = c0 + cc;
        if (c > 129) continue;
        const float* xp = xi + cin*4096;
        float v = 0.f;
        int u = c - 1;
        if (u >= 0 && u < 128) {
            int j = u >> 1;
            int ja, jb; float wa, wb;
            if (u & 1) { ja = j; jb = min(j+1, 63); wa = 0.75f; wb = 0.25f; }
            else       { ja = max(j-1, 0); jb = j;  wa = 0.25f; wb = 0.75f; }
            float xa, xb;
            if (side == 0) {
                if (s == 0) { xa = xp[ja]; xb = xp[jb]; }
                else { xa = 0.75f*xp[ja] + 0.25f*xp[64+ja];
                       xb = 0.75f*xp[jb] + 0.25f*xp[64+jb]; }
            } else if (side == 1) {
                const float* r62 = xp + 62*64; const float* r63 = xp + 63*64;
                if (s == 0) { xa = 0.25f*r62[ja] + 0.75f*r63[ja];
                              xb = 0.25f*r62[jb] + 0.75f*r63[jb]; }
                else { xa = r63[ja]; xb = r63[jb]; }
            } else if (side == 2) {
                if (s == 0) { xa = xp[ja*64]; xb = xp[jb*64]; }
                else { xa = 0.75f*xp[ja*64] + 0.25f*xp[ja*64+1];
                       xb = 0.75f*xp[jb*64] + 0.25f*xp[jb*64+1]; }
            } else {
                if (s == 0) { xa = 0.25f*xp[ja*64+62] + 0.75f*xp[ja*64+63];
                              xb = 0.25f*xp[jb*64+62] + 0.75f*xp[jb*64+63]; }
                else { xa = xp[ja*64+63]; xb = xp[jb*64+63]; }
            }
            v = wa*xa + wb*xb;
        }
        sT[cin*260 + s*130 + c] = v;
    }
    __syncthreads();
    int oc = tid >> 2;
    int q = tid & 3;
    if (side <= 1) {
        int uy = (side == 0) ? 0 : 127;
        int ky0 = (side == 0) ? 1 : 0;
        for (int ux = c0 + q; ux < c0 + 64; ux += 4) {
            float acc = bias[oc];
            for (int cin = 0; cin < 32; cin++) {
                const float* wp = sW + (oc*32 + cin)*9;
                const float* tp = sT + cin*260;
                #pragma unroll
                for (int s = 0; s < 2; s++)
                    #pragma unroll
                    for (int kx = 0; kx < 3; kx++)
                        acc += wp[(ky0+s)*3 + kx] * tp[s*130 + ux + kx];
            }
            g_d2[((size_t)(img*64 + oc)*128 + uy)*128 + ux] = fmaxf(acc, 0.f);
        }
    } else {
        int ux = (side == 2) ? 0 : 127;
        int kx0 = (side == 2) ? 1 : 0;
        int uy_s = (half == 0) ? 1 : 64;
        int uy_e = (half == 0) ? 64 : 127;
        for (int uy = uy_s + q; uy < uy_e; uy += 4) {
            float acc = bias[oc];
            for (int cin = 0; cin < 32; cin++) {
                const float* wp = sW + (oc*32 + cin)*9;
                const float* tp = sT + cin*260;
                #pragma unroll
                for (int s = 0; s < 2; s++)
                    #pragma unroll
                    for (int ky = 0; ky < 3; ky++)
                        acc += wp[ky*3 + kx0 + s] * tp[s*130 + uy + ky];
            }
            g_d2[((size_t)(img*64 + oc)*128 + uy)*128 + ux] = fmaxf(acc, 0.f);
        }
    }
}

// ---------------- dec3 main mma (unchanged) ----------
__global__ __launch_bounds__(128) void k_dec3_mma(const float* __restrict__ bias,
                                                  float* __restrict__ dst)
{
    extern __shared__ __align__(16) float sm3[];
    float* sA = sm3;
    float* sX = sm3 + 16*580;
    int*   sK = (int*)(sm3 + 16*580 + 11520);
    __shared__ float sB3[3];
    int b = blockIdx.x;
    int txt = b & 7;
    int tyt = (b >> 3) & 15;
    int img = b >> 7;
    int tx0 = txt * 16;
    int ty0 = tyt * 8;
    int tid = threadIdx.x;
    {
        const float4* src = reinterpret_cast<const float4*>(g_weff3);
        for (int i = tid; i < 16*144; i += 128) {
            int r = i / 144, kq = (i - r*144)*4;
            float4 v = src[i];
            float* d = sA + r*580 + kq;
            d[0] = v.x; d[1] = v.y; d[2] = v.z; d[3] = v.w;
        }
    }
    for (int k = tid; k < 576; k += 128) {
        int cin = k / 9, rr = k - cin*9;
        sK[k] = cin*180 + (rr/3)*18 + (rr - (rr/3)*3);
    }
    if (tid < 3) sB3[tid] = bias[tid];
    const float* simg = g_d2 + (size_t)img*64*16384;
    for (int i = tid; i < 11520; i += 128) {
        int cin = i / 180;
        int rem = i - cin*180;
        int r = rem / 18, c = rem - r*18;
        int sy = ty0 - 1 + r; sy = max(0, min(127, sy));
        int sx = tx0 - 1 + c; sx = max(0, min(127, sx));
        sX[i] = __uint_as_float(to_tf32(simg[cin*16384 + sy*128 + sx]));
    }
    __syncthreads();
    int wn = tid >> 5, lane = tid & 31;
    int lg = lane >> 2, lig = lane & 3;
    float acc[4][4];
    #pragma unroll
    for (int nt = 0; nt < 4; nt++)
        #pragma unroll
        for (int c = 0; c < 4; c++) acc[nt][c] = 0.f;
    int pb[4];
    #pragma unroll
    for (int nt = 0; nt < 4; nt++) {
        int n = wn*32 + nt*8 + lg;
        pb[nt] = (n >> 4)*18 + (n & 15);
    }
    const float* arow = sA + lg*580 + lig;
    u32 abuf[2][4];
    u32 bbuf[2][4][2];
    {
        int ko0 = sK[lig];
        int ko1 = sK[lig + 4];
        abuf[0][0] = __float_as_uint(arow[0]);
        abuf[0][1] = __float_as_uint(arow[8*580]);
        abuf[0][2] = __float_as_uint(arow[4]);
        abuf[0][3] = __float_as_uint(arow[8*580 + 4]);
        #pragma unroll
        for (int nt = 0; nt < 4; nt++) {
            bbuf[0][nt][0] = __float_as_uint(sX[ko0 + pb[nt]]);
            bbuf[0][nt][1] = __float_as_uint(sX[ko1 + pb[nt]]);
        }
    }
    #pragma unroll 2
    for (int ks = 0; ks < 72; ks++) {
        int cur = ks & 1, nxt = cur ^ 1;
        if (ks < 71) {
            int kb = (ks+1)*8;
            int ko0 = sK[kb + lig];
            int ko1 = sK[kb + lig + 4];
            const float* ap = arow + kb;
            abuf[nxt][0] = __float_as_uint(ap[0]);
            abuf[nxt][1] = __float_as_uint(ap[8*580]);
            abuf[nxt][2] = __float_as_uint(ap[4]);
            abuf[nxt][3] = __float_as_uint(ap[8*580 + 4]);
            #pragma unroll
            for (int nt = 0; nt < 4; nt++) {
                bbuf[nxt][nt][0] = __float_as_uint(sX[ko0 + pb[nt]]);
                bbuf[nxt][nt][1] = __float_as_uint(sX[ko1 + pb[nt]]);
            }
        }
        #pragma unroll
        for (int nt = 0; nt < 4; nt++)
            mma_tf32(acc[nt], abuf[cur], bbuf[cur][nt][0], bbuf[cur][nt][1]);
    }
    #pragma unroll
    for (int nt = 0; nt < 4; nt++) {
        #pragma unroll
        for (int c = 0; c < 4; c++) {
            int m = lg + ((c >= 2) ? 8 : 0);
            if (m < 12) {
                int oc = m >> 2, ap = (m >> 1) & 1, bp = m & 1;
                int n = wn*32 + nt*8 + 2*lig + (c & 1);
                int uy = 2*(ty0 + (n >> 4)) + ap;
                int ux = 2*(tx0 + (n & 15)) + bp;
                dst[(((size_t)(img*3 + oc)) << 16) + uy*256 + ux] = acc[nt][c] + sB3[oc];
            }
        }
    }
}

// ---------------- dec3 border fixup: split 2x (grid 256) ---------
__global__ __launch_bounds__(256) void k_dec3_fix(const float* __restrict__ w,
                                                  const float* __restrict__ bias,
                                                  float* __restrict__ dst)
{
    extern __shared__ __align__(16) float sf3[];
    float* sW = sf3;         // 1728
    float* sT = sf3 + 1728;  // 64*2*258 layout (partially filled)
    int half = blockIdx.x & 1;
    int side = (blockIdx.x >> 1) & 3;
    int img = blockIdx.x >> 3;
    int tid = threadIdx.x;
    int c0 = half * 128;
    for (int i = tid; i < 1728; i += 256) sW[i] = w[i];
    const float* xi = g_d2 + (size_t)img*64*16384;
    // fill only columns [c0, c0+130] (131 columns)
    for (int i = tid; i < 64*2*131; i += 256) {
        int cin = i / 262;
        int rem = i - cin*262;
        int s = rem / 131, cc = rem - s*131;
        int c = c0 + cc;
        if (c > 257) continue;
        const float* xp = xi + cin*16384;
        float v = 0.f;
        int u = c - 1;
        if (u >= 0 && u < 256) {
            int j = u >> 1;
            int ja, jb; float wa, wb;
            if (u & 1) { ja = j; jb = min(j+1, 127); wa = 0.75f; wb = 0.25f; }
            else       { ja = max(j-1, 0); jb = j;   wa = 0.25f; wb = 0.75f; }
            float xa, xb;
            if (side == 0) {
                if (s == 0) { xa = xp[ja]; xb = xp[jb]; }
                else { xa = 0.75f*xp[ja] + 0.25f*xp[128+ja];
                       xb = 0.75f*xp[jb] + 0.25f*xp[128+jb]; }
            } else if (side == 1) {
                const float* rA = xp + 126*128; const float* rB = xp + 127*128;
                if (s == 0) { xa = 0.25f*rA[ja] + 0.75f*rB[ja];
                              xb = 0.25f*rA[jb] + 0.75f*rB[jb]; }
                else { xa = rB[ja]; xb = rB[jb]; }
            } else if (side == 2) {
                if (s == 0) { xa = xp[ja*128]; xb = xp[jb*128]; }
                else { xa = 0.75f*xp[ja*128] + 0.25f*xp[ja*128+1];
                       xb = 0.75f*xp[jb*128] + 0.25f*xp[jb*128+1]; }
            } else {
                if (s == 0) { xa = 0.25f*xp[ja*128+126] + 0.75f*xp[ja*128+127];
                              xb = 0.25f*xp[jb*128+126] + 0.75f*xp[jb*128+127]; }
                else { xa = xp[ja*128+127]; xb = xp[jb*128+127]; }
            }
            v = wa*xa + wb*xb;
        }
        sT[cin*516 + s*258 + c] = v;
    }
    __syncthreads();
    if (side <= 1) {
        int uy = (side == 0) ? 0 : 255;
        int ky0 = (side == 0) ? 1 : 0;
        for (int idx = tid; idx < 3*128; idx += 256) {
            int oc = idx >> 7, ux = c0 + (idx & 127);
            float acc = bias[oc];
            for (int cin = 0; cin < 64; cin++) {
                const float* wp = sW + (oc*64 + cin)*9;
                const float* tp = sT + cin*516;
                #pragma unroll
                for (int s = 0; s < 2; s++)
                    #pragma unroll
                    for (int kx = 0; kx < 3; kx++)
                        acc += wp[(ky0+s)*3 + kx] * tp[s*258 + ux + kx];
            }
            dst[(((size_t)(img*3 + oc)) << 16) + uy*256 + ux] = acc;
        }
    } else {
        int ux = (side == 2) ? 0 : 255;
        int kx0 = (side == 2) ? 1 : 0;
        int uy_s = (half == 0) ? 1 : 128;
        int cnt  = 127;
        for (int idx = tid; idx < 3*cnt; idx += 256) {
            int oc = idx / cnt;
            int uy = uy_s + idx - oc*cnt;
            float acc = bias[oc];
            for (int cin = 0; cin < 64; cin++) {
                const float* wp = sW + (oc*64 + cin)*9;
                const float* tp = sT + cin*516;
                #pragma unroll
                for (int s = 0; s < 2; s++)
                    #pragma unroll
                    for (int ky = 0; ky < 3; ky++)
                        acc += wp[ky*3 + kx0 + s] * tp[s*258 + uy + ky];
            }
            dst[(((size_t)(img*3 + oc)) << 16) + uy*256 + ux] = acc;
        }
    }
}

// ---------------- host launch ----------------
extern "C" void kernel_launch(void* const* d_in, const int* in_sizes, int n_in,
                              void* d_out, int out_size) {
    const float* x   = (const float*)d_in[0];
    const float* cb  = (const float*)d_in[1];
    const float* ew1 = (const float*)d_in[2];
    const float* eb1 = (const float*)d_in[3];
    const float* ew2 = (const float*)d_in[4];
    const float* eb2 = (const float*)d_in[5];
    const float* ew3 = (const float*)d_in[6];
    const float* eb3 = (const float*)d_in[7];
    const float* dw1 = (const float*)d_in[8];
    const float* db1 = (const float*)d_in[9];
    const float* dw2 = (const float*)d_in[10];
    const float* db2 = (const float*)d_in[11];
    const float* dw3 = (const float*)d_in[12];
    const float* db3 = (const float*)d_in[13];
    float* out = (float*)d_out;

    cudaFuncSetAttribute(k_enc2, cudaFuncAttributeMaxDynamicSharedMemorySize, 54088);
    cudaFuncSetAttribute(k_enc3_vq, cudaFuncAttributeMaxDynamicSharedMemorySize, 141568);
    cudaFuncSetAttribute(k_dec2_mma, cudaFuncAttributeMaxDynamicSharedMemorySize, 98944);
    cudaFuncSetAttribute(k_dec2_fix, cudaFuncAttributeMaxDynamicSharedMemorySize, 107008);
    cudaFuncSetAttribute(k_dec3_mma, cudaFuncAttributeMaxDynamicSharedMemorySize, 85504);
    cudaFuncSetAttribute(k_dec3_fix, cudaFuncAttributeMaxDynamicSharedMemorySize, 139008);

    k_prep<<<649, 128>>>(dw2, dw3);
    k_enc1<<<1024, 256>>>(x, ew1, eb1);
    k_enc2<<<512, 128, 54088>>>(ew2, eb2);
    k_enc3_vq<<<256, 256, 141568>>>(ew3, eb3, cb);
    k_loss_out<<<1, 1>>>(out);
    k_dec1<<<512, 256>>>(cb, dw1, db1);
    k_dec2_mma<<<4096, 128, 98944>>>(db2);
    k_dec2_fix<<<256, 256, 107008>>>(dw2, db2);
    k_dec3_mma<<<4096, 128, 85504>>>(db3, out + 2);
    k_dec3_fix<<<256, 256, 139008>>>(dw3, db3, out + 2);
}

// round 16
// speedup vs baseline: 1.0430x; 1.0032x over previous
#include <cuda_runtime.h>

typedef unsigned long long u64;
typedef unsigned int u32;
__device__ __forceinline__ u64 pk2(float lo, float hi) {
    u64 r; asm("mov.b64 %0,{%1,%2};" : "=l"(r) : "f"(lo), "f"(hi)); return r;
}
__device__ __forceinline__ void upk2(u64 v, float& lo, float& hi) {
    asm("mov.b64 {%0,%1},%2;" : "=f"(lo), "=f"(hi) : "l"(v));
}
__device__ __forceinline__ void fma2(u64& d, u64 a, u64 b) {
    asm("fma.rn.f32x2 %0,%1,%2,%0;" : "+l"(d) : "l"(a), "l"(b));
}
__device__ __forceinline__ u64 add2(u64 a, u64 b) {
    u64 r; asm("add.rn.f32x2 %0,%1,%2;" : "=l"(r) : "l"(a), "l"(b)); return r;
}
__device__ __forceinline__ u32 to_tf32(float v) {
    u32 r; asm("cvt.rna.tf32.f32 %0, %1;" : "=r"(r) : "f"(v)); return r;
}
__device__ __forceinline__ void mma_tf32(float* c, const u32* a, u32 b0, u32 b1) {
    asm("mma.sync.aligned.m16n8k8.row.col.f32.tf32.tf32.f32 "
        "{%0,%1,%2,%3}, {%4,%5,%6,%7}, {%8,%9}, {%0,%1,%2,%3};"
        : "+f"(c[0]), "+f"(c[1]), "+f"(c[2]), "+f"(c[3])
        : "r"(a[0]), "r"(a[1]), "r"(a[2]), "r"(a[3]), "r"(b0), "r"(b1));
}
__device__ __forceinline__ void cp4(u32 dst, const float* src, bool pred) {
    asm volatile("cp.async.ca.shared.global [%0], [%1], 4, %2;"
                 :: "r"(dst), "l"(src), "r"(pred ? 4 : 0));
}
#define CP_COMMIT() asm volatile("cp.async.commit_group;")
#define CP_WAIT0()  asm volatile("cp.async.wait_group 0;")

// ---------------- scratch ----------------
__device__ float g_h1[(size_t)32*64*128*128];   // enc1 out, NCHW
__device__ float g_h2[(size_t)32*64*64*32];     // enc2 out, NHWC
__device__ int   g_idx[131072];
__device__ float g_d1[(size_t)32*32*64*64];     // dec1 out, NCHW
__device__ float g_d2[(size_t)32*64*128*128];   // dec2 out, NCHW
__device__ float g_weff2[256*288];              // dec2 effective weights (tf32)
__device__ float g_weff3[16*576];               // dec3 effective weights (tf32)
__device__ float g_loss;

// ---------------- parity matrices ----------------
__device__ __constant__ float c_M[2][3][3] = {
    {{0.75f,0.25f,0.f},{0.25f,0.75f,0.f},{0.f,0.75f,0.25f}},
    {{0.25f,0.75f,0.f},{0.f,0.75f,0.25f},{0.f,0.25f,0.75f}}};

// ---------------- prep: zero loss + weff2 + weff3 ----------------
__global__ void k_prep(const float* __restrict__ w2, const float* __restrict__ w3)
{
    int idx = blockIdx.x*128 + threadIdx.x;
    if (idx < 73728) {
        int m = idx / 288, k = idx - m*288;
        int oc = m >> 2, a = (m >> 1) & 1, bp = m & 1;
        int cin = k / 9, r = k - cin*9, dy = r / 3, dx = r - dy*3;
        float s = 0.f;
        #pragma unroll
        for (int ky = 0; ky < 3; ky++)
            #pragma unroll
            for (int kx = 0; kx < 3; kx++)
                s += w2[((oc*32+cin)*3+ky)*3+kx] * c_M[a][ky][dy] * c_M[bp][kx][dx];
        g_weff2[m*288 + k] = __uint_as_float(to_tf32(s));
    } else if (idx < 82944) {
        int j = idx - 73728;
        int m = j / 576, k = j - m*576;
        float s = 0.f;
        if (m < 12) {
            int oc = m >> 2, a = (m >> 1) & 1, bp = m & 1;
            int cin = k / 9, r = k - cin*9, dy = r / 3, dx = r - dy*3;
            #pragma unroll
            for (int ky = 0; ky < 3; ky++)
                #pragma unroll
                for (int kx = 0; kx < 3; kx++)
                    s += w3[((oc*64+cin)*3+ky)*3+kx] * c_M[a][ky][dy] * c_M[bp][kx][dx];
        }
        g_weff3[m*576 + k] = __uint_as_float(to_tf32(s));
    } else if (idx == 82944) {
        g_loss = 0.f;
    }
}

// ---------------- enc1: 2 CTA/SM via launch bounds ----------------
__global__ __launch_bounds__(256, 2) void k_enc1(const float* __restrict__ x,
                                                 const float* __restrict__ w,
                                                 const float* __restrict__ bias)
{
    __shared__ __align__(16) float sWt[27*64];
    __shared__ __align__(16) float sIn[3*33*65];
    __shared__ __align__(16) float sB[64];
    int blk = blockIdx.x;
    int img = blk >> 5;
    int tile = blk & 31;
    int tx0 = (tile & 3) * 32;
    int ty0 = (tile >> 2) * 16;
    int tid = threadIdx.x;
    for (int i = tid; i < 27*64; i += 256) {
        int t = i >> 6, o = i & 63;
        sWt[i] = w[o*27 + t];
    }
    if (tid < 64) sB[tid] = bias[tid];
    int iy0 = 2*ty0 - 1, ix0 = 2*tx0 - 1;
    const float* xim = x + (size_t)img*3*65536;
    for (int i = tid; i < 3*33*65; i += 256) {
        int c = i / (33*65); int rem = i - c*(33*65);
        int r = rem / 65; int cc = rem - r*65;
        int gy = iy0 + r, gx = ix0 + cc;
        float v = 0.f;
        if (gy >= 0 && gy < 256 && gx >= 0 && gx < 256)
            v = xim[(size_t)c*65536 + gy*256 + gx];
        sIn[i] = v;
    }
    __syncthreads();
    int tx = tid & 31, tyq = tid >> 5;
    float in[3][5][3];
    int lr0 = 4*tyq, lc0 = 2*tx;
    #pragma unroll
    for (int c = 0; c < 3; c++)
        #pragma unroll
        for (int r = 0; r < 5; r++)
            #pragma unroll
            for (int cc = 0; cc < 3; cc++)
                in[c][r][cc] = sIn[c*(33*65) + (lr0+r)*65 + lc0+cc];
    float* h1o = g_h1 + (size_t)img*64*16384;
    int oy = ty0 + 2*tyq, ox = tx0 + tx;
    #pragma unroll 1
    for (int half = 0; half < 2; half++) {
        int ocg = half * 32;
        u64 a0[16], a1[16];
        #pragma unroll
        for (int i = 0; i < 16; i++) {
            a0[i] = pk2(sB[ocg+2*i], sB[ocg+2*i+1]);
            a1[i] = a0[i];
        }
        #pragma unroll
        for (int c = 0; c < 3; c++)
            #pragma unroll
            for (int ky = 0; ky < 3; ky++)
                #pragma unroll
                for (int kx = 0; kx < 3; kx++) {
                    u64 vv0 = pk2(in[c][ky][kx], in[c][ky][kx]);
                    u64 vv1 = pk2(in[c][ky+2][kx], in[c][ky+2][kx]);
                    const ulonglong2* wp = reinterpret_cast<const ulonglong2*>(&sWt[(c*9+ky*3+kx)*64 + ocg]);
                    #pragma unroll
                    for (int q = 0; q < 8; q++) {
                        ulonglong2 wq = wp[q];
                        fma2(a0[2*q],   vv0, wq.x);
                        fma2(a0[2*q+1], vv0, wq.y);
                        fma2(a1[2*q],   vv1, wq.x);
                        fma2(a1[2*q+1], vv1, wq.y);
                    }
                }
        #pragma unroll
        for (int i = 0; i < 16; i++) {
            float l0, h0v, l1, h1v;
            upk2(a0[i], l0, h0v);
            upk2(a1[i], l1, h1v);
            h1o[(size_t)(ocg+2*i)*16384   + (size_t)oy*128 + ox]     = fmaxf(l0, 0.f);
            h1o[(size_t)(ocg+2*i+1)*16384 + (size_t)oy*128 + ox]     = fmaxf(h0v, 0.f);
            h1o[(size_t)(ocg+2*i)*16384   + (size_t)(oy+1)*128 + ox] = fmaxf(l1, 0.f);
            h1o[(size_t)(ocg+2*i+1)*16384 + (size_t)(oy+1)*128 + ox] = fmaxf(h1v, 0.f);
        }
    }
}

// ---------------- enc2: cp.async double-buffered (unchanged) ----------------
__global__ __launch_bounds__(128) void k_enc2(const float* __restrict__ w,
                                              const float* __restrict__ bias)
{
    extern __shared__ __align__(16) float se2[];
    float* sWt = se2;
    float* sInb[2] = { se2 + 9216, se2 + 9216 + 2145 };
    float* sB  = se2 + 9216 + 4290;
    int b = blockIdx.x;
    int og = b & 1;
    int t = (b >> 1) & 7;
    int img = b >> 4;
    int ox0 = (t & 1) * 32;
    int oy0 = (t >> 1) * 16;
    int tid = threadIdx.x;
    for (int i = tid; i < 9216; i += 128) {
        int o = i & 15, rc = i >> 4;
        sWt[i] = w[(og*16 + o)*576 + rc];
    }
    if (tid < 16) sB[tid] = bias[og*16 + tid];
    const float* h1im = g_h1 + (size_t)img*64*16384;
    int iy0 = 2*oy0 - 1, ix0 = 2*ox0 - 1;
    {
        u32 dst0 = (u32)__cvta_generic_to_shared(sInb[0]);
        for (int i = tid; i < 2145; i += 128) {
            int r = i / 65, cc = i - r*65;
            int gy = iy0 + r, gx = ix0 + cc;
            bool ok = (gy >= 0 && gy < 128 && gx >= 0 && gx < 128);
            cp4(dst0 + 4u*i, h1im + ((size_t)gy*128 + gx), ok);
        }
        CP_COMMIT();
    }
    int ttx = tid & 15, tty = tid >> 4;
    u64 acc[2][2][8];
    #pragma unroll 1
    for (int cin = 0; cin < 64; cin++) {
        float* cur = sInb[cin & 1];
        float* nxt = sInb[(cin & 1) ^ 1];
        CP_WAIT0();
        __syncthreads();
        if (cin == 0) {
            #pragma unroll
            for (int r = 0; r < 2; r++)
                #pragma unroll
                for (int cc = 0; cc < 2; cc++)
                    #pragma unroll
                    for (int p = 0; p < 8; p++) acc[r][cc][p] = pk2(sB[2*p], sB[2*p+1]);
        }
        if (cin < 63) {
            const float* hp = h1im + (size_t)(cin+1)*16384;
            u32 dstn = (u32)__cvta_generic_to_shared(nxt);
            for (int i = tid; i < 2145; i += 128) {
                int r = i / 65, cc = i - r*65;
                int gy = iy0 + r, gx = ix0 + cc;
                bool ok = (gy >= 0 && gy < 128 && gx >= 0 && gx < 128);
                cp4(dstn + 4u*i, hp + ((size_t)gy*128 + gx), ok);
            }
        }
        CP_COMMIT();
        float in[5][5];
        #pragma unroll
        for (int r = 0; r < 5; r++)
            #pragma unroll
            for (int c = 0; c < 5; c++)
                in[r][c] = cur[(4*tty + r)*65 + 4*ttx + c];
        #pragma unroll
        for (int ky = 0; ky < 3; ky++)
            #pragma unroll
            for (int kx = 0; kx < 3; kx++) {
                u64 vv[2][2];
                #pragma unroll
                for (int r = 0; r < 2; r++)
                    #pragma unroll
                    for (int cc = 0; cc < 2; cc++) {
                        float v = in[2*r+ky][2*cc+kx];
                        vv[r][cc] = pk2(v, v);
                    }
                const ulonglong2* wp = reinterpret_cast<const ulonglong2*>(&sWt[(cin*9+ky*3+kx)*16]);
                #pragma unroll
                for (int q = 0; q < 4; q++) {
                    ulonglong2 wq = wp[q];
                    #pragma unroll
                    for (int r = 0; r < 2; r++)
                        #pragma unroll
                        for (int cc = 0; cc < 2; cc++) {
                            fma2(acc[r][cc][2*q],   vv[r][cc], wq.x);
                            fma2(acc[r][cc][2*q+1], vv[r][cc], wq.y);
                        }
                }
            }
    }
    #pragma unroll
    for (int r = 0; r < 2; r++)
        #pragma unroll
        for (int cc = 0; cc < 2; cc++) {
            int oy = oy0 + 2*tty + r, ox = ox0 + 2*ttx + cc;
            float* dp = g_h2 + ((size_t)(img*64 + oy)*64 + ox)*32 + og*16;
            #pragma unroll
            for (int p = 0; p < 8; p++) {
                float lo, hi;
                upk2(acc[r][cc][p], lo, hi);
                dp[2*p]   = fmaxf(lo, 0.f);
                dp[2*p+1] = fmaxf(hi, 0.f);
            }
        }
}

// ---------------- enc3 + VQ: 128 thr, 2 px/thr, half-staged codebook --------
// grid 512 x 128 thr; smem = 16384 + 256 + 2048 + 64 floats = 75,008 B
// -> 3 CTA/SM (regs 164*128*3 = 63K < 64K; smem 225 KB < 228 KB)
__global__ __launch_bounds__(128) void k_enc3_vq(const float* __restrict__ w3,
                                                 const float* __restrict__ b3,
                                                 const float* __restrict__ cb)
{
    extern __shared__ __align__(16) float sm[];
    float* sCB = sm;            // 16384 (half codebook: 256 codes x 64)
    float* sCn = sm + 16384;    // 256
    float* sW  = sm + 16640;    // 2048
    float* sB  = sm + 18688;    // 64
    int tid = threadIdx.x;
    for (int i = tid; i < 2048; i += 128) sW[i] = w3[i];
    if (tid < 64) sB[tid] = b3[tid];
    __syncthreads();
    // z for 2 pixels
    int p0 = blockIdx.x*256 + tid;
    int p1 = p0 + 128;
    float h0[32], h1[32];
    {
        const float4* hp0 = reinterpret_cast<const float4*>(g_h2 + (size_t)p0*32);
        const float4* hp1 = reinterpret_cast<const float4*>(g_h2 + (size_t)p1*32);
        #pragma unroll
        for (int q = 0; q < 8; q++) {
            float4 v0 = hp0[q];
            h0[4*q] = v0.x; h0[4*q+1] = v0.y; h0[4*q+2] = v0.z; h0[4*q+3] = v0.w;
            float4 v1 = hp1[q];
            h1[4*q] = v1.x; h1[4*q+1] = v1.y; h1[4*q+2] = v1.z; h1[4*q+3] = v1.w;
        }
    }
    u64 z20[32], z21[32];
    const float4* sW4 = reinterpret_cast<const float4*>(sW);
    #pragma unroll 2
    for (int i = 0; i < 32; i++) {
        float a0 = 0.f, a1 = 0.f, b0 = 0.f, b1 = 0.f;
        #pragma unroll
        for (int q = 0; q < 8; q++) {
            float4 wa = sW4[(2*i)*8 + q];
            float4 wb = sW4[(2*i+1)*8 + q];
            a0 = fmaf(wa.x, h0[4*q],   a0); a0 = fmaf(wa.y, h0[4*q+1], a0);
            a0 = fmaf(wa.z, h0[4*q+2], a0); a0 = fmaf(wa.w, h0[4*q+3], a0);
            a1 = fmaf(wa.x, h1[4*q],   a1); a1 = fmaf(wa.y, h1[4*q+1], a1);
            a1 = fmaf(wa.z, h1[4*q+2], a1); a1 = fmaf(wa.w, h1[4*q+3], a1);
            b0 = fmaf(wb.x, h0[4*q],   b0); b0 = fmaf(wb.y, h0[4*q+1], b0);
            b0 = fmaf(wb.z, h0[4*q+2], b0); b0 = fmaf(wb.w, h0[4*q+3], b0);
            b1 = fmaf(wb.x, h1[4*q],   b1); b1 = fmaf(wb.y, h1[4*q+1], b1);
            b1 = fmaf(wb.z, h1[4*q+2], b1); b1 = fmaf(wb.w, h1[4*q+3], b1);
        }
        z20[i] = pk2(sB[2*i] + a0, sB[2*i+1] + b0);
        z21[i] = pk2(sB[2*i] + a1, sB[2*i+1] + b1);
    }
    float best0 = 3.4e38f, best1 = 3.4e38f;
    int bi0 = 0, bi1 = 0;
    #pragma unroll 1
    for (int stage = 0; stage < 2; stage++) {
        __syncthreads();   // prior stage's reads complete before overwrite
        {
            const float4* s4 = reinterpret_cast<const float4*>(cb + (size_t)stage*16384);
            float4* d4 = reinterpret_cast<float4*>(sCB);
            for (int i = tid; i < 4096; i += 128) d4[i] = s4[i];
        }
        __syncthreads();
        for (int k = tid; k < 256; k += 128) {
            float s = 0.f;
            #pragma unroll 8
            for (int d = 0; d < 64; d++) { float v = sCB[k*64+d]; s = fmaf(v, v, s); }
            sCn[k] = s;
        }
        __syncthreads();
        const ulonglong2* sCB2 = reinterpret_cast<const ulonglong2*>(sCB);
        int kbase = stage*256;
        #pragma unroll 1
        for (int k = 0; k < 256; k++) {
            const ulonglong2* ck = sCB2 + k*16;
            u64 a0 = 0, a1 = 0, b0 = 0, b1 = 0;
            #pragma unroll
            for (int q = 0; q < 16; q++) {
                ulonglong2 cq = ck[q];
                fma2(a0, z20[2*q],   cq.x);
                fma2(a1, z20[2*q+1], cq.y);
                fma2(b0, z21[2*q],   cq.x);
                fma2(b1, z21[2*q+1], cq.y);
            }
            float cn = sCn[k];
            u64 sa = add2(a0, a1);
            u64 sb = add2(b0, b1);
            float la, ha, lb, hb;
            upk2(sa, la, ha);
            upk2(sb, lb, hb);
            float s0 = cn - 2.f*(la + ha);
            float s1 = cn - 2.f*(lb + hb);
            if (s0 < best0) { best0 = s0; bi0 = kbase + k; }
            if (s1 < best1) { best1 = s1; bi1 = kbase + k; }
        }
    }
    g_idx[p0] = bi0;
    g_idx[p1] = bi1;
    u64 n0 = 0, n1 = 0;
    #pragma unroll
    for (int i = 0; i < 32; i++) {
        fma2(n0, z20[i], z20[i]);
        fma2(n1, z21[i], z21[i]);
    }
    float l0, h0v, l1, h1v;
    upk2(n0, l0, h0v);
    upk2(n1, l1, h1v);
    float s = (best0 + (l0 + h0v)) + (best1 + (l1 + h1v));
    #pragma unroll
    for (int off = 16; off > 0; off >>= 1)
        s += __shfl_down_sync(0xffffffffu, s, off);
    if ((tid & 31) == 0) atomicAdd(&g_loss, s);
}

__global__ void k_loss_out(float* __restrict__ out)
{
    float v = g_loss * (1.f/8388608.f);
    out[0] = v;
    out[1] = v;
}

// ---------------- dec1 (unchanged) ----------------
__global__ __launch_bounds__(256) void k_dec1(const float* __restrict__ cb,
                                              const float* __restrict__ w,
                                              const float* __restrict__ bias)
{
    __shared__ __align__(16) float sW[32*64];
    __shared__ __align__(16) float sB[32];
    int tid = threadIdx.x;
    for (int i = tid; i < 2048; i += 256) sW[i] = w[i];
    if (tid < 32) sB[tid] = bias[tid];
    __syncthreads();
    int p = blockIdx.x*256 + tid;
    int ki = g_idx[p];
    float c[64];
    const float4* cp = reinterpret_cast<const float4*>(cb + (size_t)ki*64);
    #pragma unroll
    for (int q = 0; q < 16; q++) {
        float4 v = cp[q];
        c[4*q] = v.x; c[4*q+1] = v.y; c[4*q+2] = v.z; c[4*q+3] = v.w;
    }
    int img = p >> 12;
    int rem = p & 4095;
    float* dp = g_d1 + (size_t)img*32*4096 + rem;
    const float4* sW4 = reinterpret_cast<const float4*>(sW);
    #pragma unroll 1
    for (int oc = 0; oc < 32; oc++) {
        float a0 = 0.f, a1 = 0.f, a2 = 0.f, a3 = 0.f;
        #pragma unroll
        for (int q = 0; q < 16; q++) {
            float4 wv = sW4[oc*16 + q];
            a0 = fmaf(wv.x, c[4*q],   a0);
            a1 = fmaf(wv.y, c[4*q+1], a1);
            a2 = fmaf(wv.z, c[4*q+2], a2);
            a3 = fmaf(wv.w, c[4*q+3], a3);
        }
        float v = sB[oc] + ((a0+a1) + (a2+a3));
        dp[(size_t)oc*4096] = fmaxf(v, 0.f);
    }
}

// ---------------- dec2 main mma (unchanged) ----------
__global__ __launch_bounds__(128) void k_dec2_mma(const float* __restrict__ bias)
{
    extern __shared__ __align__(16) float smx[];
    float* sA = smx;
    float* sX = smx + 64*292;
    int*   sK = (int*)(smx + 64*292 + 5760);
    int b = blockIdx.x;
    int mb = b & 3;
    int t = (b >> 2) & 31;
    int img = b >> 7;
    int tx0 = (t & 3) * 16;
    int ty0 = (t >> 2) * 8;
    int tid = threadIdx.x;
    {
        const float4* src = reinterpret_cast<const float4*>(g_weff2 + mb*64*288);
        for (int i = tid; i < 64*72; i += 128) {
            int r = i / 72, kq = (i - r*72)*4;
            float4 v = src[i];
            float* d = sA + r*292 + kq;
            d[0] = v.x; d[1] = v.y; d[2] = v.z; d[3] = v.w;
        }
    }
    for (int k = tid; k < 288; k += 128) {
        int cin = k / 9, rr = k - cin*9;
        sK[k] = cin*180 + (rr/3)*18 + (rr - (rr/3)*3);
    }
    const float* simg = g_d1 + (size_t)img*32*4096;
    for (int i = tid; i < 5760; i += 128) {
        int cin = i / 180;
        int rem = i - cin*180;
        int r = rem / 18, c = rem - r*18;
        int sy = ty0 - 1 + r; sy = max(0, min(63, sy));
        int sx = tx0 - 1 + c; sx = max(0, min(63, sx));
        sX[i] = __uint_as_float(to_tf32(simg[cin*4096 + sy*64 + sx]));
    }
    __syncthreads();
    int wid = tid >> 5, lane = tid & 31;
    int wm = wid & 1, wn = wid >> 1;
    int lg = lane >> 2, lig = lane & 3;
    float acc[2][8][4];
    #pragma unroll
    for (int mt = 0; mt < 2; mt++)
        #pragma unroll
        for (int nt = 0; nt < 8; nt++)
            #pragma unroll
            for (int c = 0; c < 4; c++) acc[mt][nt][c] = 0.f;
    int pb[8];
    #pragma unroll
    for (int nt = 0; nt < 8; nt++) {
        int n = wn*64 + nt*8 + lg;
        pb[nt] = (n >> 4)*18 + (n & 15);
    }
    const float* arow0 = sA + (wm*32 + lg)*292 + lig;
    const float* arow1 = arow0 + 16*292;
    u32 abuf[2][2][4];
    u32 bbuf[2][8][2];
    {
        int ko0 = sK[lig];
        int ko1 = sK[lig + 4];
        abuf[0][0][0] = __float_as_uint(arow0[0]);
        abuf[0][0][1] = __float_as_uint(arow0[8*292]);
        abuf[0][0][2] = __float_as_uint(arow0[4]);
        abuf[0][0][3] = __float_as_uint(arow0[8*292 + 4]);
        abuf[0][1][0] = __float_as_uint(arow1[0]);
        abuf[0][1][1] = __float_as_uint(arow1[8*292]);
        abuf[0][1][2] = __float_as_uint(arow1[4]);
        abuf[0][1][3] = __float_as_uint(arow1[8*292 + 4]);
        #pragma unroll
        for (int nt = 0; nt < 8; nt++) {
            bbuf[0][nt][0] = __float_as_uint(sX[ko0 + pb[nt]]);
            bbuf[0][nt][1] = __float_as_uint(sX[ko1 + pb[nt]]);
        }
    }
    #pragma unroll 2
    for (int ks = 0; ks < 36; ks++) {
        int cur = ks & 1, nxt = cur ^ 1;
        if (ks < 35) {
            int kb = (ks+1)*8;
            int ko0 = sK[kb + lig];
            int ko1 = sK[kb + lig + 4];
            const float* a0p = arow0 + kb;
            const float* a1p = arow1 + kb;
            abuf[nxt][0][0] = __float_as_uint(a0p[0]);
            abuf[nxt][0][1] = __float_as_uint(a0p[8*292]);
            abuf[nxt][0][2] = __float_as_uint(a0p[4]);
            abuf[nxt][0][3] = __float_as_uint(a0p[8*292 + 4]);
            abuf[nxt][1][0] = __float_as_uint(a1p[0]);
            abuf[nxt][1][1] = __float_as_uint(a1p[8*292]);
            abuf[nxt][1][2] = __float_as_uint(a1p[4]);
            abuf[nxt][1][3] = __float_as_uint(a1p[8*292 + 4]);
            #pragma unroll
            for (int nt = 0; nt < 8; nt++) {
                bbuf[nxt][nt][0] = __float_as_uint(sX[ko0 + pb[nt]]);
                bbuf[nxt][nt][1] = __float_as_uint(sX[ko1 + pb[nt]]);
            }
        }
        #pragma unroll
        for (int nt = 0; nt < 8; nt++) {
            mma_tf32(acc[0][nt], abuf[cur][0], bbuf[cur][nt][0], bbuf[cur][nt][1]);
            mma_tf32(acc[1][nt], abuf[cur][1], bbuf[cur][nt][0], bbuf[cur][nt][1]);
        }
    }
    #pragma unroll
    for (int mt = 0; mt < 2; mt++) {
        int mbase = mb*64 + wm*32 + mt*16 + lg;
        float bv0 = bias[mbase >> 2];
        float bv2 = bias[(mbase + 8) >> 2];
        #pragma unroll
        for (int nt = 0; nt < 8; nt++) {
            #pragma unroll
            for (int c = 0; c < 4; c++) {
                int m = mbase + ((c >= 2) ? 8 : 0);
                int n = wn*64 + nt*8 + 2*lig + (c & 1);
                int oc = m >> 2, ap = (m >> 1) & 1, bp2 = m & 1;
                int py = n >> 4, px = n & 15;
                int uy = 2*(ty0 + py) + ap, ux = 2*(tx0 + px) + bp2;
                float v = acc[mt][nt][c] + ((c >= 2) ? bv2 : bv0);
                g_d2[((size_t)(img*64 + oc)*128 + uy)*128 + ux] = fmaxf(v, 0.f);
            }
        }
    }
}

// ---------------- dec2 border fixup: split 2x (unchanged from R15) ----------
__global__ __launch_bounds__(256) void k_dec2_fix(const float* __restrict__ w,
                                                  const float* __restrict__ bias)
{
    extern __shared__ __align__(16) float sf[];
    float* sW = sf;
    float* sT = sf + 18432;
    int half = blockIdx.x & 1;
    int side = (blockIdx.x >> 1) & 3;
    int img = blockIdx.x >> 3;
    int tid = threadIdx.x;
    int c0 = half * 64;
    for (int i = tid; i < 18432; i += 256) sW[i] = w[i];
    const float* xi = g_d1 + (size_t)img*32*4096;
    for (int i = tid; i < 32*2*67; i += 256) {
        int cin = i / 134;
        int rem = i - cin*134;
        int s = rem / 67, cc = rem - s*67;
        int c = c0 + cc;
        if (c > 129) continue;
        const float* xp = xi + cin*4096;
        float v = 0.f;
        int u = c - 1;
        if (u >= 0 && u < 128) {
            int j = u >> 1;
            int ja, jb; float wa, wb;
            if (u & 1) { ja = j; jb = min(j+1, 63); wa = 0.75f; wb = 0.25f; }
            else       { ja = max(j-1, 0); jb = j;  wa = 0.25f; wb = 0.75f; }
            float xa, xb;
            if (side == 0) {
                if (s == 0) { xa = xp[ja]; xb = xp[jb]; }
                else { xa = 0.75f*xp[ja] + 0.25f*xp[64+ja];
                       xb = 0.75f*xp[jb] + 0.25f*xp[64+jb]; }
            } else if (side == 1) {
                const float* r62 = xp + 62*64; const float* r63 = xp + 63*64;
                if (s == 0) { xa = 0.25f*r62[ja] + 0.75f*r63[ja];
                              xb = 0.25f*r62[jb] + 0.75f*r63[jb]; }
                else { xa = r63[ja]; xb = r63[jb]; }
            } else if (side == 2) {
                if (s == 0) { xa = xp[ja*64]; xb = xp[jb*64]; }
                else { xa = 0.75f*xp[ja*64] + 0.25f*xp[ja*64+1];
                       xb = 0.75f*xp[jb*64] + 0.25f*xp[jb*64+1]; }
            } else {
                if (s == 0) { xa = 0.25f*xp[ja*64+62] + 0.75f*xp[ja*64+63];
                              xb = 0.25f*xp[jb*64+62] + 0.75f*xp[jb*64+63]; }
                else { xa = xp[ja*64+63]; xb = xp[jb*64+63]; }
            }
            v = wa*xa + wb*xb;
        }
        sT[cin*260 + s*130 + c] = v;
    }
    __syncthreads();
    int oc = tid >> 2;
    int q = tid & 3;
    if (side <= 1) {
        int uy = (side == 0) ? 0 : 127;
        int ky0 = (side == 0) ? 1 : 0;
        for (int ux = c0 + q; ux < c0 + 64; ux += 4) {
            float acc = bias[oc];
            for (int cin = 0; cin < 32; cin++) {
                const float* wp = sW + (oc*32 + cin)*9;
                const float* tp = sT + cin*260;
                #pragma unroll
                for (int s = 0; s < 2; s++)
                    #pragma unroll
                    for (int kx = 0; kx < 3; kx++)
                        acc += wp[(ky0+s)*3 + kx] * tp[s*130 + ux + kx];
            }
            g_d2[((size_t)(img*64 + oc)*128 + uy)*128 + ux] = fmaxf(acc, 0.f);
        }
    } else {
        int ux = (side == 2) ? 0 : 127;
        int kx0 = (side == 2) ? 1 : 0;
        int uy_s = (half == 0) ? 1 : 64;
        int uy_e = (half == 0) ? 64 : 127;
        for (int uy = uy_s + q; uy < uy_e; uy += 4) {
            float acc = bias[oc];
            for (int cin = 0; cin < 32; cin++) {
                const float* wp = sW + (oc*32 + cin)*9;
                const float* tp = sT + cin*260;
                #pragma unroll
                for (int s = 0; s < 2; s++)
                    #pragma unroll
                    for (int ky = 0; ky < 3; ky++)
                        acc += wp[ky*3 + kx0 + s] * tp[s*130 + uy + ky];
            }
            g_d2[((size_t)(img*64 + oc)*128 + uy)*128 + ux] = fmaxf(acc, 0.f);
        }
    }
}

// ---------------- dec3 main mma (unchanged) ----------
__global__ __launch_bounds__(128) void k_dec3_mma(const float* __restrict__ bias,
                                                  float* __restrict__ dst)
{
    extern __shared__ __align__(16) float sm3[];
    float* sA = sm3;
    float* sX = sm3 + 16*580;
    int*   sK = (int*)(sm3 + 16*580 + 11520);
    __shared__ float sB3[3];
    int b = blockIdx.x;
    int txt = b & 7;
    int tyt = (b >> 3) & 15;
    int img = b >> 7;
    int tx0 = txt * 16;
    int ty0 = tyt * 8;
    int tid = threadIdx.x;
    {
        const float4* src = reinterpret_cast<const float4*>(g_weff3);
        for (int i = tid; i < 16*144; i += 128) {
            int r = i / 144, kq = (i - r*144)*4;
            float4 v = src[i];
            float* d = sA + r*580 + kq;
            d[0] = v.x; d[1] = v.y; d[2] = v.z; d[3] = v.w;
        }
    }
    for (int k = tid; k < 576; k += 128) {
        int cin = k / 9, rr = k - cin*9;
        sK[k] = cin*180 + (rr/3)*18 + (rr - (rr/3)*3);
    }
    if (tid < 3) sB3[tid] = bias[tid];
    const float* simg = g_d2 + (size_t)img*64*16384;
    for (int i = tid; i < 11520; i += 128) {
        int cin = i / 180;
        int rem = i - cin*180;
        int r = rem / 18, c = rem - r*18;
        int sy = ty0 - 1 + r; sy = max(0, min(127, sy));
        int sx = tx0 - 1 + c; sx = max(0, min(127, sx));
        sX[i] = __uint_as_float(to_tf32(simg[cin*16384 + sy*128 + sx]));
    }
    __syncthreads();
    int wn = tid >> 5, lane = tid & 31;
    int lg = lane >> 2, lig = lane & 3;
    float acc[4][4];
    #pragma unroll
    for (int nt = 0; nt < 4; nt++)
        #pragma unroll
        for (int c = 0; c < 4; c++) acc[nt][c] = 0.f;
    int pb[4];
    #pragma unroll
    for (int nt = 0; nt < 4; nt++) {
        int n = wn*32 + nt*8 + lg;
        pb[nt] = (n >> 4)*18 + (n & 15);
    }
    const float* arow = sA + lg*580 + lig;
    u32 abuf[2][4];
    u32 bbuf[2][4][2];
    {
        int ko0 = sK[lig];
        int ko1 = sK[lig + 4];
        abuf[0][0] = __float_as_uint(arow[0]);
        abuf[0][1] = __float_as_uint(arow[8*580]);
        abuf[0][2] = __float_as_uint(arow[4]);
        abuf[0][3] = __float_as_uint(arow[8*580 + 4]);
        #pragma unroll
        for (int nt = 0; nt < 4; nt++) {
            bbuf[0][nt][0] = __float_as_uint(sX[ko0 + pb[nt]]);
            bbuf[0][nt][1] = __float_as_uint(sX[ko1 + pb[nt]]);
        }
    }
    #pragma unroll 2
    for (int ks = 0; ks < 72; ks++) {
        int cur = ks & 1, nxt = cur ^ 1;
        if (ks < 71) {
            int kb = (ks+1)*8;
            int ko0 = sK[kb + lig];
            int ko1 = sK[kb + lig + 4];
            const float* ap = arow + kb;
            abuf[nxt][0] = __float_as_uint(ap[0]);
            abuf[nxt][1] = __float_as_uint(ap[8*580]);
            abuf[nxt][2] = __float_as_uint(ap[4]);
            abuf[nxt][3] = __float_as_uint(ap[8*580 + 4]);
            #pragma unroll
            for (int nt = 0; nt < 4; nt++) {
                bbuf[nxt][nt][0] = __float_as_uint(sX[ko0 + pb[nt]]);
                bbuf[nxt][nt][1] = __float_as_uint(sX[ko1 + pb[nt]]);
            }
        }
        #pragma unroll
        for (int nt = 0; nt < 4; nt++)
            mma_tf32(acc[nt], abuf[cur], bbuf[cur][nt][0], bbuf[cur][nt][1]);
    }
    #pragma unroll
    for (int nt = 0; nt < 4; nt++) {
        #pragma unroll
        for (int c = 0; c < 4; c++) {
            int m = lg + ((c >= 2) ? 8 : 0);
            if (m < 12) {
                int oc = m >> 2, ap = (m >> 1) & 1, bp = m & 1;
                int n = wn*32 + nt*8 + 2*lig + (c & 1);
                int uy = 2*(ty0 + (n >> 4)) + ap;
                int ux = 2*(tx0 + (n & 15)) + bp;
                dst[(((size_t)(img*3 + oc)) << 16) + uy*256 + ux] = acc[nt][c] + sB3[oc];
            }
        }
    }
}

// ---------------- dec3 border fixup: split 2x (unchanged from R15) ---------
__global__ __launch_bounds__(256) void k_dec3_fix(const float* __restrict__ w,
                                                  const float* __restrict__ bias,
                                                  float* __restrict__ dst)
{
    extern __shared__ __align__(16) float sf3[];
    float* sW = sf3;
    float* sT = sf3 + 1728;
    int half = blockIdx.x & 1;
    int side = (blockIdx.x >> 1) & 3;
    int img = blockIdx.x >> 3;
    int tid = threadIdx.x;
    int c0 = half * 128;
    for (int i = tid; i < 1728; i += 256) sW[i] = w[i];
    const float* xi = g_d2 + (size_t)img*64*16384;
    for (int i = tid; i < 64*2*131; i += 256) {
        int cin = i / 262;
        int rem = i - cin*262;
        int s = rem / 131, cc = rem - s*131;
        int c = c0 + cc;
        if (c > 257) continue;
        const float* xp = xi + cin*16384;
        float v = 0.f;
        int u = c - 1;
        if (u >= 0 && u < 256) {
            int j = u >> 1;
            int ja, jb; float wa, wb;
            if (u & 1) { ja = j; jb = min(j+1, 127); wa = 0.75f; wb = 0.25f; }
            else       { ja = max(j-1, 0); jb = j;   wa = 0.25f; wb = 0.75f; }
            float xa, xb;
            if (side == 0) {
                if (s == 0) { xa = xp[ja]; xb = xp[jb]; }
                else { xa = 0.75f*xp[ja] + 0.25f*xp[128+ja];
                       xb = 0.75f*xp[jb] + 0.25f*xp[128+jb]; }
            } else if (side == 1) {
                const float* rA = xp + 126*128; const float* rB = xp + 127*128;
                if (s == 0) { xa = 0.25f*rA[ja] + 0.75f*rB[ja];
                              xb = 0.25f*rA[jb] + 0.75f*rB[jb]; }
                else { xa = rB[ja]; xb = rB[jb]; }
            } else if (side == 2) {
                if (s == 0) { xa = xp[ja*128]; xb = xp[jb*128]; }
                else { xa = 0.75f*xp[ja*128] + 0.25f*xp[ja*128+1];
                       xb = 0.75f*xp[jb*128] + 0.25f*xp[jb*128+1]; }
            } else {
                if (s == 0) { xa = 0.25f*xp[ja*128+126] + 0.75f*xp[ja*128+127];
                              xb = 0.25f*xp[jb*128+126] + 0.75f*xp[jb*128+127]; }
                else { xa = xp[ja*128+127]; xb = xp[jb*128+127]; }
            }
            v = wa*xa + wb*xb;
        }
        sT[cin*516 + s*258 + c] = v;
    }
    __syncthreads();
    if (side <= 1) {
        int uy = (side == 0) ? 0 : 255;
        int ky0 = (side == 0) ? 1 : 0;
        for (int idx = tid; idx < 3*128; idx += 256) {
            int oc = idx >> 7, ux = c0 + (idx & 127);
            float acc = bias[oc];
            for (int cin = 0; cin < 64; cin++) {
                const float* wp = sW + (oc*64 + cin)*9;
                const float* tp = sT + cin*516;
                #pragma unroll
                for (int s = 0; s < 2; s++)
                    #pragma unroll
                    for (int kx = 0; kx < 3; kx++)
                        acc += wp[(ky0+s)*3 + kx] * tp[s*258 + ux + kx];
            }
            dst[(((size_t)(img*3 + oc)) << 16) + uy*256 + ux] = acc;
        }
    } else {
        int ux = (side == 2) ? 0 : 255;
        int kx0 = (side == 2) ? 1 : 0;
        int uy_s = (half == 0) ? 1 : 128;
        int cnt  = 127;
        for (int idx = tid; idx < 3*cnt; idx += 256) {
            int oc = idx / cnt;
            int uy = uy_s + idx - oc*cnt;
            float acc = bias[oc];
            for (int cin = 0; cin < 64; cin++) {
                const float* wp = sW + (oc*64 + cin)*9;
                const float* tp = sT + cin*516;
                #pragma unroll
                for (int s = 0; s < 2; s++)
                    #pragma unroll
                    for (int ky = 0; ky < 3; ky++)
                        acc += wp[ky*3 + kx0 + s] * tp[s*258 + uy + ky];
            }
            dst[(((size_t)(img*3 + oc)) << 16) + uy*256 + ux] = acc;
        }
    }
}

// ---------------- host launch ----------------
extern "C" void kernel_launch(void* const* d_in, const int* in_sizes, int n_in,
                              void* d_out, int out_size) {
    const float* x   = (const float*)d_in[0];
    const float* cb  = (const float*)d_in[1];
    const float* ew1 = (const float*)d_in[2];
    const float* eb1 = (const float*)d_in[3];
    const float* ew2 = (const float*)d_in[4];
    const float* eb2 = (const float*)d_in[5];
    const float* ew3 = (const float*)d_in[6];
    const float* eb3 = (const float*)d_in[7];
    const float* dw1 = (const float*)d_in[8];
    const float* db1 = (const float*)d_in[9];
    const float* dw2 = (const float*)d_in[10];
    const float* db2 = (const float*)d_in[11];
    const float* dw3 = (const float*)d_in[12];
    const float* db3 = (const float*)d_in[13];
    float* out = (float*)d_out;

    cudaFuncSetAttribute(k_enc2, cudaFuncAttributeMaxDynamicSharedMemorySize, 54088);
    cudaFuncSetAttribute(k_enc3_vq, cudaFuncAttributeMaxDynamicSharedMemorySize, 75008);
    cudaFuncSetAttribute(k_dec2_mma, cudaFuncAttributeMaxDynamicSharedMemorySize, 98944);
    cudaFuncSetAttribute(k_dec2_fix, cudaFuncAttributeMaxDynamicSharedMemorySize, 107008);
    cudaFuncSetAttribute(k_dec3_mma, cudaFuncAttributeMaxDynamicSharedMemorySize, 85504);
    cudaFuncSetAttribute(k_dec3_fix, cudaFuncAttributeMaxDynamicSharedMemorySize, 139008);

    k_prep<<<649, 128>>>(dw2, dw3);
    k_enc1<<<1024, 256>>>(x, ew1, eb1);
    k_enc2<<<512, 128, 54088>>>(ew2, eb2);
    k_enc3_vq<<<512, 128, 75008>>>(ew3, eb3, cb);
    k_loss_out<<<1, 1>>>(out);
    k_dec1<<<512, 256>>>(cb, dw1, db1);
    k_dec2_mma<<<4096, 128, 98944>>>(db2);
    k_dec2_fix<<<256, 256, 107008>>>(dw2, db2);
    k_dec3_mma<<<4096, 128, 85504>>>(db3, out + 2);
    k_dec3_fix<<<256, 256, 139008>>>(dw3, db3, out + 2);
}

// round 17
// speedup vs baseline: 1.0539x; 1.0105x over previous
#include <cuda_runtime.h>

typedef unsigned long long u64;
typedef unsigned int u32;
__device__ __forceinline__ u64 pk2(float lo, float hi) {
    u64 r; asm("mov.b64 %0,{%1,%2};" : "=l"(r) : "f"(lo), "f"(hi)); return r;
}
__device__ __forceinline__ void upk2(u64 v, float& lo, float& hi) {
    asm("mov.b64 {%0,%1},%2;" : "=f"(lo), "=f"(hi) : "l"(v));
}
__device__ __forceinline__ void fma2(u64& d, u64 a, u64 b) {
    asm("fma.rn.f32x2 %0,%1,%2,%0;" : "+l"(d) : "l"(a), "l"(b));
}
__device__ __forceinline__ u64 add2(u64 a, u64 b) {
    u64 r; asm("add.rn.f32x2 %0,%1,%2;" : "=l"(r) : "l"(a), "l"(b)); return r;
}
__device__ __forceinline__ u32 to_tf32(float v) {
    u32 r; asm("cvt.rna.tf32.f32 %0, %1;" : "=r"(r) : "f"(v)); return r;
}
__device__ __forceinline__ void mma_tf32(float* c, const u32* a, u32 b0, u32 b1) {
    asm("mma.sync.aligned.m16n8k8.row.col.f32.tf32.tf32.f32 "
        "{%0,%1,%2,%3}, {%4,%5,%6,%7}, {%8,%9}, {%0,%1,%2,%3};"
        : "+f"(c[0]), "+f"(c[1]), "+f"(c[2]), "+f"(c[3])
        : "r"(a[0]), "r"(a[1]), "r"(a[2]), "r"(a[3]), "r"(b0), "r"(b1));
}
__device__ __forceinline__ void cp4(u32 dst, const float* src, bool pred) {
    asm volatile("cp.async.ca.shared.global [%0], [%1], 4, %2;"
                 :: "r"(dst), "l"(src), "r"(pred ? 4 : 0));
}
#define CP_COMMIT() asm volatile("cp.async.commit_group;")
#define CP_WAIT0()  asm volatile("cp.async.wait_group 0;")

// ---------------- scratch ----------------
__device__ float g_h1[(size_t)32*64*128*128];   // enc1 out, NCHW
__device__ float g_h2[(size_t)32*64*64*32];     // enc2 out, NHWC
__device__ int   g_idx[131072];
__device__ float g_d1[(size_t)32*32*64*64];     // dec1 out, NCHW
__device__ float g_d2[(size_t)32*64*128*128];   // dec2 out, NCHW
__device__ float g_weff2[256*288];              // dec2 effective weights (tf32)
__device__ float g_weff3[16*576];               // dec3 effective weights (tf32)
__device__ float g_loss;

// ---------------- parity matrices ----------------
__device__ __constant__ float c_M[2][3][3] = {
    {{0.75f,0.25f,0.f},{0.25f,0.75f,0.f},{0.f,0.75f,0.25f}},
    {{0.25f,0.75f,0.f},{0.f,0.75f,0.25f},{0.f,0.25f,0.75f}}};

// ---------------- prep: zero loss + weff2 + weff3 ----------------
__global__ void k_prep(const float* __restrict__ w2, const float* __restrict__ w3)
{
    int idx = blockIdx.x*128 + threadIdx.x;
    if (idx < 73728) {
        int m = idx / 288, k = idx - m*288;
        int oc = m >> 2, a = (m >> 1) & 1, bp = m & 1;
        int cin = k / 9, r = k - cin*9, dy = r / 3, dx = r - dy*3;
        float s = 0.f;
        #pragma unroll
        for (int ky = 0; ky < 3; ky++)
            #pragma unroll
            for (int kx = 0; kx < 3; kx++)
                s += w2[((oc*32+cin)*3+ky)*3+kx] * c_M[a][ky][dy] * c_M[bp][kx][dx];
        g_weff2[m*288 + k] = __uint_as_float(to_tf32(s));
    } else if (idx < 82944) {
        int j = idx - 73728;
        int m = j / 576, k = j - m*576;
        float s = 0.f;
        if (m < 12) {
            int oc = m >> 2, a = (m >> 1) & 1, bp = m & 1;
            int cin = k / 9, r = k - cin*9, dy = r / 3, dx = r - dy*3;
            #pragma unroll
            for (int ky = 0; ky < 3; ky++)
                #pragma unroll
                for (int kx = 0; kx < 3; kx++)
                    s += w3[((oc*64+cin)*3+ky)*3+kx] * c_M[a][ky][dy] * c_M[bp][kx][dx];
        }
        g_weff3[m*576 + k] = __uint_as_float(to_tf32(s));
    } else if (idx == 82944) {
        g_loss = 0.f;
    }
}

// ---------------- enc1: 2 CTA/SM via launch bounds ----------------
__global__ __launch_bounds__(256, 2) void k_enc1(const float* __restrict__ x,
                                                 const float* __restrict__ w,
                                                 const float* __restrict__ bias)
{
    __shared__ __align__(16) float sWt[27*64];
    __shared__ __align__(16) float sIn[3*33*65];
    __shared__ __align__(16) float sB[64];
    int blk = blockIdx.x;
    int img = blk >> 5;
    int tile = blk & 31;
    int tx0 = (tile & 3) * 32;
    int ty0 = (tile >> 2) * 16;
    int tid = threadIdx.x;
    for (int i = tid; i < 27*64; i += 256) {
        int t = i >> 6, o = i & 63;
        sWt[i] = w[o*27 + t];
    }
    if (tid < 64) sB[tid] = bias[tid];
    int iy0 = 2*ty0 - 1, ix0 = 2*tx0 - 1;
    const float* xim = x + (size_t)img*3*65536;
    for (int i = tid; i < 3*33*65; i += 256) {
        int c = i / (33*65); int rem = i - c*(33*65);
        int r = rem / 65; int cc = rem - r*65;
        int gy = iy0 + r, gx = ix0 + cc;
        float v = 0.f;
        if (gy >= 0 && gy < 256 && gx >= 0 && gx < 256)
            v = xim[(size_t)c*65536 + gy*256 + gx];
        sIn[i] = v;
    }
    __syncthreads();
    int tx = tid & 31, tyq = tid >> 5;
    float in[3][5][3];
    int lr0 = 4*tyq, lc0 = 2*tx;
    #pragma unroll
    for (int c = 0; c < 3; c++)
        #pragma unroll
        for (int r = 0; r < 5; r++)
            #pragma unroll
            for (int cc = 0; cc < 3; cc++)
                in[c][r][cc] = sIn[c*(33*65) + (lr0+r)*65 + lc0+cc];
    float* h1o = g_h1 + (size_t)img*64*16384;
    int oy = ty0 + 2*tyq, ox = tx0 + tx;
    #pragma unroll 1
    for (int half = 0; half < 2; half++) {
        int ocg = half * 32;
        u64 a0[16], a1[16];
        #pragma unroll
        for (int i = 0; i < 16; i++) {
            a0[i] = pk2(sB[ocg+2*i], sB[ocg+2*i+1]);
            a1[i] = a0[i];
        }
        #pragma unroll
        for (int c = 0; c < 3; c++)
            #pragma unroll
            for (int ky = 0; ky < 3; ky++)
                #pragma unroll
                for (int kx = 0; kx < 3; kx++) {
                    u64 vv0 = pk2(in[c][ky][kx], in[c][ky][kx]);
                    u64 vv1 = pk2(in[c][ky+2][kx], in[c][ky+2][kx]);
                    const ulonglong2* wp = reinterpret_cast<const ulonglong2*>(&sWt[(c*9+ky*3+kx)*64 + ocg]);
                    #pragma unroll
                    for (int q = 0; q < 8; q++) {
                        ulonglong2 wq = wp[q];
                        fma2(a0[2*q],   vv0, wq.x);
                        fma2(a0[2*q+1], vv0, wq.y);
                        fma2(a1[2*q],   vv1, wq.x);
                        fma2(a1[2*q+1], vv1, wq.y);
                    }
                }
        #pragma unroll
        for (int i = 0; i < 16; i++) {
            float l0, h0v, l1, h1v;
            upk2(a0[i], l0, h0v);
            upk2(a1[i], l1, h1v);
            h1o[(size_t)(ocg+2*i)*16384   + (size_t)oy*128 + ox]     = fmaxf(l0, 0.f);
            h1o[(size_t)(ocg+2*i+1)*16384 + (size_t)oy*128 + ox]     = fmaxf(h0v, 0.f);
            h1o[(size_t)(ocg+2*i)*16384   + (size_t)(oy+1)*128 + ox] = fmaxf(l1, 0.f);
            h1o[(size_t)(ocg+2*i+1)*16384 + (size_t)(oy+1)*128 + ox] = fmaxf(h1v, 0.f);
        }
    }
}

// ---------------- enc2: cp.async double-buffered (unchanged) ----------------
__global__ __launch_bounds__(128) void k_enc2(const float* __restrict__ w,
                                              const float* __restrict__ bias)
{
    extern __shared__ __align__(16) float se2[];
    float* sWt = se2;
    float* sInb[2] = { se2 + 9216, se2 + 9216 + 2145 };
    float* sB  = se2 + 9216 + 4290;
    int b = blockIdx.x;
    int og = b & 1;
    int t = (b >> 1) & 7;
    int img = b >> 4;
    int ox0 = (t & 1) * 32;
    int oy0 = (t >> 1) * 16;
    int tid = threadIdx.x;
    for (int i = tid; i < 9216; i += 128) {
        int o = i & 15, rc = i >> 4;
        sWt[i] = w[(og*16 + o)*576 + rc];
    }
    if (tid < 16) sB[tid] = bias[og*16 + tid];
    const float* h1im = g_h1 + (size_t)img*64*16384;
    int iy0 = 2*oy0 - 1, ix0 = 2*ox0 - 1;
    {
        u32 dst0 = (u32)__cvta_generic_to_shared(sInb[0]);
        for (int i = tid; i < 2145; i += 128) {
            int r = i / 65, cc = i - r*65;
            int gy = iy0 + r, gx = ix0 + cc;
            bool ok = (gy >= 0 && gy < 128 && gx >= 0 && gx < 128);
            cp4(dst0 + 4u*i, h1im + ((size_t)gy*128 + gx), ok);
        }
        CP_COMMIT();
    }
    int ttx = tid & 15, tty = tid >> 4;
    u64 acc[2][2][8];
    #pragma unroll 1
    for (int cin = 0; cin < 64; cin++) {
        float* cur = sInb[cin & 1];
        float* nxt = sInb[(cin & 1) ^ 1];
        CP_WAIT0();
        __syncthreads();
        if (cin == 0) {
            #pragma unroll
            for (int r = 0; r < 2; r++)
                #pragma unroll
                for (int cc = 0; cc < 2; cc++)
                    #pragma unroll
                    for (int p = 0; p < 8; p++) acc[r][cc][p] = pk2(sB[2*p], sB[2*p+1]);
        }
        if (cin < 63) {
            const float* hp = h1im + (size_t)(cin+1)*16384;
            u32 dstn = (u32)__cvta_generic_to_shared(nxt);
            for (int i = tid; i < 2145; i += 128) {
                int r = i / 65, cc = i - r*65;
                int gy = iy0 + r, gx = ix0 + cc;
                bool ok = (gy >= 0 && gy < 128 && gx >= 0 && gx < 128);
                cp4(dstn + 4u*i, hp + ((size_t)gy*128 + gx), ok);
            }
        }
        CP_COMMIT();
        float in[5][5];
        #pragma unroll
        for (int r = 0; r < 5; r++)
            #pragma unroll
            for (int c = 0; c < 5; c++)
                in[r][c] = cur[(4*tty + r)*65 + 4*ttx + c];
        #pragma unroll
        for (int ky = 0; ky < 3; ky++)
            #pragma unroll
            for (int kx = 0; kx < 3; kx++) {
                u64 vv[2][2];
                #pragma unroll
                for (int r = 0; r < 2; r++)
                    #pragma unroll
                    for (int cc = 0; cc < 2; cc++) {
                        float v = in[2*r+ky][2*cc+kx];
                        vv[r][cc] = pk2(v, v);
                    }
                const ulonglong2* wp = reinterpret_cast<const ulonglong2*>(&sWt[(cin*9+ky*3+kx)*16]);
                #pragma unroll
                for (int q = 0; q < 4; q++) {
                    ulonglong2 wq = wp[q];
                    #pragma unroll
                    for (int r = 0; r < 2; r++)
                        #pragma unroll
                        for (int cc = 0; cc < 2; cc++) {
                            fma2(acc[r][cc][2*q],   vv[r][cc], wq.x);
                            fma2(acc[r][cc][2*q+1], vv[r][cc], wq.y);
                        }
                }
            }
    }
    #pragma unroll
    for (int r = 0; r < 2; r++)
        #pragma unroll
        for (int cc = 0; cc < 2; cc++) {
            int oy = oy0 + 2*tty + r, ox = ox0 + 2*ttx + cc;
            float* dp = g_h2 + ((size_t)(img*64 + oy)*64 + ox)*32 + og*16;
            #pragma unroll
            for (int p = 0; p < 8; p++) {
                float lo, hi;
                upk2(acc[r][cc][p], lo, hi);
                dp[2*p]   = fmaxf(lo, 0.f);
                dp[2*p+1] = fmaxf(hi, 0.f);
            }
        }
}

// ---------------- enc3 + VQ (unchanged from R16) ----------------
__global__ __launch_bounds__(128) void k_enc3_vq(const float* __restrict__ w3,
                                                 const float* __restrict__ b3,
                                                 const float* __restrict__ cb)
{
    extern __shared__ __align__(16) float sm[];
    float* sCB = sm;            // 16384
    float* sCn = sm + 16384;    // 256
    float* sW  = sm + 16640;    // 2048
    float* sB  = sm + 18688;    // 64
    int tid = threadIdx.x;
    for (int i = tid; i < 2048; i += 128) sW[i] = w3[i];
    if (tid < 64) sB[tid] = b3[tid];
    __syncthreads();
    int p0 = blockIdx.x*256 + tid;
    int p1 = p0 + 128;
    float h0[32], h1[32];
    {
        const float4* hp0 = reinterpret_cast<const float4*>(g_h2 + (size_t)p0*32);
        const float4* hp1 = reinterpret_cast<const float4*>(g_h2 + (size_t)p1*32);
        #pragma unroll
        for (int q = 0; q < 8; q++) {
            float4 v0 = hp0[q];
            h0[4*q] = v0.x; h0[4*q+1] = v0.y; h0[4*q+2] = v0.z; h0[4*q+3] = v0.w;
            float4 v1 = hp1[q];
            h1[4*q] = v1.x; h1[4*q+1] = v1.y; h1[4*q+2] = v1.z; h1[4*q+3] = v1.w;
        }
    }
    u64 z20[32], z21[32];
    const float4* sW4 = reinterpret_cast<const float4*>(sW);
    #pragma unroll 2
    for (int i = 0; i < 32; i++) {
        float a0 = 0.f, a1 = 0.f, b0 = 0.f, b1 = 0.f;
        #pragma unroll
        for (int q = 0; q < 8; q++) {
            float4 wa = sW4[(2*i)*8 + q];
            float4 wb = sW4[(2*i+1)*8 + q];
            a0 = fmaf(wa.x, h0[4*q],   a0); a0 = fmaf(wa.y, h0[4*q+1], a0);
            a0 = fmaf(wa.z, h0[4*q+2], a0); a0 = fmaf(wa.w, h0[4*q+3], a0);
            a1 = fmaf(wa.x, h1[4*q],   a1); a1 = fmaf(wa.y, h1[4*q+1], a1);
            a1 = fmaf(wa.z, h1[4*q+2], a1); a1 = fmaf(wa.w, h1[4*q+3], a1);
            b0 = fmaf(wb.x, h0[4*q],   b0); b0 = fmaf(wb.y, h0[4*q+1], b0);
            b0 = fmaf(wb.z, h0[4*q+2], b0); b0 = fmaf(wb.w, h0[4*q+3], b0);
            b1 = fmaf(wb.x, h1[4*q],   b1); b1 = fmaf(wb.y, h1[4*q+1], b1);
            b1 = fmaf(wb.z, h1[4*q+2], b1); b1 = fmaf(wb.w, h1[4*q+3], b1);
        }
        z20[i] = pk2(sB[2*i] + a0, sB[2*i+1] + b0);
        z21[i] = pk2(sB[2*i] + a1, sB[2*i+1] + b1);
    }
    float best0 = 3.4e38f, best1 = 3.4e38f;
    int bi0 = 0, bi1 = 0;
    #pragma unroll 1
    for (int stage = 0; stage < 2; stage++) {
        __syncthreads();
        {
            const float4* s4 = reinterpret_cast<const float4*>(cb + (size_t)stage*16384);
            float4* d4 = reinterpret_cast<float4*>(sCB);
            for (int i = tid; i < 4096; i += 128) d4[i] = s4[i];
        }
        __syncthreads();
        for (int k = tid; k < 256; k += 128) {
            float s = 0.f;
            #pragma unroll 8
            for (int d = 0; d < 64; d++) { float v = sCB[k*64+d]; s = fmaf(v, v, s); }
            sCn[k] = s;
        }
        __syncthreads();
        const ulonglong2* sCB2 = reinterpret_cast<const ulonglong2*>(sCB);
        int kbase = stage*256;
        #pragma unroll 1
        for (int k = 0; k < 256; k++) {
            const ulonglong2* ck = sCB2 + k*16;
            u64 a0 = 0, a1 = 0, b0 = 0, b1 = 0;
            #pragma unroll
            for (int q = 0; q < 16; q++) {
                ulonglong2 cq = ck[q];
                fma2(a0, z20[2*q],   cq.x);
                fma2(a1, z20[2*q+1], cq.y);
                fma2(b0, z21[2*q],   cq.x);
                fma2(b1, z21[2*q+1], cq.y);
            }
            float cn = sCn[k];
            u64 sa = add2(a0, a1);
            u64 sb = add2(b0, b1);
            float la, ha, lb, hb;
            upk2(sa, la, ha);
            upk2(sb, lb, hb);
            float s0 = cn - 2.f*(la + ha);
            float s1 = cn - 2.f*(lb + hb);
            if (s0 < best0) { best0 = s0; bi0 = kbase + k; }
            if (s1 < best1) { best1 = s1; bi1 = kbase + k; }
        }
    }
    g_idx[p0] = bi0;
    g_idx[p1] = bi1;
    u64 n0 = 0, n1 = 0;
    #pragma unroll
    for (int i = 0; i < 32; i++) {
        fma2(n0, z20[i], z20[i]);
        fma2(n1, z21[i], z21[i]);
    }
    float l0, h0v, l1, h1v;
    upk2(n0, l0, h0v);
    upk2(n1, l1, h1v);
    float s = (best0 + (l0 + h0v)) + (best1 + (l1 + h1v));
    #pragma unroll
    for (int off = 16; off > 0; off >>= 1)
        s += __shfl_down_sync(0xffffffffu, s, off);
    if ((tid & 31) == 0) atomicAdd(&g_loss, s);
}

__global__ void k_loss_out(float* __restrict__ out)
{
    float v = g_loss * (1.f/8388608.f);
    out[0] = v;
    out[1] = v;
}

// ---------------- dec1 (unchanged) ----------------
__global__ __launch_bounds__(256) void k_dec1(const float* __restrict__ cb,
                                              const float* __restrict__ w,
                                              const float* __restrict__ bias)
{
    __shared__ __align__(16) float sW[32*64];
    __shared__ __align__(16) float sB[32];
    int tid = threadIdx.x;
    for (int i = tid; i < 2048; i += 256) sW[i] = w[i];
    if (tid < 32) sB[tid] = bias[tid];
    __syncthreads();
    int p = blockIdx.x*256 + tid;
    int ki = g_idx[p];
    float c[64];
    const float4* cp = reinterpret_cast<const float4*>(cb + (size_t)ki*64);
    #pragma unroll
    for (int q = 0; q < 16; q++) {
        float4 v = cp[q];
        c[4*q] = v.x; c[4*q+1] = v.y; c[4*q+2] = v.z; c[4*q+3] = v.w;
    }
    int img = p >> 12;
    int rem = p & 4095;
    float* dp = g_d1 + (size_t)img*32*4096 + rem;
    const float4* sW4 = reinterpret_cast<const float4*>(sW);
    #pragma unroll 1
    for (int oc = 0; oc < 32; oc++) {
        float a0 = 0.f, a1 = 0.f, a2 = 0.f, a3 = 0.f;
        #pragma unroll
        for (int q = 0; q < 16; q++) {
            float4 wv = sW4[oc*16 + q];
            a0 = fmaf(wv.x, c[4*q],   a0);
            a1 = fmaf(wv.y, c[4*q+1], a1);
            a2 = fmaf(wv.z, c[4*q+2], a2);
            a3 = fmaf(wv.w, c[4*q+3], a3);
        }
        float v = sB[oc] + ((a0+a1) + (a2+a3));
        dp[(size_t)oc*4096] = fmaxf(v, 0.f);
    }
}

// ---------------- dec2 main mma: mb-merged, X loaded once -------------------
// grid 1024 = [tile 0..31][img 0..31]; 128 thr; loop mb=0..3 over A slices.
__global__ __launch_bounds__(128) void k_dec2_mma(const float* __restrict__ bias)
{
    extern __shared__ __align__(16) float smx[];
    float* sA = smx;                      // 64 x 292
    float* sX = smx + 64*292;             // 32 x 180
    int*   sK = (int*)(smx + 64*292 + 5760);
    int b = blockIdx.x;
    int t = b & 31;
    int img = b >> 5;
    int tx0 = (t & 3) * 16;
    int ty0 = (t >> 2) * 8;
    int tid = threadIdx.x;
    for (int k = tid; k < 288; k += 128) {
        int cin = k / 9, rr = k - cin*9;
        sK[k] = cin*180 + (rr/3)*18 + (rr - (rr/3)*3);
    }
    const float* simg = g_d1 + (size_t)img*32*4096;
    for (int i = tid; i < 5760; i += 128) {
        int cin = i / 180;
        int rem = i - cin*180;
        int r = rem / 18, c = rem - r*18;
        int sy = ty0 - 1 + r; sy = max(0, min(63, sy));
        int sx = tx0 - 1 + c; sx = max(0, min(63, sx));
        sX[i] = __uint_as_float(to_tf32(simg[cin*4096 + sy*64 + sx]));
    }
    int wid = tid >> 5, lane = tid & 31;
    int wm = wid & 1, wn = wid >> 1;
    int lg = lane >> 2, lig = lane & 3;
    int pb[8];
    #pragma unroll
    for (int nt = 0; nt < 8; nt++) {
        int n = wn*64 + nt*8 + lg;
        pb[nt] = (n >> 4)*18 + (n & 15);
    }
    const float* arow0 = sA + (wm*32 + lg)*292 + lig;
    const float* arow1 = arow0 + 16*292;
    #pragma unroll 1
    for (int mb = 0; mb < 4; mb++) {
        __syncthreads();   // mb=0: X/K ready; mb>0: prior sA reads complete
        {
            const float4* src = reinterpret_cast<const float4*>(g_weff2 + mb*64*288);
            for (int i = tid; i < 64*72; i += 128) {
                int r = i / 72, kq = (i - r*72)*4;
                float4 v = src[i];
                float* d = sA + r*292 + kq;
                d[0] = v.x; d[1] = v.y; d[2] = v.z; d[3] = v.w;
            }
        }
        __syncthreads();
        float acc[2][8][4];
        #pragma unroll
        for (int mt = 0; mt < 2; mt++)
            #pragma unroll
            for (int nt = 0; nt < 8; nt++)
                #pragma unroll
                for (int c = 0; c < 4; c++) acc[mt][nt][c] = 0.f;
        u32 abuf[2][2][4];
        u32 bbuf[2][8][2];
        {
            int ko0 = sK[lig];
            int ko1 = sK[lig + 4];
            abuf[0][0][0] = __float_as_uint(arow0[0]);
            abuf[0][0][1] = __float_as_uint(arow0[8*292]);
            abuf[0][0][2] = __float_as_uint(arow0[4]);
            abuf[0][0][3] = __float_as_uint(arow0[8*292 + 4]);
            abuf[0][1][0] = __float_as_uint(arow1[0]);
            abuf[0][1][1] = __float_as_uint(arow1[8*292]);
            abuf[0][1][2] = __float_as_uint(arow1[4]);
            abuf[0][1][3] = __float_as_uint(arow1[8*292 + 4]);
            #pragma unroll
            for (int nt = 0; nt < 8; nt++) {
                bbuf[0][nt][0] = __float_as_uint(sX[ko0 + pb[nt]]);
                bbuf[0][nt][1] = __float_as_uint(sX[ko1 + pb[nt]]);
            }
        }
        #pragma unroll 2
        for (int ks = 0; ks < 36; ks++) {
            int cur = ks & 1, nxt = cur ^ 1;
            if (ks < 35) {
                int kb = (ks+1)*8;
                int ko0 = sK[kb + lig];
                int ko1 = sK[kb + lig + 4];
                const float* a0p = arow0 + kb;
                const float* a1p = arow1 + kb;
                abuf[nxt][0][0] = __float_as_uint(a0p[0]);
                abuf[nxt][0][1] = __float_as_uint(a0p[8*292]);
                abuf[nxt][0][2] = __float_as_uint(a0p[4]);
                abuf[nxt][0][3] = __float_as_uint(a0p[8*292 + 4]);
                abuf[nxt][1][0] = __float_as_uint(a1p[0]);
                abuf[nxt][1][1] = __float_as_uint(a1p[8*292]);
                abuf[nxt][1][2] = __float_as_uint(a1p[4]);
                abuf[nxt][1][3] = __float_as_uint(a1p[8*292 + 4]);
                #pragma unroll
                for (int nt = 0; nt < 8; nt++) {
                    bbuf[nxt][nt][0] = __float_as_uint(sX[ko0 + pb[nt]]);
                    bbuf[nxt][nt][1] = __float_as_uint(sX[ko1 + pb[nt]]);
                }
            }
            #pragma unroll
            for (int nt = 0; nt < 8; nt++) {
                mma_tf32(acc[0][nt], abuf[cur][0], bbuf[cur][nt][0], bbuf[cur][nt][1]);
                mma_tf32(acc[1][nt], abuf[cur][1], bbuf[cur][nt][0], bbuf[cur][nt][1]);
            }
        }
        #pragma unroll
        for (int mt = 0; mt < 2; mt++) {
            int mbase = mb*64 + wm*32 + mt*16 + lg;
            float bv0 = bias[mbase >> 2];
            float bv2 = bias[(mbase + 8) >> 2];
            #pragma unroll
            for (int nt = 0; nt < 8; nt++) {
                #pragma unroll
                for (int c = 0; c < 4; c++) {
                    int m = mbase + ((c >= 2) ? 8 : 0);
                    int n = wn*64 + nt*8 + 2*lig + (c & 1);
                    int oc = m >> 2, ap = (m >> 1) & 1, bp2 = m & 1;
                    int py = n >> 4, px = n & 15;
                    int uy = 2*(ty0 + py) + ap, ux = 2*(tx0 + px) + bp2;
                    float v = acc[mt][nt][c] + ((c >= 2) ? bv2 : bv0);
                    g_d2[((size_t)(img*64 + oc)*128 + uy)*128 + ux] = fmaxf(v, 0.f);
                }
            }
        }
    }
}

// ---------------- dec2 border fixup: split 2x (unchanged) ----------------
__global__ __launch_bounds__(256) void k_dec2_fix(const float* __restrict__ w,
                                                  const float* __restrict__ bias)
{
    extern __shared__ __align__(16) float sf[];
    float* sW = sf;
    float* sT = sf + 18432;
    int half = blockIdx.x & 1;
    int side = (blockIdx.x >> 1) & 3;
    int img = blockIdx.x >> 3;
    int tid = threadIdx.x;
    int c0 = half * 64;
    for (int i = tid; i < 18432; i += 256) sW[i] = w[i];
    const float* xi = g_d1 + (size_t)img*32*4096;
    for (int i = tid; i < 32*2*67; i += 256) {
        int cin = i / 134;
        int rem = i - cin*134;
        int s = rem / 67, cc = rem - s*67;
        int c = c0 + cc;
        if (c > 129) continue;
        const float* xp = xi + cin*4096;
        float v = 0.f;
        int u = c - 1;
        if (u >= 0 && u < 128) {
            int j = u >> 1;
            int ja, jb; float wa, wb;
            if (u & 1) { ja = j; jb = min(j+1, 63); wa = 0.75f; wb = 0.25f; }
            else       { ja = max(j-1, 0); jb = j;  wa = 0.25f; wb = 0.75f; }
            float xa, xb;
            if (side == 0) {
                if (s == 0) { xa = xp[ja]; xb = xp[jb]; }
                else { xa = 0.75f*xp[ja] + 0.25f*xp[64+ja];
                       xb = 0.75f*xp[jb] + 0.25f*xp[64+jb]; }
            } else if (side == 1) {
                const float* r62 = xp + 62*64; const float* r63 = xp + 63*64;
                if (s == 0) { xa = 0.25f*r62[ja] + 0.75f*r63[ja];
                              xb = 0.25f*r62[jb] + 0.75f*r63[jb]; }
                else { xa = r63[ja]; xb = r63[jb]; }
            } else if (side == 2) {
                if (s == 0) { xa = xp[ja*64]; xb = xp[jb*64]; }
                else { xa = 0.75f*xp[ja*64] + 0.25f*xp[ja*64+1];
                       xb = 0.75f*xp[jb*64] + 0.25f*xp[jb*64+1]; }
            } else {
                if (s == 0) { xa = 0.25f*xp[ja*64+62] + 0.75f*xp[ja*64+63];
                              xb = 0.25f*xp[jb*64+62] + 0.75f*xp[jb*64+63]; }
                else { xa = xp[ja*64+63]; xb = xp[jb*64+63]; }
            }
            v = wa*xa + wb*xb;
        }
        sT[cin*260 + s*130 + c] = v;
    }
    __syncthreads();
    int oc = tid >> 2;
    int q = tid & 3;
    if (side <= 1) {
        int uy = (side == 0) ? 0 : 127;
        int ky0 = (side == 0) ? 1 : 0;
        for (int ux = c0 + q; ux < c0 + 64; ux += 4) {
            float acc = bias[oc];
            for (int cin = 0; cin < 32; cin++) {
                const float* wp = sW + (oc*32 + cin)*9;
                const float* tp = sT + cin*260;
                #pragma unroll
                for (int s = 0; s < 2; s++)
                    #pragma unroll
                    for (int kx = 0; kx < 3; kx++)
                        acc += wp[(ky0+s)*3 + kx] * tp[s*130 + ux + kx];
            }
            g_d2[((size_t)(img*64 + oc)*128 + uy)*128 + ux] = fmaxf(acc, 0.f);
        }
    } else {
        int ux = (side == 2) ? 0 : 127;
        int kx0 = (side == 2) ? 1 : 0;
        int uy_s = (half == 0) ? 1 : 64;
        int uy_e = (half == 0) ? 64 : 127;
        for (int uy = uy_s + q; uy < uy_e; uy += 4) {
            float acc = bias[oc];
            for (int cin = 0; cin < 32; cin++) {
                const float* wp = sW + (oc*32 + cin)*9;
                const float* tp = sT + cin*260;
                #pragma unroll
                for (int s = 0; s < 2; s++)
                    #pragma unroll
                    for (int ky = 0; ky < 3; ky++)
                        acc += wp[ky*3 + kx0 + s] * tp[s*130 + uy + ky];
            }
            g_d2[((size_t)(img*64 + oc)*128 + uy)*128 + ux] = fmaxf(acc, 0.f);
        }
    }
}

// ---------------- dec3 main mma (unchanged) ----------
__global__ __launch_bounds__(128) void k_dec3_mma(const float* __restrict__ bias,
                                                  float* __restrict__ dst)
{
    extern __shared__ __align__(16) float sm3[];
    float* sA = sm3;
    float* sX = sm3 + 16*580;
    int*   sK = (int*)(sm3 + 16*580 + 11520);
    __shared__ float sB3[3];
    int b = blockIdx.x;
    int txt = b & 7;
    int tyt = (b >> 3) & 15;
    int img = b >> 7;
    int tx0 = txt * 16;
    int ty0 = tyt * 8;
    int tid = threadIdx.x;
    {
        const float4* src = reinterpret_cast<const float4*>(g_weff3);
        for (int i = tid; i < 16*144; i += 128) {
            int r = i / 144, kq = (i - r*144)*4;
            float4 v = src[i];
            float* d = sA + r*580 + kq;
            d[0] = v.x; d[1] = v.y; d[2] = v.z; d[3] = v.w;
        }
    }
    for (int k = tid; k < 576; k += 128) {
        int cin = k / 9, rr = k - cin*9;
        sK[k] = cin*180 + (rr/3)*18 + (rr - (rr/3)*3);
    }
    if (tid < 3) sB3[tid] = bias[tid];
    const float* simg = g_d2 + (size_t)img*64*16384;
    for (int i = tid; i < 11520; i += 128) {
        int cin = i / 180;
        int rem = i - cin*180;
        int r = rem / 18, c = rem - r*18;
        int sy = ty0 - 1 + r; sy = max(0, min(127, sy));
        int sx = tx0 - 1 + c; sx = max(0, min(127, sx));
        sX[i] = __uint_as_float(to_tf32(simg[cin*16384 + sy*128 + sx]));
    }
    __syncthreads();
    int wn = tid >> 5, lane = tid & 31;
    int lg = lane >> 2, lig = lane & 3;
    float acc[4][4];
    #pragma unroll
    for (int nt = 0; nt < 4; nt++)
        #pragma unroll
        for (int c = 0; c < 4; c++) acc[nt][c] = 0.f;
    int pb[4];
    #pragma unroll
    for (int nt = 0; nt < 4; nt++) {
        int n = wn*32 + nt*8 + lg;
        pb[nt] = (n >> 4)*18 + (n & 15);
    }
    const float* arow = sA + lg*580 + lig;
    u32 abuf[2][4];
    u32 bbuf[2][4][2];
    {
        int ko0 = sK[lig];
        int ko1 = sK[lig + 4];
        abuf[0][0] = __float_as_uint(arow[0]);
        abuf[0][1] = __float_as_uint(arow[8*580]);
        abuf[0][2] = __float_as_uint(arow[4]);
        abuf[0][3] = __float_as_uint(arow[8*580 + 4]);
        #pragma unroll
        for (int nt = 0; nt < 4; nt++) {
            bbuf[0][nt][0] = __float_as_uint(sX[ko0 + pb[nt]]);
            bbuf[0][nt][1] = __float_as_uint(sX[ko1 + pb[nt]]);
        }
    }
    #pragma unroll 2
    for (int ks = 0; ks < 72; ks++) {
        int cur = ks & 1, nxt = cur ^ 1;
        if (ks < 71) {
            int kb = (ks+1)*8;
            int ko0 = sK[kb + lig];
            int ko1 = sK[kb + lig + 4];
            const float* ap = arow + kb;
            abuf[nxt][0] = __float_as_uint(ap[0]);
            abuf[nxt][1] = __float_as_uint(ap[8*580]);
            abuf[nxt][2] = __float_as_uint(ap[4]);
            abuf[nxt][3] = __float_as_uint(ap[8*580 + 4]);
            #pragma unroll
            for (int nt = 0; nt < 4; nt++) {
                bbuf[nxt][nt][0] = __float_as_uint(sX[ko0 + pb[nt]]);
                bbuf[nxt][nt][1] = __float_as_uint(sX[ko1 + pb[nt]]);
            }
        }
        #pragma unroll
        for (int nt = 0; nt < 4; nt++)
            mma_tf32(acc[nt], abuf[cur], bbuf[cur][nt][0], bbuf[cur][nt][1]);
    }
    #pragma unroll
    for (int nt = 0; nt < 4; nt++) {
        #pragma unroll
        for (int c = 0; c < 4; c++) {
            int m = lg + ((c >= 2) ? 8 : 0);
            if (m < 12) {
                int oc = m >> 2, ap = (m >> 1) & 1, bp = m & 1;
                int n = wn*32 + nt*8 + 2*lig + (c & 1);
                int uy = 2*(ty0 + (n >> 4)) + ap;
                int ux = 2*(tx0 + (n & 15)) + bp;
                dst[(((size_t)(img*3 + oc)) << 16) + uy*256 + ux] = acc[nt][c] + sB3[oc];
            }
        }
    }
}

// ---------------- dec3 border fixup: split 2x (unchanged) ---------
__global__ __launch_bounds__(256) void k_dec3_fix(const float* __restrict__ w,
                                                  const float* __restrict__ bias,
                                                  float* __restrict__ dst)
{
    extern __shared__ __align__(16) float sf3[];
    float* sW = sf3;
    float* sT = sf3 + 1728;
    int half = blockIdx.x & 1;
    int side = (blockIdx.x >> 1) & 3;
    int img = blockIdx.x >> 3;
    int tid = threadIdx.x;
    int c0 = half * 128;
    for (int i = tid; i < 1728; i += 256) sW[i] = w[i];
    const float* xi = g_d2 + (size_t)img*64*16384;
    for (int i = tid; i < 64*2*131; i += 256) {
        int cin = i / 262;
        int rem = i - cin*262;
        int s = rem / 131, cc = rem - s*131;
        int c = c0 + cc;
        if (c > 257) continue;
        const float* xp = xi + cin*16384;
        float v = 0.f;
        int u = c - 1;
        if (u >= 0 && u < 256) {
            int j = u >> 1;
            int ja, jb; float wa, wb;
            if (u & 1) { ja = j; jb = min(j+1, 127); wa = 0.75f; wb = 0.25f; }
            else       { ja = max(j-1, 0); jb = j;   wa = 0.25f; wb = 0.75f; }
            float xa, xb;
            if (side == 0) {
                if (s == 0) { xa = xp[ja]; xb = xp[jb]; }
                else { xa = 0.75f*xp[ja] + 0.25f*xp[128+ja];
                       xb = 0.75f*xp[jb] + 0.25f*xp[128+jb]; }
            } else if (side == 1) {
                const float* rA = xp + 126*128; const float* rB = xp + 127*128;
                if (s == 0) { xa = 0.25f*rA[ja] + 0.75f*rB[ja];
                              xb = 0.25f*rA[jb] + 0.75f*rB[jb]; }
                else { xa = rB[ja]; xb = rB[jb]; }
            } else if (side == 2) {
                if (s == 0) { xa = xp[ja*128]; xb = xp[jb*128]; }
                else { xa = 0.75f*xp[ja*128] + 0.25f*xp[ja*128+1];
                       xb = 0.75f*xp[jb*128] + 0.25f*xp[jb*128+1]; }
            } else {
                if (s == 0) { xa = 0.25f*xp[ja*128+126] + 0.75f*xp[ja*128+127];
                              xb = 0.25f*xp[jb*128+126] + 0.75f*xp[jb*128+127]; }
                else { xa = xp[ja*128+127]; xb = xp[jb*128+127]; }
            }
            v = wa*xa + wb*xb;
        }
        sT[cin*516 + s*258 + c] = v;
    }
    __syncthreads();
    if (side <= 1) {
        int uy = (side == 0) ? 0 : 255;
        int ky0 = (side == 0) ? 1 : 0;
        for (int idx = tid; idx < 3*128; idx += 256) {
            int oc = idx >> 7, ux = c0 + (idx & 127);
            float acc = bias[oc];
            for (int cin = 0; cin < 64; cin++) {
                const float* wp = sW + (oc*64 + cin)*9;
                const float* tp = sT + cin*516;
                #pragma unroll
                for (int s = 0; s < 2; s++)
                    #pragma unroll
                    for (int kx = 0; kx < 3; kx++)
                        acc += wp[(ky0+s)*3 + kx] * tp[s*258 + ux + kx];
            }
            dst[(((size_t)(img*3 + oc)) << 16) + uy*256 + ux] = acc;
        }
    } else {
        int ux = (side == 2) ? 0 : 255;
        int kx0 = (side == 2) ? 1 : 0;
        int uy_s = (half == 0) ? 1 : 128;
        int cnt  = 127;
        for (int idx = tid; idx < 3*cnt; idx += 256) {
            int oc = idx / cnt;
            int uy = uy_s + idx - oc*cnt;
            float acc = bias[oc];
            for (int cin = 0; cin < 64; cin++) {
                const float* wp = sW + (oc*64 + cin)*9;
                const float* tp = sT + cin*516;
                #pragma unroll
                for (int s = 0; s < 2; s++)
                    #pragma unroll
                    for (int ky = 0; ky < 3; ky++)
                        acc += wp[ky*3 + kx0 + s] * tp[s*258 + uy + ky];
            }
            dst[(((size_t)(img*3 + oc)) << 16) + uy*256 + ux] = acc;
        }
    }
}

// ---------------- host launch ----------------
extern "C" void kernel_launch(void* const* d_in, const int* in_sizes, int n_in,
                              void* d_out, int out_size) {
    const float* x   = (const float*)d_in[0];
    const float* cb  = (const float*)d_in[1];
    const float* ew1 = (const float*)d_in[2];
    const float* eb1 = (const float*)d_in[3];
    const float* ew2 = (const float*)d_in[4];
    const float* eb2 = (const float*)d_in[5];
    const float* ew3 = (const float*)d_in[6];
    const float* eb3 = (const float*)d_in[7];
    const float* dw1 = (const float*)d_in[8];
    const float* db1 = (const float*)d_in[9];
    const float* dw2 = (const float*)d_in[10];
    const float* db2 = (const float*)d_in[11];
    const float* dw3 = (const float*)d_in[12];
    const float* db3 = (const float*)d_in[13];
    float* out = (float*)d_out;

    cudaFuncSetAttribute(k_enc2, cudaFuncAttributeMaxDynamicSharedMemorySize, 54088);
    cudaFuncSetAttribute(k_enc3_vq, cudaFuncAttributeMaxDynamicSharedMemorySize, 75008);
    cudaFuncSetAttribute(k_dec2_mma, cudaFuncAttributeMaxDynamicSharedMemorySize, 98944);
    cudaFuncSetAttribute(k_dec2_fix, cudaFuncAttributeMaxDynamicSharedMemorySize, 107008);
    cudaFuncSetAttribute(k_dec3_mma, cudaFuncAttributeMaxDynamicSharedMemorySize, 85504);
    cudaFuncSetAttribute(k_dec3_fix, cudaFuncAttributeMaxDynamicSharedMemorySize, 139008);

    k_prep<<<649, 128>>>(dw2, dw3);
    k_enc1<<<1024, 256>>>(x, ew1, eb1);
    k_enc2<<<512, 128, 54088>>>(ew2, eb2);
    k_enc3_vq<<<512, 128, 75008>>>(ew3, eb3, cb);
    k_loss_out<<<1, 1>>>(out);
    k_dec1<<<512, 256>>>(cb, dw1, db1);
    k_dec2_mma<<<1024, 128, 98944>>>(db2);
    k_dec2_fix<<<256, 256, 107008>>>(dw2, db2);
    k_dec3_mma<<<4096, 128, 85504>>>(db3, out + 2);
    k_dec3_fix<<<256, 256, 139008>>>(dw3, db3, out + 2);
}